// round 7
// baseline (speedup 1.0000x reference)
#include <cuda_runtime.h>
#include <cuda_bf16.h>
#include <math.h>

#define BB 8
#define NN 256
#define DD 384
#define LL 6
#define HH 8
#define FFD 1536
#define TT 4
#define DH 48
#define NM1 517
#define SS 1034
#define SPAD 1152
#define MM (BB*SS)
#define QKVN 1152

// ---------------- scratch ----------------
__device__ float g_SRC [MM*DD];
__device__ float g_COORD[MM*3];
__device__ float g_QKV [MM*QKVN];
__device__ float g_PROJ[MM*DD];

__device__ __nv_bfloat16 g_XH[MM*DD];
__device__ __nv_bfloat16 g_XL[MM*DD];
__device__ __nv_bfloat16 g_FFH[MM*FFD];
__device__ __nv_bfloat16 g_FFL[MM*FFD];

__device__ __nv_bfloat16 g_QH[64*SPAD*DH];
__device__ __nv_bfloat16 g_QL[64*SPAD*DH];
__device__ __nv_bfloat16 g_KH[64*SPAD*DH];
__device__ __nv_bfloat16 g_KL[64*SPAD*DH];
__device__ __nv_bfloat16 g_VH[64*DH*SPAD];
__device__ __nv_bfloat16 g_VL[64*DH*SPAD];

__device__ __nv_bfloat16 g_WqkvH[LL*QKVN*DD];
__device__ __nv_bfloat16 g_WqkvL[LL*QKVN*DD];
__device__ __nv_bfloat16 g_WoH[LL*DD*DD];
__device__ __nv_bfloat16 g_WoL[LL*DD*DD];
__device__ __nv_bfloat16 g_W1H[LL*FFD*DD];
__device__ __nv_bfloat16 g_W1L[LL*FFD*DD];
__device__ __nv_bfloat16 g_W2H[LL*DD*FFD];
__device__ __nv_bfloat16 g_W2L[LL*DD*FFD];
__device__ float g_bqkv[LL*QKVN];

// ---------------- input assembly ----------------
__global__ void build_src_kernel(const float* __restrict__ hand_t, const float* __restrict__ head_t,
                                 const float* __restrict__ hand_m1, const float* __restrict__ head_m1,
                                 const float* __restrict__ state_t, const float* __restrict__ state_m1,
                                 const float* __restrict__ tok_m1, const float* __restrict__ tok_t)
{
    for (int idx = blockIdx.x*blockDim.x + threadIdx.x; idx < BB*SS*DD; idx += gridDim.x*blockDim.x) {
        int d = idx % DD;
        int s = (idx / DD) % SS;
        int b = idx / (DD*SS);
        float v;
        if      (s == 0)    v = state_m1[b*DD + d];
        else if (s < 257)   v = hand_m1[((b*NN)+(s-1  ))*DD + d];
        else if (s < 513)   v = head_m1[((b*NN)+(s-257))*DD + d];
        else if (s < 517)   v = tok_m1[(s-513)*DD + d];
        else if (s == 517)  v = state_t[b*DD + d];
        else if (s < 774)   v = hand_t[((b*NN)+(s-518))*DD + d];
        else if (s < 1030)  v = head_t[((b*NN)+(s-774))*DD + d];
        else                v = tok_t[(s-1030)*DD + d];
        g_SRC[idx] = v;
    }
}

__global__ void build_coord_kernel(const float* __restrict__ c_hand_t, const float* __restrict__ c_head_t,
                                   const float* __restrict__ c_hand_m1, const float* __restrict__ c_head_m1,
                                   const float* __restrict__ tr_t, const float* __restrict__ tr_m1)
{
    for (int idx = blockIdx.x*blockDim.x + threadIdx.x; idx < BB*SS*3; idx += gridDim.x*blockDim.x) {
        int cdim = idx % 3;
        int s = (idx/3) % SS;
        int b = idx / (3*SS);
        float v;
        if      (s == 0)    v = tr_m1[b*3+cdim];
        else if (s < 257)   v = c_hand_m1[((b*NN)+(s-1  ))*3 + cdim];
        else if (s < 513)   v = c_head_m1[((b*NN)+(s-257))*3 + cdim];
        else if (s < 517)   v = tr_m1[b*3+cdim];
        else if (s == 517)  v = tr_t[b*3+cdim];
        else if (s < 774)   v = c_hand_t[((b*NN)+(s-518))*3 + cdim];
        else if (s < 1030)  v = c_head_t[((b*NN)+(s-774))*3 + cdim];
        else                v = tr_t[b*3+cdim];
        g_COORD[idx] = v;
    }
}

// ---------------- weight prep ----------------
__global__ void split_kernel(const float* __restrict__ x,
                             __nv_bfloat16* __restrict__ hi,
                             __nv_bfloat16* __restrict__ lo, int n)
{
    for (int i = blockIdx.x*blockDim.x + threadIdx.x; i < n; i += gridDim.x*blockDim.x) {
        float v = x[i];
        __nv_bfloat16 h = __float2bfloat16_rn(v);
        hi[i] = h;
        lo[i] = __float2bfloat16_rn(v - __bfloat162float(h));
    }
}

// packs Wq/Wk/Wv -> g_Wqkv (split) and bq/bk/bv -> g_bqkv
__global__ void split_qkv_w_kernel(const float* __restrict__ Wq, const float* __restrict__ Wk,
                                   const float* __restrict__ Wv, const float* __restrict__ bq,
                                   const float* __restrict__ bk, const float* __restrict__ bv)
{
    int tid0 = blockIdx.x*blockDim.x + threadIdx.x;
    if (tid0 < LL*QKVN) {
        int r = tid0 % QKVN, l = tid0 / QKVN;
        float v;
        if      (r < DD)   v = bq[l*DD + r];
        else if (r < 2*DD) v = bk[l*DD + r-DD];
        else               v = bv[l*DD + r-2*DD];
        g_bqkv[tid0] = v;
    }
    const int total = LL*QKVN*DD;
    for (int idx = tid0; idx < total; idx += gridDim.x*blockDim.x) {
        int k = idx % DD;
        int r = (idx / DD) % QKVN;
        int l = idx / (DD*QKVN);
        float v;
        if      (r < DD)    v = Wq[((size_t)l*DD + r      )*DD + k];
        else if (r < 2*DD)  v = Wk[((size_t)l*DD + r-DD   )*DD + k];
        else                v = Wv[((size_t)l*DD + r-2*DD )*DD + k];
        __nv_bfloat16 h = __float2bfloat16_rn(v);
        g_WqkvH[idx] = h;
        g_WqkvL[idx] = __float2bfloat16_rn(v - __bfloat162float(h));
    }
}

// splits Wo, W1, W2 in one kernel
__global__ void split_weights_kernel(const float* __restrict__ Wo, const float* __restrict__ W1,
                                     const float* __restrict__ W2)
{
    const int S1 = DD*DD, S2 = FFD*DD, S3 = DD*FFD;
    const int SEG = S1 + S2 + S3;
    const int total = LL*SEG;
    for (int idx = blockIdx.x*blockDim.x + threadIdx.x; idx < total; idx += gridDim.x*blockDim.x) {
        int l = idx / SEG, r = idx % SEG;
        float v; __nv_bfloat16 *dh, *dl; size_t o;
        if (r < S1)           { v = Wo[(size_t)l*S1 + r];        dh = g_WoH; dl = g_WoL; o = (size_t)l*S1 + r; }
        else if (r < S1+S2)   { int rr = r - S1;
                                v = W1[(size_t)l*S2 + rr];       dh = g_W1H; dl = g_W1L; o = (size_t)l*S2 + rr; }
        else                  { int rr = r - S1 - S2;
                                v = W2[(size_t)l*S3 + rr];       dh = g_W2H; dl = g_W2L; o = (size_t)l*S3 + rr; }
        __nv_bfloat16 h = __float2bfloat16_rn(v);
        dh[o] = h;
        dl[o] = __float2bfloat16_rn(v - __bfloat162float(h));
    }
}

// ---------------- helpers ----------------
__device__ __forceinline__ unsigned smem_addr(const void* p) {
    return (unsigned)__cvta_generic_to_shared(p);
}
__device__ __forceinline__ void ldsm_x4(unsigned r[4], unsigned addr) {
    asm volatile("ldmatrix.sync.aligned.m8n8.x4.shared.b16 {%0,%1,%2,%3}, [%4];"
                 : "=r"(r[0]), "=r"(r[1]), "=r"(r[2]), "=r"(r[3]) : "r"(addr));
}
__device__ __forceinline__ void mma_bf16(float c[4], const unsigned a[4], const unsigned b[2]) {
    asm volatile("mma.sync.aligned.m16n8k16.row.col.f32.bf16.bf16.f32 "
                 "{%0,%1,%2,%3}, {%4,%5,%6,%7}, {%8,%9}, {%0,%1,%2,%3};"
                 : "+f"(c[0]), "+f"(c[1]), "+f"(c[2]), "+f"(c[3])
                 : "r"(a[0]), "r"(a[1]), "r"(a[2]), "r"(a[3]), "r"(b[0]), "r"(b[1]));
}
__device__ __forceinline__ void cpa16(unsigned dst, const void* src, bool pred) {
    int sz = pred ? 16 : 0;
    asm volatile("cp.async.cg.shared.global [%0], [%1], 16, %2;"
                 :: "r"(dst), "l"(src), "r"(sz) : "memory");
}
#define CP_COMMIT() asm volatile("cp.async.commit_group;" ::: "memory")
#define CP_WAIT1()  asm volatile("cp.async.wait_group 1;" ::: "memory")
#define CP_WAIT0()  asm volatile("cp.async.wait_group 0;" ::: "memory")

__device__ __forceinline__ void split2(float a, float b, unsigned &h, unsigned &l) {
    __nv_bfloat162 hh = __floats2bfloat162_rn(a, b);
    h = *(unsigned*)&hh;
    float ra = a - __bfloat162float(hh.x);
    float rb = b - __bfloat162float(hh.y);
    __nv_bfloat162 ll = __floats2bfloat162_rn(ra, rb);
    l = *(unsigned*)&ll;
}

// ---------------- bf16x3 GEMM: BM=256, BN=128, BK=32, 512 thr, 2-stage cp.async ----------
#define LDSMP 40
#define GA_E (256*LDSMP)          // A elems per array
#define GB_E (128*LDSMP)          // B elems per array
#define GA_B (GA_E*2)             // 20480 bytes
#define GB_B (GB_E*2)             // 10240 bytes
#define GSTG (2*GA_B + 2*GB_B)    // 61440
#define GSMEM (2*GSTG)            // 122880

template<bool DO_GELU, bool SPLIT_OUT>
__global__ void __launch_bounds__(512, 1) gemm_kernel(int M, int N, int K,
    const __nv_bfloat16* __restrict__ Ah, const __nv_bfloat16* __restrict__ Al,
    const __nv_bfloat16* __restrict__ Wh, const __nv_bfloat16* __restrict__ Wl,
    const float* __restrict__ bias, float* __restrict__ C,
    __nv_bfloat16* __restrict__ Ch, __nv_bfloat16* __restrict__ Cl)
{
    extern __shared__ __nv_bfloat16 dsm[];
    const int tid  = threadIdx.x;
    const int lane = tid & 31;
    const int warp = tid >> 5;          // 0..15
    const int wm   = warp >> 1;         // 0..7  -> m offset wm*32
    const int wn   = warp & 1;          // 0..1  -> n offset wn*64
    const int m0   = blockIdx.x * 256;
    const int n0   = blockIdx.y * 128;

    float c[2][8][4];
    #pragma unroll
    for (int i = 0; i < 2; i++)
        #pragma unroll
        for (int j = 0; j < 8; j++)
            #pragma unroll
            for (int r = 0; r < 4; r++) c[i][j][r] = 0.f;

    const int aRowSel = (lane & 7) + ((lane >> 3) & 1) * 8;
    const int aColSel = (lane >> 4) * 8;
    const int bRowSel = (lane & 7) + ((lane >> 4) & 1) * 8;
    const int bColSel = ((lane >> 3) & 1) * 8;

    const unsigned sbase = smem_addr(dsm);

    auto load_tile = [&](int kt, int stage) {
        const int kc = kt * 32;
        const unsigned sb = sbase + stage*GSTG;
        // A: 256 rows x 4 chunks, hi+lo
        #pragma unroll
        for (int i = 0; i < 2; i++) {
            int idx = tid + i*512;
            int row = idx >> 2, u = idx & 3;
            int gm = m0 + row;
            bool pa = gm < M;
            int gmc = pa ? gm : 0;
            unsigned d = (unsigned)(row*(LDSMP*2) + u*16);
            cpa16(sb + d,        Ah + (size_t)gmc*K + kc + u*8, pa);
            cpa16(sb + GA_B + d, Al + (size_t)gmc*K + kc + u*8, pa);
        }
        // B: 128 rows x 4 chunks, hi+lo
        {
            int row = tid >> 2, u = tid & 3;
            if (row < 128) {
                unsigned d = (unsigned)(row*(LDSMP*2) + u*16);
                cpa16(sb + 2*GA_B + d,        Wh + (size_t)(n0 + row)*K + kc + u*8, true);
                cpa16(sb + 2*GA_B + GB_B + d, Wl + (size_t)(n0 + row)*K + kc + u*8, true);
            }
        }
    };

    const int nk = K >> 5;
    load_tile(0, 0);
    CP_COMMIT();

    for (int kt = 0; kt < nk; kt++) {
        const int cur = kt & 1;
        if (kt + 1 < nk) load_tile(kt + 1, cur ^ 1);
        CP_COMMIT();
        CP_WAIT1();
        __syncthreads();

        const unsigned sb    = sbase + cur*GSTG;
        const unsigned sAh_b = sb;
        const unsigned sAl_b = sb + GA_B;
        const unsigned sBh_b = sb + 2*GA_B;
        const unsigned sBl_b = sb + 2*GA_B + GB_B;

        #pragma unroll
        for (int kk = 0; kk < 2; kk++) {
            unsigned ah[2][4], al[2][4];
            #pragma unroll
            for (int mt = 0; mt < 2; mt++) {
                unsigned off = (unsigned)(((wm*32 + mt*16 + aRowSel)*LDSMP + kk*16 + aColSel) * 2);
                ldsm_x4(ah[mt], sAh_b + off);
                ldsm_x4(al[mt], sAl_b + off);
            }
            #pragma unroll
            for (int nh = 0; nh < 2; nh++) {
                unsigned bh[4][2], bl[4][2];
                #pragma unroll
                for (int nb = 0; nb < 2; nb++) {
                    unsigned off = (unsigned)(((wn*64 + nh*32 + nb*16 + bRowSel)*LDSMP + kk*16 + bColSel) * 2);
                    unsigned t[4];
                    ldsm_x4(t, sBh_b + off);
                    bh[2*nb][0]=t[0]; bh[2*nb][1]=t[1]; bh[2*nb+1][0]=t[2]; bh[2*nb+1][1]=t[3];
                    ldsm_x4(t, sBl_b + off);
                    bl[2*nb][0]=t[0]; bl[2*nb][1]=t[1]; bl[2*nb+1][0]=t[2]; bl[2*nb+1][1]=t[3];
                }
                #pragma unroll
                for (int mt = 0; mt < 2; mt++)
                    #pragma unroll
                    for (int nt = 0; nt < 4; nt++) {
                        mma_bf16(c[mt][nh*4+nt], ah[mt], bh[nt]);
                        mma_bf16(c[mt][nh*4+nt], al[mt], bh[nt]);
                        mma_bf16(c[mt][nh*4+nt], ah[mt], bl[nt]);
                    }
            }
        }
        __syncthreads();
    }

    #pragma unroll
    for (int mt = 0; mt < 2; mt++) {
        #pragma unroll
        for (int nt = 0; nt < 8; nt++) {
            int col  = n0 + wn*64 + nt*8 + (lane & 3)*2;
            float b0 = bias[col], b1 = bias[col+1];
            int row0 = m0 + wm*32 + mt*16 + (lane >> 2);
            int row1 = row0 + 8;
            float v0 = c[mt][nt][0] + b0, v1 = c[mt][nt][1] + b1;
            float v2 = c[mt][nt][2] + b0, v3 = c[mt][nt][3] + b1;
            if (DO_GELU) {
                v0 = 0.5f*v0*(1.0f+erff(v0*0.7071067811865475f));
                v1 = 0.5f*v1*(1.0f+erff(v1*0.7071067811865475f));
                v2 = 0.5f*v2*(1.0f+erff(v2*0.7071067811865475f));
                v3 = 0.5f*v3*(1.0f+erff(v3*0.7071067811865475f));
            }
            if (SPLIT_OUT) {
                unsigned h01, l01, h23, l23;
                split2(v0, v1, h01, l01);
                split2(v2, v3, h23, l23);
                if (row0 < M) { *(unsigned*)&Ch[(size_t)row0*N + col] = h01;
                                *(unsigned*)&Cl[(size_t)row0*N + col] = l01; }
                if (row1 < M) { *(unsigned*)&Ch[(size_t)row1*N + col] = h23;
                                *(unsigned*)&Cl[(size_t)row1*N + col] = l23; }
            } else {
                if (row0 < M) *(float2*)&C[(size_t)row0*N + col] = make_float2(v0, v1);
                if (row1 < M) *(float2*)&C[(size_t)row1*N + col] = make_float2(v2, v3);
            }
        }
    }
}

// ---------------- rope + split + relayout ----------------
__global__ void __launch_bounds__(256) rope_split_kernel()
{
    int t = blockIdx.x*blockDim.x + threadIdx.x;
    if (t >= 64*SS) return;
    int s  = t % SS;
    int bh = t / SS;
    int b = bh >> 3, h = bh & 7;

    const float* src = g_QKV + ((size_t)(b*SS + s))*QKVN + h*DH;
    float q[48], k[48], v[48];
    #pragma unroll
    for (int i = 0; i < 12; i++) {
        *(float4*)&q[i*4] = *(const float4*)(src + i*4);
        *(float4*)&k[i*4] = *(const float4*)(src + DD + i*4);
        *(float4*)&v[i*4] = *(const float4*)(src + 2*DD + i*4);
    }

    float invf[8];
    #pragma unroll
    for (int j = 0; j < 8; j++)
        invf[j] = exp2f(-1.6609640474436813f * (float)j);

    #pragma unroll
    for (int a = 0; a < 3; a++) {
        float co = g_COORD[(b*SS + s)*3 + a];
        #pragma unroll
        for (int j = 0; j < 8; j++) {
            float ang = co * invf[j];
            float cs = cosf(ang), sn = sinf(ang);
            int i1 = a*16 + j, i2 = i1 + 8;
            float q1 = q[i1], q2 = q[i2];
            q[i1] = q1*cs - q2*sn;  q[i2] = q1*sn + q2*cs;
            float k1 = k[i1], k2 = k[i2];
            k[i1] = k1*cs - k2*sn;  k[i2] = k1*sn + k2*cs;
        }
    }

    const float scale = 0.14433756729740643f;
    size_t qkbase = ((size_t)bh*SPAD + s)*DH;
    #pragma unroll
    for (int d = 0; d < 48; d++) {
        float qq = q[d]*scale;
        __nv_bfloat16 hh = __float2bfloat16_rn(qq);
        g_QH[qkbase + d] = hh;
        g_QL[qkbase + d] = __float2bfloat16_rn(qq - __bfloat162float(hh));
        hh = __float2bfloat16_rn(k[d]);
        g_KH[qkbase + d] = hh;
        g_KL[qkbase + d] = __float2bfloat16_rn(k[d] - __bfloat162float(hh));
        hh = __float2bfloat16_rn(v[d]);
        size_t vi = ((size_t)bh*DH + d)*SPAD + s;
        g_VH[vi] = hh;
        g_VL[vi] = __float2bfloat16_rn(v[d] - __bfloat162float(hh));
    }
}

// ---------------- tensor-core flash attention (128 q-rows, 8 warps) ----------------
#define QKP 56
#define VTP 72
#define AQ_B (128*QKP*2)    // 14336
#define AK_B (64*QKP*2)     // 7168
#define AV_B (48*VTP*2)     // 6912
#define ASMEM (2*AQ_B + 2*AK_B + 2*AV_B)   // 56832

__global__ void __launch_bounds__(256) attn_mma_kernel(__nv_bfloat16* __restrict__ AH,
                                                       __nv_bfloat16* __restrict__ AL)
{
    extern __shared__ __nv_bfloat16 asm_dsm[];
    const int bh = blockIdx.y;
    const int b = bh >> 3, h = bh & 7;
    const int q0 = blockIdx.x * 128;
    const int tid = threadIdx.x;
    const int lane = tid & 31;
    const int warp = tid >> 5;          // 0..7

    const unsigned sQh_b = smem_addr(asm_dsm);
    const unsigned sQl_b = sQh_b + AQ_B;
    const unsigned sKh_b = sQl_b + AQ_B;
    const unsigned sKl_b = sKh_b + AK_B;
    const unsigned sVh_b = sKl_b + AK_B;
    const unsigned sVl_b = sVh_b + AV_B;

    const size_t qkBase = (size_t)bh*SPAD*DH;
    const size_t vBase  = (size_t)bh*DH*SPAD;

    // stage Q: 128 rows x 6 chunks = 768 per array
    #pragma unroll
    for (int i = 0; i < 3; i++) {
        int cidx = tid + i*256;
        int row = cidx / 6, off = (cidx % 6) * 8;
        unsigned d = (unsigned)((row*QKP + off) * 2);
        const size_t g = qkBase + (size_t)(q0 + row)*DH + off;
        cpa16(sQh_b + d, g_QH + g, true);
        cpa16(sQl_b + d, g_QL + g, true);
    }
    CP_COMMIT(); CP_WAIT0();
    __syncthreads();

    const int aRow = 16*warp + (lane & 7) + ((lane >> 3) & 1) * 8;
    const int aColSel = (lane >> 4) * 8;
    unsigned qh[3][4], ql[3][4];
    #pragma unroll
    for (int kk = 0; kk < 3; kk++) {
        unsigned off = (unsigned)((aRow*QKP + kk*16 + aColSel) * 2);
        ldsm_x4(qh[kk], sQh_b + off);
        ldsm_x4(ql[kk], sQl_b + off);
    }

    float o[6][4];
    #pragma unroll
    for (int i = 0; i < 6; i++)
        #pragma unroll
        for (int j = 0; j < 4; j++) o[i][j] = 0.f;
    float m0r = -1e30f, m1r = -1e30f, l0 = 0.f, l1 = 0.f;

    const int row0 = q0 + 16*warp + (lane >> 2);
    const int row1 = row0 + 8;
    const bool rm0 = row0 < NM1, rm1 = row1 < NM1;

    const int bRowSel = (lane & 7) + ((lane >> 4) & 1) * 8;
    const int bColSel = ((lane >> 3) & 1) * 8;

    for (int kt = 0; kt < 17; kt++) {
        int k0 = kt * 64;
        if ((q0 + 127 < NM1) && (k0 >= NM1)) continue;

        __syncthreads();
        // K: 64 rows x 6 chunks = 384; V: 48 rows x 8 chunks = 384
        #pragma unroll
        for (int i = 0; i < 2; i++) {
            int cidx = tid + i*256;
            if (cidx < 384) {
                int row = cidx / 6, off = (cidx % 6) * 8;
                unsigned d = (unsigned)((row*QKP + off) * 2);
                const size_t g = qkBase + (size_t)(k0 + row)*DH + off;
                cpa16(sKh_b + d, g_KH + g, true);
                cpa16(sKl_b + d, g_KL + g, true);
            }
        }
        #pragma unroll
        for (int i = 0; i < 2; i++) {
            int cidx = tid + i*256;
            if (cidx < 384) {
                int row = cidx / 8, off = (cidx % 8) * 8;
                unsigned d = (unsigned)((row*VTP + off) * 2);
                const size_t g = vBase + (size_t)row*SPAD + k0 + off;
                cpa16(sVh_b + d, g_VH + g, true);
                cpa16(sVl_b + d, g_VL + g, true);
            }
        }
        CP_COMMIT(); CP_WAIT0();
        __syncthreads();

        float s[8][4];
        #pragma unroll
        for (int i = 0; i < 8; i++)
            #pragma unroll
            for (int j = 0; j < 4; j++) s[i][j] = 0.f;

        #pragma unroll
        for (int kk = 0; kk < 3; kk++) {
            unsigned bhf[8][2], blf[8][2];
            #pragma unroll
            for (int nb = 0; nb < 4; nb++) {
                unsigned off = (unsigned)(((nb*16 + bRowSel)*QKP + kk*16 + bColSel) * 2);
                unsigned t[4];
                ldsm_x4(t, sKh_b + off);
                bhf[2*nb][0]=t[0]; bhf[2*nb][1]=t[1]; bhf[2*nb+1][0]=t[2]; bhf[2*nb+1][1]=t[3];
                ldsm_x4(t, sKl_b + off);
                blf[2*nb][0]=t[0]; blf[2*nb][1]=t[1]; blf[2*nb+1][0]=t[2]; blf[2*nb+1][1]=t[3];
            }
            #pragma unroll
            for (int nt = 0; nt < 8; nt++) {
                mma_bf16(s[nt], qh[kk], bhf[nt]);
                mma_bf16(s[nt], ql[kk], bhf[nt]);
                mma_bf16(s[nt], qh[kk], blf[nt]);
            }
        }

        #pragma unroll
        for (int nt = 0; nt < 8; nt++) {
            #pragma unroll
            for (int e = 0; e < 2; e++) {
                int col = k0 + nt*8 + (lane & 3)*2 + e;
                bool cmm = (col >= SS);
                bool cnm = (col >= NM1);
                if (cmm || (rm0 && cnm)) s[nt][e]   = -1e30f;
                if (cmm || (rm1 && cnm)) s[nt][2+e] = -1e30f;
            }
        }

        float t0 = -1e30f, t1 = -1e30f;
        #pragma unroll
        for (int nt = 0; nt < 8; nt++) {
            t0 = fmaxf(t0, fmaxf(s[nt][0], s[nt][1]));
            t1 = fmaxf(t1, fmaxf(s[nt][2], s[nt][3]));
        }
        t0 = fmaxf(t0, __shfl_xor_sync(0xffffffffu, t0, 1));
        t0 = fmaxf(t0, __shfl_xor_sync(0xffffffffu, t0, 2));
        t1 = fmaxf(t1, __shfl_xor_sync(0xffffffffu, t1, 1));
        t1 = fmaxf(t1, __shfl_xor_sync(0xffffffffu, t1, 2));
        float nm0 = fmaxf(m0r, t0), nm1 = fmaxf(m1r, t1);
        float f0 = __expf(m0r - nm0), f1 = __expf(m1r - nm1);
        m0r = nm0; m1r = nm1;

        float ps0 = 0.f, ps1 = 0.f;
        #pragma unroll
        for (int nt = 0; nt < 8; nt++) {
            s[nt][0] = __expf(s[nt][0] - m0r);
            s[nt][1] = __expf(s[nt][1] - m0r);
            s[nt][2] = __expf(s[nt][2] - m1r);
            s[nt][3] = __expf(s[nt][3] - m1r);
            ps0 += s[nt][0] + s[nt][1];
            ps1 += s[nt][2] + s[nt][3];
        }
        ps0 += __shfl_xor_sync(0xffffffffu, ps0, 1);
        ps0 += __shfl_xor_sync(0xffffffffu, ps0, 2);
        ps1 += __shfl_xor_sync(0xffffffffu, ps1, 1);
        ps1 += __shfl_xor_sync(0xffffffffu, ps1, 2);
        l0 = l0*f0 + ps0;
        l1 = l1*f1 + ps1;
        #pragma unroll
        for (int nt = 0; nt < 6; nt++) {
            o[nt][0] *= f0; o[nt][1] *= f0;
            o[nt][2] *= f1; o[nt][3] *= f1;
        }

        #pragma unroll
        for (int kk = 0; kk < 4; kk++) {
            unsigned pah[4], pal[4];
            split2(s[2*kk  ][0], s[2*kk  ][1], pah[0], pal[0]);
            split2(s[2*kk  ][2], s[2*kk  ][3], pah[1], pal[1]);
            split2(s[2*kk+1][0], s[2*kk+1][1], pah[2], pal[2]);
            split2(s[2*kk+1][2], s[2*kk+1][3], pah[3], pal[3]);

            unsigned vbh[6][2], vbl[6][2];
            #pragma unroll
            for (int nb = 0; nb < 3; nb++) {
                unsigned off = (unsigned)(((nb*16 + bRowSel)*VTP + kk*16 + bColSel) * 2);
                unsigned t[4];
                ldsm_x4(t, sVh_b + off);
                vbh[2*nb][0]=t[0]; vbh[2*nb][1]=t[1]; vbh[2*nb+1][0]=t[2]; vbh[2*nb+1][1]=t[3];
                ldsm_x4(t, sVl_b + off);
                vbl[2*nb][0]=t[0]; vbl[2*nb][1]=t[1]; vbl[2*nb+1][0]=t[2]; vbl[2*nb+1][1]=t[3];
            }
            #pragma unroll
            for (int nt = 0; nt < 6; nt++) {
                mma_bf16(o[nt], pah, vbh[nt]);
                mma_bf16(o[nt], pal, vbh[nt]);
                mma_bf16(o[nt], pah, vbl[nt]);
            }
        }
    }

    float il0 = 1.f / l0, il1 = 1.f / l1;
    #pragma unroll
    for (int nt = 0; nt < 6; nt++) {
        int col = h*DH + nt*8 + (lane & 3)*2;
        if (row0 < SS) {
            unsigned hh, ll;
            split2(o[nt][0]*il0, o[nt][1]*il0, hh, ll);
            *(unsigned*)&AH[(size_t)(b*SS + row0)*DD + col] = hh;
            *(unsigned*)&AL[(size_t)(b*SS + row0)*DD + col] = ll;
        }
        if (row1 < SS) {
            unsigned hh, ll;
            split2(o[nt][2]*il1, o[nt][3]*il1, hh, ll);
            *(unsigned*)&AH[(size_t)(b*SS + row1)*DD + col] = hh;
            *(unsigned*)&AL[(size_t)(b*SS + row1)*DD + col] = ll;
        }
    }
}

// ---------------- residual add + layernorm ----------------
__global__ void __launch_bounds__(128) add_ln_kernel(float* __restrict__ src, const float* __restrict__ res,
                                                     const float* __restrict__ g, const float* __restrict__ bta,
                                                     __nv_bfloat16* __restrict__ XH, __nv_bfloat16* __restrict__ XL)
{
    int row = blockIdx.x;
    int tid = threadIdx.x;
    float x[3];
    float s = 0.f, sq = 0.f;
    #pragma unroll
    for (int i = 0; i < 3; i++) {
        int d = tid + i*128;
        float v = src[(size_t)row*DD + d] + res[(size_t)row*DD + d];
        x[i] = v; s += v; sq += v*v;
    }
    #pragma unroll
    for (int o = 16; o > 0; o >>= 1) {
        s  += __shfl_xor_sync(0xffffffffu, s,  o);
        sq += __shfl_xor_sync(0xffffffffu, sq, o);
    }
    __shared__ float ss[4], ssq[4];
    int w = tid >> 5;
    if ((tid & 31) == 0) { ss[w] = s; ssq[w] = sq; }
    __syncthreads();
    s  = ss[0]+ss[1]+ss[2]+ss[3];
    sq = ssq[0]+ssq[1]+ssq[2]+ssq[3];
    float mean = s * (1.f/384.f);
    float var  = sq * (1.f/384.f) - mean*mean;
    float rs = rsqrtf(var + 1e-5f);
    #pragma unroll
    for (int i = 0; i < 3; i++) {
        int d = tid + i*128;
        float y = (x[i]-mean)*rs*g[d] + bta[d];
        src[(size_t)row*DD + d] = y;
        __nv_bfloat16 hh = __float2bfloat16_rn(y);
        XH[(size_t)row*DD + d] = hh;
        XL[(size_t)row*DD + d] = __float2bfloat16_rn(y - __bfloat162float(hh));
    }
}

__global__ void copy_out_kernel(float* __restrict__ out)
{
    int idx = blockIdx.x*blockDim.x + threadIdx.x;
    if (idx >= BB*TT*DD) return;
    int d = idx % DD;
    int t = (idx/DD) % TT;
    int b = idx / (DD*TT);
    out[idx] = g_SRC[((size_t)(b*SS + (SS-TT) + t))*DD + d];
}

// ---------------- host launcher ----------------
extern "C" void kernel_launch(void* const* d_in, const int* in_sizes, int n_in,
                              void* d_out, int out_size)
{
    (void)in_sizes; (void)n_in; (void)out_size;
    const float* hand_t    = (const float*)d_in[0];
    const float* head_t    = (const float*)d_in[1];
    const float* hand_m1   = (const float*)d_in[2];
    const float* head_m1   = (const float*)d_in[3];
    const float* c_hand_t  = (const float*)d_in[4];
    const float* c_head_t  = (const float*)d_in[5];
    const float* c_hand_m1 = (const float*)d_in[6];
    const float* c_head_m1 = (const float*)d_in[7];
    const float* state_t   = (const float*)d_in[8];
    const float* state_m1  = (const float*)d_in[9];
    const float* tr_t      = (const float*)d_in[10];
    const float* tr_m1     = (const float*)d_in[11];
    const float* tok_m1    = (const float*)d_in[12];
    const float* tok_t     = (const float*)d_in[13];
    const float* Wq  = (const float*)d_in[14];
    const float* bq  = (const float*)d_in[15];
    const float* Wk  = (const float*)d_in[16];
    const float* bk  = (const float*)d_in[17];
    const float* Wv  = (const float*)d_in[18];
    const float* bv  = (const float*)d_in[19];
    const float* Wo  = (const float*)d_in[20];
    const float* bo  = (const float*)d_in[21];
    const float* W1  = (const float*)d_in[22];
    const float* b1  = (const float*)d_in[23];
    const float* W2  = (const float*)d_in[24];
    const float* b2  = (const float*)d_in[25];
    const float* g1  = (const float*)d_in[26];
    const float* be1 = (const float*)d_in[27];
    const float* g2  = (const float*)d_in[28];
    const float* be2 = (const float*)d_in[29];

    float *SRC, *QKVp, *PROJ, *BQKV;
    __nv_bfloat16 *XH, *XL, *FFH, *FFL, *WqkvH, *WqkvL, *WoH, *WoL, *W1H, *W1L, *W2H, *W2L;
    cudaGetSymbolAddress((void**)&SRC,   g_SRC);
    cudaGetSymbolAddress((void**)&QKVp,  g_QKV);
    cudaGetSymbolAddress((void**)&PROJ,  g_PROJ);
    cudaGetSymbolAddress((void**)&XH,    g_XH);
    cudaGetSymbolAddress((void**)&XL,    g_XL);
    cudaGetSymbolAddress((void**)&FFH,   g_FFH);
    cudaGetSymbolAddress((void**)&FFL,   g_FFL);
    cudaGetSymbolAddress((void**)&WqkvH, g_WqkvH);
    cudaGetSymbolAddress((void**)&WqkvL, g_WqkvL);
    cudaGetSymbolAddress((void**)&WoH,   g_WoH);
    cudaGetSymbolAddress((void**)&WoL,   g_WoL);
    cudaGetSymbolAddress((void**)&W1H,   g_W1H);
    cudaGetSymbolAddress((void**)&W1L,   g_W1L);
    cudaGetSymbolAddress((void**)&W2H,   g_W2H);
    cudaGetSymbolAddress((void**)&W2L,   g_W2L);
    cudaGetSymbolAddress((void**)&BQKV,  g_bqkv);

    cudaFuncSetAttribute(gemm_kernel<false,false>, cudaFuncAttributeMaxDynamicSharedMemorySize, GSMEM);
    cudaFuncSetAttribute(gemm_kernel<true,true>,   cudaFuncAttributeMaxDynamicSharedMemorySize, GSMEM);
    cudaFuncSetAttribute(attn_mma_kernel,          cudaFuncAttributeMaxDynamicSharedMemorySize, ASMEM);

    // 5 setup launches, so launch #6 (first GEMM) is what ncu -s 5 captures
    build_src_kernel<<<1024, 256>>>(hand_t, head_t, hand_m1, head_m1,
                                    state_t, state_m1, tok_m1, tok_t);
    build_coord_kernel<<<98, 256>>>(c_hand_t, c_head_t, c_hand_m1, c_head_m1, tr_t, tr_m1);
    split_qkv_w_kernel<<<2048, 256>>>(Wq, Wk, Wv, bq, bk, bv);
    split_weights_kernel<<<4096, 256>>>(Wo, W1, W2);
    split_kernel<<<2048, 256>>>(SRC, XH, XL, MM*DD);

    const int MB = (MM + 255)/256;   // 33
    for (int l = 0; l < LL; l++) {
        gemm_kernel<false,false><<<dim3(MB, QKVN/128), 512, GSMEM>>>(MM, QKVN, DD, XH, XL,
            WqkvH + (size_t)l*QKVN*DD, WqkvL + (size_t)l*QKVN*DD, BQKV + l*QKVN, QKVp, nullptr, nullptr);
        rope_split_kernel<<<(64*SS + 255)/256, 256>>>();
        attn_mma_kernel<<<dim3(9, 64), 256, ASMEM>>>(XH, XL);
        gemm_kernel<false,false><<<dim3(MB, DD/128), 512, GSMEM>>>(MM, DD, DD, XH, XL,
            WoH + (size_t)l*DD*DD, WoL + (size_t)l*DD*DD, bo + l*DD, PROJ, nullptr, nullptr);
        add_ln_kernel<<<MM, 128>>>(SRC, PROJ, g1 + l*DD, be1 + l*DD, XH, XL);
        gemm_kernel<true,true><<<dim3(MB, FFD/128), 512, GSMEM>>>(MM, FFD, DD, XH, XL,
            W1H + (size_t)l*FFD*DD, W1L + (size_t)l*FFD*DD, b1 + l*FFD, nullptr, FFH, FFL);
        gemm_kernel<false,false><<<dim3(MB, DD/128), 512, GSMEM>>>(MM, DD, FFD, FFH, FFL,
            W2H + (size_t)l*DD*FFD, W2L + (size_t)l*DD*FFD, b2 + l*DD, PROJ, nullptr, nullptr);
        add_ln_kernel<<<MM, 128>>>(SRC, PROJ, g2 + l*DD, be2 + l*DD, XH, XL);
    }
    copy_out_kernel<<<48, 256>>>((float*)d_out);
}

// round 8
// speedup vs baseline: 1.2609x; 1.2609x over previous
#include <cuda_runtime.h>
#include <cuda_bf16.h>
#include <cuda_fp16.h>
#include <math.h>

#define BB 8
#define NN 256
#define DD 384
#define LL 6
#define HH 8
#define FFD 1536
#define TT 4
#define DH 48
#define NM1 517
#define SS 1034
#define SPAD 1152
#define MM (BB*SS)
#define QKVN 1152

// ---------------- scratch ----------------
__device__ float g_SRC [MM*DD];
__device__ float g_COORD[MM*3];
__device__ float g_QKV [MM*QKVN];
__device__ float g_PROJ[MM*DD];

__device__ __half g_XH[MM*DD];
__device__ __half g_XL[MM*DD];
__device__ __half g_FFH[MM*FFD];
__device__ __half g_FFL[MM*FFD];

__device__ __nv_bfloat16 g_QH[64*SPAD*DH];
__device__ __nv_bfloat16 g_QL[64*SPAD*DH];
__device__ __nv_bfloat16 g_KH[64*SPAD*DH];
__device__ __nv_bfloat16 g_KL[64*SPAD*DH];
__device__ __nv_bfloat16 g_VH[64*DH*SPAD];
__device__ __nv_bfloat16 g_VL[64*DH*SPAD];

__device__ __half g_WqkvH[LL*QKVN*DD];
__device__ __half g_WoH[LL*DD*DD];
__device__ __half g_W1H[LL*FFD*DD];
__device__ __half g_W2H[LL*DD*FFD];
__device__ float g_bqkv[LL*QKVN];

// ---------------- input assembly ----------------
__global__ void build_src_kernel(const float* __restrict__ hand_t, const float* __restrict__ head_t,
                                 const float* __restrict__ hand_m1, const float* __restrict__ head_m1,
                                 const float* __restrict__ state_t, const float* __restrict__ state_m1,
                                 const float* __restrict__ tok_m1, const float* __restrict__ tok_t)
{
    for (int idx = blockIdx.x*blockDim.x + threadIdx.x; idx < BB*SS*DD; idx += gridDim.x*blockDim.x) {
        int d = idx % DD;
        int s = (idx / DD) % SS;
        int b = idx / (DD*SS);
        float v;
        if      (s == 0)    v = state_m1[b*DD + d];
        else if (s < 257)   v = hand_m1[((b*NN)+(s-1  ))*DD + d];
        else if (s < 513)   v = head_m1[((b*NN)+(s-257))*DD + d];
        else if (s < 517)   v = tok_m1[(s-513)*DD + d];
        else if (s == 517)  v = state_t[b*DD + d];
        else if (s < 774)   v = hand_t[((b*NN)+(s-518))*DD + d];
        else if (s < 1030)  v = head_t[((b*NN)+(s-774))*DD + d];
        else                v = tok_t[(s-1030)*DD + d];
        g_SRC[idx] = v;
    }
}

__global__ void build_coord_kernel(const float* __restrict__ c_hand_t, const float* __restrict__ c_head_t,
                                   const float* __restrict__ c_hand_m1, const float* __restrict__ c_head_m1,
                                   const float* __restrict__ tr_t, const float* __restrict__ tr_m1)
{
    for (int idx = blockIdx.x*blockDim.x + threadIdx.x; idx < BB*SS*3; idx += gridDim.x*blockDim.x) {
        int cdim = idx % 3;
        int s = (idx/3) % SS;
        int b = idx / (3*SS);
        float v;
        if      (s == 0)    v = tr_m1[b*3+cdim];
        else if (s < 257)   v = c_hand_m1[((b*NN)+(s-1  ))*3 + cdim];
        else if (s < 513)   v = c_head_m1[((b*NN)+(s-257))*3 + cdim];
        else if (s < 517)   v = tr_m1[b*3+cdim];
        else if (s == 517)  v = tr_t[b*3+cdim];
        else if (s < 774)   v = c_hand_t[((b*NN)+(s-518))*3 + cdim];
        else if (s < 1030)  v = c_head_t[((b*NN)+(s-774))*3 + cdim];
        else                v = tr_t[b*3+cdim];
        g_COORD[idx] = v;
    }
}

// ---------------- fp32 -> fp16 hi/lo split (activations) ----------------
__global__ void split_kernel(const float* __restrict__ x,
                             __half* __restrict__ hi, __half* __restrict__ lo, int n)
{
    for (int i = blockIdx.x*blockDim.x + threadIdx.x; i < n; i += gridDim.x*blockDim.x) {
        float v = x[i];
        __half h = __float2half_rn(v);
        hi[i] = h;
        lo[i] = __float2half_rn(v - __half2float(h));
    }
}

// pack Wq/Wk/Wv -> fp16 hi, and bias
__global__ void split_qkv_w_kernel(const float* __restrict__ Wq, const float* __restrict__ Wk,
                                   const float* __restrict__ Wv, const float* __restrict__ bq,
                                   const float* __restrict__ bk, const float* __restrict__ bv)
{
    int tid0 = blockIdx.x*blockDim.x + threadIdx.x;
    if (tid0 < LL*QKVN) {
        int r = tid0 % QKVN, l = tid0 / QKVN;
        float v;
        if      (r < DD)   v = bq[l*DD + r];
        else if (r < 2*DD) v = bk[l*DD + r-DD];
        else               v = bv[l*DD + r-2*DD];
        g_bqkv[tid0] = v;
    }
    const int total = LL*QKVN*DD;
    for (int idx = tid0; idx < total; idx += gridDim.x*blockDim.x) {
        int k = idx % DD;
        int r = (idx / DD) % QKVN;
        int l = idx / (DD*QKVN);
        float v;
        if      (r < DD)    v = Wq[((size_t)l*DD + r      )*DD + k];
        else if (r < 2*DD)  v = Wk[((size_t)l*DD + r-DD   )*DD + k];
        else                v = Wv[((size_t)l*DD + r-2*DD )*DD + k];
        g_WqkvH[idx] = __float2half_rn(v);
    }
}

__global__ void split_weights_kernel(const float* __restrict__ Wo, const float* __restrict__ W1,
                                     const float* __restrict__ W2)
{
    const int S1 = DD*DD, S2 = FFD*DD, S3 = DD*FFD;
    const int SEG = S1 + S2 + S3;
    const int total = LL*SEG;
    for (int idx = blockIdx.x*blockDim.x + threadIdx.x; idx < total; idx += gridDim.x*blockDim.x) {
        int l = idx / SEG, r = idx % SEG;
        if (r < S1)         g_WoH[(size_t)l*S1 + r]      = __float2half_rn(Wo[(size_t)l*S1 + r]);
        else if (r < S1+S2) g_W1H[(size_t)l*S2 + r-S1]   = __float2half_rn(W1[(size_t)l*S2 + r-S1]);
        else                g_W2H[(size_t)l*S3 + r-S1-S2]= __float2half_rn(W2[(size_t)l*S3 + r-S1-S2]);
    }
}

// ---------------- helpers ----------------
__device__ __forceinline__ unsigned smem_addr(const void* p) {
    return (unsigned)__cvta_generic_to_shared(p);
}
__device__ __forceinline__ void ldsm_x4(unsigned r[4], unsigned addr) {
    asm volatile("ldmatrix.sync.aligned.m8n8.x4.shared.b16 {%0,%1,%2,%3}, [%4];"
                 : "=r"(r[0]), "=r"(r[1]), "=r"(r[2]), "=r"(r[3]) : "r"(addr));
}
__device__ __forceinline__ void mma_bf16(float c[4], const unsigned a[4], const unsigned b[2]) {
    asm volatile("mma.sync.aligned.m16n8k16.row.col.f32.bf16.bf16.f32 "
                 "{%0,%1,%2,%3}, {%4,%5,%6,%7}, {%8,%9}, {%0,%1,%2,%3};"
                 : "+f"(c[0]), "+f"(c[1]), "+f"(c[2]), "+f"(c[3])
                 : "r"(a[0]), "r"(a[1]), "r"(a[2]), "r"(a[3]), "r"(b[0]), "r"(b[1]));
}
__device__ __forceinline__ void mma_f16(float c[4], const unsigned a[4], const unsigned b[2]) {
    asm volatile("mma.sync.aligned.m16n8k16.row.col.f32.f16.f16.f32 "
                 "{%0,%1,%2,%3}, {%4,%5,%6,%7}, {%8,%9}, {%0,%1,%2,%3};"
                 : "+f"(c[0]), "+f"(c[1]), "+f"(c[2]), "+f"(c[3])
                 : "r"(a[0]), "r"(a[1]), "r"(a[2]), "r"(a[3]), "r"(b[0]), "r"(b[1]));
}
__device__ __forceinline__ void cpa16(unsigned dst, const void* src, bool pred) {
    int sz = pred ? 16 : 0;
    asm volatile("cp.async.cg.shared.global [%0], [%1], 16, %2;"
                 :: "r"(dst), "l"(src), "r"(sz) : "memory");
}
#define CP_COMMIT() asm volatile("cp.async.commit_group;" ::: "memory")
#define CP_WAIT1()  asm volatile("cp.async.wait_group 1;" ::: "memory")
#define CP_WAIT0()  asm volatile("cp.async.wait_group 0;" ::: "memory")

// bf16 pack (attention internals)
__device__ __forceinline__ void split2(float a, float b, unsigned &h, unsigned &l) {
    __nv_bfloat162 hh = __floats2bfloat162_rn(a, b);
    h = *(unsigned*)&hh;
    float ra = a - __bfloat162float(hh.x);
    float rb = b - __bfloat162float(hh.y);
    __nv_bfloat162 ll = __floats2bfloat162_rn(ra, rb);
    l = *(unsigned*)&ll;
}
// fp16 pack (GEMM activations)
__device__ __forceinline__ void split2h(float a, float b, unsigned &h, unsigned &l) {
    __half2 hh = __floats2half2_rn(a, b);
    h = *(unsigned*)&hh;
    float ra = a - __half2float(__low2half(hh));
    float rb = b - __half2float(__high2half(hh));
    __half2 ll = __floats2half2_rn(ra, rb);
    l = *(unsigned*)&ll;
}

// ---------------- fp16x2 GEMM: BM=128, BN=128, BK=32, 256 thr, 2-stage cp.async ----------
// C = (Ah+Al)*Wh + bias ; A fp16 hi/lo, W fp16 hi only. 2 MMAs per tile-step.
#define LDSMP 40
#define GARRB (128*LDSMP*2)          // 10240 bytes per operand array
#define GSTG (3*GARRB)               // Ah, Al, Wh
#define GSMEM (2*GSTG)               // 61440

template<bool DO_GELU, bool SPLIT_OUT>
__global__ void __launch_bounds__(256) gemm_kernel(int M, int N, int K,
    const __half* __restrict__ Ah, const __half* __restrict__ Al,
    const __half* __restrict__ Wh,
    const float* __restrict__ bias, float* __restrict__ C,
    __half* __restrict__ Ch, __half* __restrict__ Cl)
{
    extern __shared__ __half dsm[];
    const int tid  = threadIdx.x;
    const int lane = tid & 31;
    const int warp = tid >> 5;
    const int wm   = warp >> 2;
    const int wn   = warp & 3;
    const int m0   = blockIdx.x * 128;
    const int n0   = blockIdx.y * 128;

    float c[4][4][4];
    #pragma unroll
    for (int i = 0; i < 4; i++)
        #pragma unroll
        for (int j = 0; j < 4; j++)
            #pragma unroll
            for (int r = 0; r < 4; r++) c[i][j][r] = 0.f;

    const int lr = tid >> 2;
    const int lc = (tid & 3) * 8;

    const int aRow    = wm*64 + (lane & 7) + ((lane >> 3) & 1) * 8;
    const int aColSel = (lane >> 4) * 8;
    const int bRow    = wn*32 + (lane & 7) + ((lane >> 4) & 1) * 8;
    const int bColSel = ((lane >> 3) & 1) * 8;

    const unsigned sbase = smem_addr(dsm);

    auto load_tile = [&](int kt, int stage) {
        const int kc = kt * 32;
        const unsigned sb = sbase + stage*GSTG;
        #pragma unroll
        for (int half = 0; half < 2; half++) {
            int r  = lr + half*64;
            int gm = m0 + r;
            bool pa = gm < M;
            int gmc = pa ? gm : 0;
            unsigned drow = (unsigned)((r*LDSMP + lc) * 2);
            cpa16(sb + drow,           Ah + (size_t)gmc*K + kc + lc, pa);
            cpa16(sb + GARRB + drow,   Al + (size_t)gmc*K + kc + lc, pa);
            cpa16(sb + 2*GARRB + drow, Wh + (size_t)(n0 + r)*K + kc + lc, true);
        }
    };

    const int nk = K >> 5;
    load_tile(0, 0);
    CP_COMMIT();

    for (int kt = 0; kt < nk; kt++) {
        const int cur = kt & 1;
        if (kt + 1 < nk) load_tile(kt + 1, cur ^ 1);
        CP_COMMIT();
        CP_WAIT1();
        __syncthreads();

        const unsigned sb    = sbase + cur*GSTG;
        const unsigned sAh_b = sb;
        const unsigned sAl_b = sb + GARRB;
        const unsigned sWh_b = sb + 2*GARRB;

        #pragma unroll
        for (int kk = 0; kk < 2; kk++) {
            unsigned ah[4][4], al[4][4], bh[4][2];
            #pragma unroll
            for (int mt = 0; mt < 4; mt++) {
                unsigned off = (unsigned)(((aRow + mt*16)*LDSMP + kk*16 + aColSel) * 2);
                ldsm_x4(ah[mt], sAh_b + off);
                ldsm_x4(al[mt], sAl_b + off);
            }
            #pragma unroll
            for (int np = 0; np < 2; np++) {
                unsigned off = (unsigned)(((bRow + np*16)*LDSMP + kk*16 + bColSel) * 2);
                unsigned t[4];
                ldsm_x4(t, sWh_b + off);
                bh[2*np][0]=t[0]; bh[2*np][1]=t[1]; bh[2*np+1][0]=t[2]; bh[2*np+1][1]=t[3];
            }
            #pragma unroll
            for (int mt = 0; mt < 4; mt++)
                #pragma unroll
                for (int nt = 0; nt < 4; nt++) {
                    mma_f16(c[mt][nt], ah[mt], bh[nt]);
                    mma_f16(c[mt][nt], al[mt], bh[nt]);
                }
        }
        __syncthreads();
    }

    #pragma unroll
    for (int mt = 0; mt < 4; mt++) {
        #pragma unroll
        for (int nt = 0; nt < 4; nt++) {
            int col  = n0 + wn*32 + nt*8 + (lane & 3)*2;
            float b0 = bias[col], b1 = bias[col+1];
            int row0 = m0 + wm*64 + mt*16 + (lane >> 2);
            int row1 = row0 + 8;
            float v0 = c[mt][nt][0] + b0, v1 = c[mt][nt][1] + b1;
            float v2 = c[mt][nt][2] + b0, v3 = c[mt][nt][3] + b1;
            if (DO_GELU) {
                v0 = 0.5f*v0*(1.0f+erff(v0*0.7071067811865475f));
                v1 = 0.5f*v1*(1.0f+erff(v1*0.7071067811865475f));
                v2 = 0.5f*v2*(1.0f+erff(v2*0.7071067811865475f));
                v3 = 0.5f*v3*(1.0f+erff(v3*0.7071067811865475f));
            }
            if (SPLIT_OUT) {
                unsigned h01, l01, h23, l23;
                split2h(v0, v1, h01, l01);
                split2h(v2, v3, h23, l23);
                if (row0 < M) { *(unsigned*)&Ch[(size_t)row0*N + col] = h01;
                                *(unsigned*)&Cl[(size_t)row0*N + col] = l01; }
                if (row1 < M) { *(unsigned*)&Ch[(size_t)row1*N + col] = h23;
                                *(unsigned*)&Cl[(size_t)row1*N + col] = l23; }
            } else {
                if (row0 < M) *(float2*)&C[(size_t)row0*N + col] = make_float2(v0, v1);
                if (row1 < M) *(float2*)&C[(size_t)row1*N + col] = make_float2(v2, v3);
            }
        }
    }
}

// ---------------- rope + split + relayout (attention operands, bf16) ----------------
__global__ void __launch_bounds__(256) rope_split_kernel()
{
    int t = blockIdx.x*blockDim.x + threadIdx.x;
    if (t >= 64*SS) return;
    int s  = t % SS;
    int bh = t / SS;
    int b = bh >> 3, h = bh & 7;

    const float* src = g_QKV + ((size_t)(b*SS + s))*QKVN + h*DH;
    float q[48], k[48], v[48];
    #pragma unroll
    for (int i = 0; i < 12; i++) {
        *(float4*)&q[i*4] = *(const float4*)(src + i*4);
        *(float4*)&k[i*4] = *(const float4*)(src + DD + i*4);
        *(float4*)&v[i*4] = *(const float4*)(src + 2*DD + i*4);
    }

    float invf[8];
    #pragma unroll
    for (int j = 0; j < 8; j++)
        invf[j] = exp2f(-1.6609640474436813f * (float)j);

    #pragma unroll
    for (int a = 0; a < 3; a++) {
        float co = g_COORD[(b*SS + s)*3 + a];
        #pragma unroll
        for (int j = 0; j < 8; j++) {
            float ang = co * invf[j];
            float cs = cosf(ang), sn = sinf(ang);
            int i1 = a*16 + j, i2 = i1 + 8;
            float q1 = q[i1], q2 = q[i2];
            q[i1] = q1*cs - q2*sn;  q[i2] = q1*sn + q2*cs;
            float k1 = k[i1], k2 = k[i2];
            k[i1] = k1*cs - k2*sn;  k[i2] = k1*sn + k2*cs;
        }
    }

    const float scale = 0.14433756729740643f;
    size_t qkbase = ((size_t)bh*SPAD + s)*DH;
    #pragma unroll
    for (int d = 0; d < 48; d++) {
        float qq = q[d]*scale;
        __nv_bfloat16 hh = __float2bfloat16_rn(qq);
        g_QH[qkbase + d] = hh;
        g_QL[qkbase + d] = __float2bfloat16_rn(qq - __bfloat162float(hh));
        hh = __float2bfloat16_rn(k[d]);
        g_KH[qkbase + d] = hh;
        g_KL[qkbase + d] = __float2bfloat16_rn(k[d] - __bfloat162float(hh));
        hh = __float2bfloat16_rn(v[d]);
        size_t vi = ((size_t)bh*DH + d)*SPAD + s;
        g_VH[vi] = hh;
        g_VL[vi] = __float2bfloat16_rn(v[d] - __bfloat162float(hh));
    }
}

// ---------------- tensor-core flash attention (bf16x3, 64-row tiles) ----------------
#define QKP 56
#define VTP 72

__global__ void __launch_bounds__(128) attn_mma_kernel(__half* __restrict__ AH,
                                                       __half* __restrict__ AL)
{
    const int bh = blockIdx.y;
    const int b = bh >> 3, h = bh & 7;
    const int q0 = blockIdx.x * 64;
    const int tid = threadIdx.x;
    const int lane = tid & 31;
    const int warp = tid >> 5;

    __shared__ __nv_bfloat16 sQh[64*QKP], sQl[64*QKP];
    __shared__ __nv_bfloat16 sKh[64*QKP], sKl[64*QKP];
    __shared__ __nv_bfloat16 sVh[48*VTP], sVl[48*VTP];

    const unsigned sQh_b = smem_addr(sQh), sQl_b = smem_addr(sQl);
    const unsigned sKh_b = smem_addr(sKh), sKl_b = smem_addr(sKl);
    const unsigned sVh_b = smem_addr(sVh), sVl_b = smem_addr(sVl);

    const size_t qkBase = (size_t)bh*SPAD*DH;
    const size_t vBase  = (size_t)bh*DH*SPAD;

    #pragma unroll
    for (int i = 0; i < 3; i++) {
        int cidx = tid + i*128;
        int row = cidx / 6, off = (cidx % 6) * 8;
        unsigned d = (unsigned)((row*QKP + off) * 2);
        const size_t g = qkBase + (size_t)(q0 + row)*DH + off;
        cpa16(sQh_b + d, g_QH + g, true);
        cpa16(sQl_b + d, g_QL + g, true);
    }
    CP_COMMIT(); CP_WAIT0();
    __syncthreads();

    const int aRow = 16*warp + (lane & 7) + ((lane >> 3) & 1) * 8;
    const int aColSel = (lane >> 4) * 8;
    unsigned qh[3][4], ql[3][4];
    #pragma unroll
    for (int kk = 0; kk < 3; kk++) {
        unsigned off = (unsigned)((aRow*QKP + kk*16 + aColSel) * 2);
        ldsm_x4(qh[kk], sQh_b + off);
        ldsm_x4(ql[kk], sQl_b + off);
    }

    float o[6][4];
    #pragma unroll
    for (int i = 0; i < 6; i++)
        #pragma unroll
        for (int j = 0; j < 4; j++) o[i][j] = 0.f;
    float m0r = -1e30f, m1r = -1e30f, l0 = 0.f, l1 = 0.f;

    const int row0 = q0 + 16*warp + (lane >> 2);
    const int row1 = row0 + 8;
    const bool rm0 = row0 < NM1, rm1 = row1 < NM1;

    const int bRowSel = (lane & 7) + ((lane >> 4) & 1) * 8;
    const int bColSel = ((lane >> 3) & 1) * 8;

    for (int kt = 0; kt < 17; kt++) {
        int k0 = kt * 64;
        if ((q0 + 63 < NM1) && (k0 >= NM1)) continue;

        __syncthreads();
        #pragma unroll
        for (int i = 0; i < 3; i++) {
            int cidx = tid + i*128;
            int row = cidx / 6, off = (cidx % 6) * 8;
            unsigned d = (unsigned)((row*QKP + off) * 2);
            const size_t g = qkBase + (size_t)(k0 + row)*DH + off;
            cpa16(sKh_b + d, g_KH + g, true);
            cpa16(sKl_b + d, g_KL + g, true);
        }
        #pragma unroll
        for (int i = 0; i < 3; i++) {
            int cidx = tid + i*128;
            int row = cidx / 8, off = (cidx % 8) * 8;
            unsigned d = (unsigned)((row*VTP + off) * 2);
            const size_t g = vBase + (size_t)row*SPAD + k0 + off;
            cpa16(sVh_b + d, g_VH + g, true);
            cpa16(sVl_b + d, g_VL + g, true);
        }
        CP_COMMIT(); CP_WAIT0();
        __syncthreads();

        float s[8][4];
        #pragma unroll
        for (int i = 0; i < 8; i++)
            #pragma unroll
            for (int j = 0; j < 4; j++) s[i][j] = 0.f;

        #pragma unroll
        for (int kk = 0; kk < 3; kk++) {
            unsigned bhf[8][2], blf[8][2];
            #pragma unroll
            for (int nb = 0; nb < 4; nb++) {
                unsigned off = (unsigned)(((nb*16 + bRowSel)*QKP + kk*16 + bColSel) * 2);
                unsigned t[4];
                ldsm_x4(t, sKh_b + off);
                bhf[2*nb][0]=t[0]; bhf[2*nb][1]=t[1]; bhf[2*nb+1][0]=t[2]; bhf[2*nb+1][1]=t[3];
                ldsm_x4(t, sKl_b + off);
                blf[2*nb][0]=t[0]; blf[2*nb][1]=t[1]; blf[2*nb+1][0]=t[2]; blf[2*nb+1][1]=t[3];
            }
            #pragma unroll
            for (int nt = 0; nt < 8; nt++) {
                mma_bf16(s[nt], qh[kk], bhf[nt]);
                mma_bf16(s[nt], ql[kk], bhf[nt]);
                mma_bf16(s[nt], qh[kk], blf[nt]);
            }
        }

        #pragma unroll
        for (int nt = 0; nt < 8; nt++) {
            #pragma unroll
            for (int e = 0; e < 2; e++) {
                int col = k0 + nt*8 + (lane & 3)*2 + e;
                bool cmm = (col >= SS);
                bool cnm = (col >= NM1);
                if (cmm || (rm0 && cnm)) s[nt][e]   = -1e30f;
                if (cmm || (rm1 && cnm)) s[nt][2+e] = -1e30f;
            }
        }

        float t0 = -1e30f, t1 = -1e30f;
        #pragma unroll
        for (int nt = 0; nt < 8; nt++) {
            t0 = fmaxf(t0, fmaxf(s[nt][0], s[nt][1]));
            t1 = fmaxf(t1, fmaxf(s[nt][2], s[nt][3]));
        }
        t0 = fmaxf(t0, __shfl_xor_sync(0xffffffffu, t0, 1));
        t0 = fmaxf(t0, __shfl_xor_sync(0xffffffffu, t0, 2));
        t1 = fmaxf(t1, __shfl_xor_sync(0xffffffffu, t1, 1));
        t1 = fmaxf(t1, __shfl_xor_sync(0xffffffffu, t1, 2));
        float nm0 = fmaxf(m0r, t0), nm1 = fmaxf(m1r, t1);
        float f0 = __expf(m0r - nm0), f1 = __expf(m1r - nm1);
        m0r = nm0; m1r = nm1;

        float ps0 = 0.f, ps1 = 0.f;
        #pragma unroll
        for (int nt = 0; nt < 8; nt++) {
            s[nt][0] = __expf(s[nt][0] - m0r);
            s[nt][1] = __expf(s[nt][1] - m0r);
            s[nt][2] = __expf(s[nt][2] - m1r);
            s[nt][3] = __expf(s[nt][3] - m1r);
            ps0 += s[nt][0] + s[nt][1];
            ps1 += s[nt][2] + s[nt][3];
        }
        ps0 += __shfl_xor_sync(0xffffffffu, ps0, 1);
        ps0 += __shfl_xor_sync(0xffffffffu, ps0, 2);
        ps1 += __shfl_xor_sync(0xffffffffu, ps1, 1);
        ps1 += __shfl_xor_sync(0xffffffffu, ps1, 2);
        l0 = l0*f0 + ps0;
        l1 = l1*f1 + ps1;
        #pragma unroll
        for (int nt = 0; nt < 6; nt++) {
            o[nt][0] *= f0; o[nt][1] *= f0;
            o[nt][2] *= f1; o[nt][3] *= f1;
        }

        #pragma unroll
        for (int kk = 0; kk < 4; kk++) {
            unsigned pah[4], pal[4];
            split2(s[2*kk  ][0], s[2*kk  ][1], pah[0], pal[0]);
            split2(s[2*kk  ][2], s[2*kk  ][3], pah[1], pal[1]);
            split2(s[2*kk+1][0], s[2*kk+1][1], pah[2], pal[2]);
            split2(s[2*kk+1][2], s[2*kk+1][3], pah[3], pal[3]);

            unsigned vbh[6][2], vbl[6][2];
            #pragma unroll
            for (int nb = 0; nb < 3; nb++) {
                unsigned off = (unsigned)(((nb*16 + bRowSel)*VTP + kk*16 + bColSel) * 2);
                unsigned t[4];
                ldsm_x4(t, sVh_b + off);
                vbh[2*nb][0]=t[0]; vbh[2*nb][1]=t[1]; vbh[2*nb+1][0]=t[2]; vbh[2*nb+1][1]=t[3];
                ldsm_x4(t, sVl_b + off);
                vbl[2*nb][0]=t[0]; vbl[2*nb][1]=t[1]; vbl[2*nb+1][0]=t[2]; vbl[2*nb+1][1]=t[3];
            }
            #pragma unroll
            for (int nt = 0; nt < 6; nt++) {
                mma_bf16(o[nt], pah, vbh[nt]);
                mma_bf16(o[nt], pal, vbh[nt]);
                mma_bf16(o[nt], pah, vbl[nt]);
            }
        }
    }

    float il0 = 1.f / l0, il1 = 1.f / l1;
    #pragma unroll
    for (int nt = 0; nt < 6; nt++) {
        int col = h*DH + nt*8 + (lane & 3)*2;
        if (row0 < SS) {
            unsigned hh, ll;
            split2h(o[nt][0]*il0, o[nt][1]*il0, hh, ll);
            *(unsigned*)&AH[(size_t)(b*SS + row0)*DD + col] = hh;
            *(unsigned*)&AL[(size_t)(b*SS + row0)*DD + col] = ll;
        }
        if (row1 < SS) {
            unsigned hh, ll;
            split2h(o[nt][2]*il1, o[nt][3]*il1, hh, ll);
            *(unsigned*)&AH[(size_t)(b*SS + row1)*DD + col] = hh;
            *(unsigned*)&AL[(size_t)(b*SS + row1)*DD + col] = ll;
        }
    }
}

// ---------------- residual add + layernorm (writes fp32 + fp16 hi/lo) ----------------
__global__ void __launch_bounds__(128) add_ln_kernel(float* __restrict__ src, const float* __restrict__ res,
                                                     const float* __restrict__ g, const float* __restrict__ bta,
                                                     __half* __restrict__ XH, __half* __restrict__ XL)
{
    int row = blockIdx.x;
    int tid = threadIdx.x;
    float x[3];
    float s = 0.f, sq = 0.f;
    #pragma unroll
    for (int i = 0; i < 3; i++) {
        int d = tid + i*128;
        float v = src[(size_t)row*DD + d] + res[(size_t)row*DD + d];
        x[i] = v; s += v; sq += v*v;
    }
    #pragma unroll
    for (int o = 16; o > 0; o >>= 1) {
        s  += __shfl_xor_sync(0xffffffffu, s,  o);
        sq += __shfl_xor_sync(0xffffffffu, sq, o);
    }
    __shared__ float ss[4], ssq[4];
    int w = tid >> 5;
    if ((tid & 31) == 0) { ss[w] = s; ssq[w] = sq; }
    __syncthreads();
    s  = ss[0]+ss[1]+ss[2]+ss[3];
    sq = ssq[0]+ssq[1]+ssq[2]+ssq[3];
    float mean = s * (1.f/384.f);
    float var  = sq * (1.f/384.f) - mean*mean;
    float rs = rsqrtf(var + 1e-5f);
    #pragma unroll
    for (int i = 0; i < 3; i++) {
        int d = tid + i*128;
        float y = (x[i]-mean)*rs*g[d] + bta[d];
        src[(size_t)row*DD + d] = y;
        __half hh = __float2half_rn(y);
        XH[(size_t)row*DD + d] = hh;
        XL[(size_t)row*DD + d] = __float2half_rn(y - __half2float(hh));
    }
}

__global__ void copy_out_kernel(float* __restrict__ out)
{
    int idx = blockIdx.x*blockDim.x + threadIdx.x;
    if (idx >= BB*TT*DD) return;
    int d = idx % DD;
    int t = (idx/DD) % TT;
    int b = idx / (DD*TT);
    out[idx] = g_SRC[((size_t)(b*SS + (SS-TT) + t))*DD + d];
}

// ---------------- host launcher ----------------
extern "C" void kernel_launch(void* const* d_in, const int* in_sizes, int n_in,
                              void* d_out, int out_size)
{
    (void)in_sizes; (void)n_in; (void)out_size;
    const float* hand_t    = (const float*)d_in[0];
    const float* head_t    = (const float*)d_in[1];
    const float* hand_m1   = (const float*)d_in[2];
    const float* head_m1   = (const float*)d_in[3];
    const float* c_hand_t  = (const float*)d_in[4];
    const float* c_head_t  = (const float*)d_in[5];
    const float* c_hand_m1 = (const float*)d_in[6];
    const float* c_head_m1 = (const float*)d_in[7];
    const float* state_t   = (const float*)d_in[8];
    const float* state_m1  = (const float*)d_in[9];
    const float* tr_t      = (const float*)d_in[10];
    const float* tr_m1     = (const float*)d_in[11];
    const float* tok_m1    = (const float*)d_in[12];
    const float* tok_t     = (const float*)d_in[13];
    const float* Wq  = (const float*)d_in[14];
    const float* bq  = (const float*)d_in[15];
    const float* Wk  = (const float*)d_in[16];
    const float* bk  = (const float*)d_in[17];
    const float* Wv  = (const float*)d_in[18];
    const float* bv  = (const float*)d_in[19];
    const float* Wo  = (const float*)d_in[20];
    const float* bo  = (const float*)d_in[21];
    const float* W1  = (const float*)d_in[22];
    const float* b1  = (const float*)d_in[23];
    const float* W2  = (const float*)d_in[24];
    const float* b2  = (const float*)d_in[25];
    const float* g1  = (const float*)d_in[26];
    const float* be1 = (const float*)d_in[27];
    const float* g2  = (const float*)d_in[28];
    const float* be2 = (const float*)d_in[29];

    float *SRC, *QKVp, *PROJ, *BQKV;
    __half *XH, *XL, *FFH, *FFL, *WqkvH, *WoH, *W1H, *W2H;
    cudaGetSymbolAddress((void**)&SRC,   g_SRC);
    cudaGetSymbolAddress((void**)&QKVp,  g_QKV);
    cudaGetSymbolAddress((void**)&PROJ,  g_PROJ);
    cudaGetSymbolAddress((void**)&XH,    g_XH);
    cudaGetSymbolAddress((void**)&XL,    g_XL);
    cudaGetSymbolAddress((void**)&FFH,   g_FFH);
    cudaGetSymbolAddress((void**)&FFL,   g_FFL);
    cudaGetSymbolAddress((void**)&WqkvH, g_WqkvH);
    cudaGetSymbolAddress((void**)&WoH,   g_WoH);
    cudaGetSymbolAddress((void**)&W1H,   g_W1H);
    cudaGetSymbolAddress((void**)&W2H,   g_W2H);
    cudaGetSymbolAddress((void**)&BQKV,  g_bqkv);

    cudaFuncSetAttribute(gemm_kernel<false,false>, cudaFuncAttributeMaxDynamicSharedMemorySize, GSMEM);
    cudaFuncSetAttribute(gemm_kernel<true,true>,   cudaFuncAttributeMaxDynamicSharedMemorySize, GSMEM);

    build_src_kernel<<<1024, 256>>>(hand_t, head_t, hand_m1, head_m1,
                                    state_t, state_m1, tok_m1, tok_t);
    build_coord_kernel<<<98, 256>>>(c_hand_t, c_head_t, c_hand_m1, c_head_m1, tr_t, tr_m1);
    split_qkv_w_kernel<<<2048, 256>>>(Wq, Wk, Wv, bq, bk, bv);
    split_weights_kernel<<<4096, 256>>>(Wo, W1, W2);
    split_kernel<<<2048, 256>>>(SRC, XH, XL, MM*DD);

    const int MB = (MM + 127)/128;   // 65
    for (int l = 0; l < LL; l++) {
        gemm_kernel<false,false><<<dim3(MB, QKVN/128), 256, GSMEM>>>(MM, QKVN, DD, XH, XL,
            WqkvH + (size_t)l*QKVN*DD, BQKV + l*QKVN, QKVp, nullptr, nullptr);
        rope_split_kernel<<<(64*SS + 255)/256, 256>>>();
        attn_mma_kernel<<<dim3(17, 64), 128>>>(XH, XL);
        gemm_kernel<false,false><<<dim3(MB, DD/128), 256, GSMEM>>>(MM, DD, DD, XH, XL,
            WoH + (size_t)l*DD*DD, bo + l*DD, PROJ, nullptr, nullptr);
        add_ln_kernel<<<MM, 128>>>(SRC, PROJ, g1 + l*DD, be1 + l*DD, XH, XL);
        gemm_kernel<true,true><<<dim3(MB, FFD/128), 256, GSMEM>>>(MM, FFD, DD, XH, XL,
            W1H + (size_t)l*FFD*DD, b1 + l*FFD, nullptr, FFH, FFL);
        gemm_kernel<false,false><<<dim3(MB, DD/128), 256, GSMEM>>>(MM, DD, FFD, FFH, FFL,
            W2H + (size_t)l*DD*FFD, b2 + l*DD, PROJ, nullptr, nullptr);
        add_ln_kernel<<<MM, 128>>>(SRC, PROJ, g2 + l*DD, be2 + l*DD, XH, XL);
    }
    copy_out_kernel<<<48, 256>>>((float*)d_out);
}

// round 9
// speedup vs baseline: 1.7943x; 1.4231x over previous
#include <cuda_runtime.h>
#include <cuda_fp16.h>
#include <math.h>

#define BB 8
#define NN 256
#define DD 384
#define LL 6
#define HH 8
#define FFD 1536
#define TT 4
#define DH 48
#define NM1 517
#define SS 1034
#define SPAD 1152
#define MM (BB*SS)
#define QKVN 1152

// ---------------- scratch ----------------
__device__ float g_SRC [MM*DD];
__device__ float g_COORD[MM*3];
__device__ float g_QKV [MM*QKVN];
__device__ float g_PROJ[MM*DD];

__device__ __half g_XH[MM*DD];
__device__ __half g_FFH[MM*FFD];

__device__ __half g_QH[64*SPAD*DH];
__device__ __half g_QL[64*SPAD*DH];
__device__ __half g_KH[64*SPAD*DH];
__device__ __half g_VH[64*DH*SPAD];

__device__ __half g_WqkvH[LL*QKVN*DD];
__device__ __half g_WoH[LL*DD*DD];
__device__ __half g_W1H[LL*FFD*DD];
__device__ __half g_W2H[LL*DD*FFD];
__device__ float g_bqkv[LL*QKVN];

// ---------------- input assembly ----------------
__global__ void build_src_kernel(const float* __restrict__ hand_t, const float* __restrict__ head_t,
                                 const float* __restrict__ hand_m1, const float* __restrict__ head_m1,
                                 const float* __restrict__ state_t, const float* __restrict__ state_m1,
                                 const float* __restrict__ tok_m1, const float* __restrict__ tok_t)
{
    for (int idx = blockIdx.x*blockDim.x + threadIdx.x; idx < BB*SS*DD; idx += gridDim.x*blockDim.x) {
        int d = idx % DD;
        int s = (idx / DD) % SS;
        int b = idx / (DD*SS);
        float v;
        if      (s == 0)    v = state_m1[b*DD + d];
        else if (s < 257)   v = hand_m1[((b*NN)+(s-1  ))*DD + d];
        else if (s < 513)   v = head_m1[((b*NN)+(s-257))*DD + d];
        else if (s < 517)   v = tok_m1[(s-513)*DD + d];
        else if (s == 517)  v = state_t[b*DD + d];
        else if (s < 774)   v = hand_t[((b*NN)+(s-518))*DD + d];
        else if (s < 1030)  v = head_t[((b*NN)+(s-774))*DD + d];
        else                v = tok_t[(s-1030)*DD + d];
        g_SRC[idx] = v;
    }
}

__global__ void build_coord_kernel(const float* __restrict__ c_hand_t, const float* __restrict__ c_head_t,
                                   const float* __restrict__ c_hand_m1, const float* __restrict__ c_head_m1,
                                   const float* __restrict__ tr_t, const float* __restrict__ tr_m1)
{
    for (int idx = blockIdx.x*blockDim.x + threadIdx.x; idx < BB*SS*3; idx += gridDim.x*blockDim.x) {
        int cdim = idx % 3;
        int s = (idx/3) % SS;
        int b = idx / (3*SS);
        float v;
        if      (s == 0)    v = tr_m1[b*3+cdim];
        else if (s < 257)   v = c_hand_m1[((b*NN)+(s-1  ))*3 + cdim];
        else if (s < 513)   v = c_head_m1[((b*NN)+(s-257))*3 + cdim];
        else if (s < 517)   v = tr_m1[b*3+cdim];
        else if (s == 517)  v = tr_t[b*3+cdim];
        else if (s < 774)   v = c_hand_t[((b*NN)+(s-518))*3 + cdim];
        else if (s < 1030)  v = c_head_t[((b*NN)+(s-774))*3 + cdim];
        else                v = tr_t[b*3+cdim];
        g_COORD[idx] = v;
    }
}

// ---------------- fp32 -> fp16 (activations, hi only) ----------------
__global__ void split_kernel(const float* __restrict__ x, __half* __restrict__ hi, int n)
{
    for (int i = blockIdx.x*blockDim.x + threadIdx.x; i < n; i += gridDim.x*blockDim.x)
        hi[i] = __float2half_rn(x[i]);
}

__global__ void split_qkv_w_kernel(const float* __restrict__ Wq, const float* __restrict__ Wk,
                                   const float* __restrict__ Wv, const float* __restrict__ bq,
                                   const float* __restrict__ bk, const float* __restrict__ bv)
{
    int tid0 = blockIdx.x*blockDim.x + threadIdx.x;
    if (tid0 < LL*QKVN) {
        int r = tid0 % QKVN, l = tid0 / QKVN;
        float v;
        if      (r < DD)   v = bq[l*DD + r];
        else if (r < 2*DD) v = bk[l*DD + r-DD];
        else               v = bv[l*DD + r-2*DD];
        g_bqkv[tid0] = v;
    }
    const int total = LL*QKVN*DD;
    for (int idx = tid0; idx < total; idx += gridDim.x*blockDim.x) {
        int k = idx % DD;
        int r = (idx / DD) % QKVN;
        int l = idx / (DD*QKVN);
        float v;
        if      (r < DD)    v = Wq[((size_t)l*DD + r      )*DD + k];
        else if (r < 2*DD)  v = Wk[((size_t)l*DD + r-DD   )*DD + k];
        else                v = Wv[((size_t)l*DD + r-2*DD )*DD + k];
        g_WqkvH[idx] = __float2half_rn(v);
    }
}

__global__ void split_weights_kernel(const float* __restrict__ Wo, const float* __restrict__ W1,
                                     const float* __restrict__ W2)
{
    const int S1 = DD*DD, S2 = FFD*DD, S3 = DD*FFD;
    const int SEG = S1 + S2 + S3;
    const int total = LL*SEG;
    for (int idx = blockIdx.x*blockDim.x + threadIdx.x; idx < total; idx += gridDim.x*blockDim.x) {
        int l = idx / SEG, r = idx % SEG;
        if (r < S1)         g_WoH[(size_t)l*S1 + r]      = __float2half_rn(Wo[(size_t)l*S1 + r]);
        else if (r < S1+S2) g_W1H[(size_t)l*S2 + r-S1]   = __float2half_rn(W1[(size_t)l*S2 + r-S1]);
        else                g_W2H[(size_t)l*S3 + r-S1-S2]= __float2half_rn(W2[(size_t)l*S3 + r-S1-S2]);
    }
}

// ---------------- helpers ----------------
__device__ __forceinline__ unsigned smem_addr(const void* p) {
    return (unsigned)__cvta_generic_to_shared(p);
}
__device__ __forceinline__ void ldsm_x4(unsigned r[4], unsigned addr) {
    asm volatile("ldmatrix.sync.aligned.m8n8.x4.shared.b16 {%0,%1,%2,%3}, [%4];"
                 : "=r"(r[0]), "=r"(r[1]), "=r"(r[2]), "=r"(r[3]) : "r"(addr));
}
__device__ __forceinline__ void mma_f16(float c[4], const unsigned a[4], const unsigned b[2]) {
    asm volatile("mma.sync.aligned.m16n8k16.row.col.f32.f16.f16.f32 "
                 "{%0,%1,%2,%3}, {%4,%5,%6,%7}, {%8,%9}, {%0,%1,%2,%3};"
                 : "+f"(c[0]), "+f"(c[1]), "+f"(c[2]), "+f"(c[3])
                 : "r"(a[0]), "r"(a[1]), "r"(a[2]), "r"(a[3]), "r"(b[0]), "r"(b[1]));
}
__device__ __forceinline__ void cpa16(unsigned dst, const void* src, bool pred) {
    int sz = pred ? 16 : 0;
    asm volatile("cp.async.cg.shared.global [%0], [%1], 16, %2;"
                 :: "r"(dst), "l"(src), "r"(sz) : "memory");
}
#define CP_COMMIT() asm volatile("cp.async.commit_group;" ::: "memory")
#define CP_WAIT1()  asm volatile("cp.async.wait_group 1;" ::: "memory")
#define CP_WAIT0()  asm volatile("cp.async.wait_group 0;" ::: "memory")

// fp16 pack hi/lo
__device__ __forceinline__ void split2h(float a, float b, unsigned &h, unsigned &l) {
    __half2 hh = __floats2half2_rn(a, b);
    h = *(unsigned*)&hh;
    float ra = a - __half2float(__low2half(hh));
    float rb = b - __half2float(__high2half(hh));
    __half2 ll = __floats2half2_rn(ra, rb);
    l = *(unsigned*)&ll;
}

// ---------------- fp16 1-term GEMM: BM=128, BN=128, BK=32, 256 thr, 2-stage ----------
#define LDSMP 40
#define GARRB (128*LDSMP*2)          // 10240 bytes per operand array
#define GSTG (2*GARRB)               // Ah, Wh
#define GSMEM (2*GSTG)               // 40960

template<bool DO_GELU, bool HALF_OUT>
__global__ void __launch_bounds__(256) gemm_kernel(int M, int N, int K,
    const __half* __restrict__ Ah, const __half* __restrict__ Wh,
    const float* __restrict__ bias, float* __restrict__ C,
    __half* __restrict__ Ch)
{
    extern __shared__ __half dsm[];
    const int tid  = threadIdx.x;
    const int lane = tid & 31;
    const int warp = tid >> 5;
    const int wm   = warp >> 2;
    const int wn   = warp & 3;
    const int m0   = blockIdx.x * 128;
    const int n0   = blockIdx.y * 128;

    float c[4][4][4];
    #pragma unroll
    for (int i = 0; i < 4; i++)
        #pragma unroll
        for (int j = 0; j < 4; j++)
            #pragma unroll
            for (int r = 0; r < 4; r++) c[i][j][r] = 0.f;

    const int lr = tid >> 2;
    const int lc = (tid & 3) * 8;

    const int aRow    = wm*64 + (lane & 7) + ((lane >> 3) & 1) * 8;
    const int aColSel = (lane >> 4) * 8;
    const int bRow    = wn*32 + (lane & 7) + ((lane >> 4) & 1) * 8;
    const int bColSel = ((lane >> 3) & 1) * 8;

    const unsigned sbase = smem_addr(dsm);

    auto load_tile = [&](int kt, int stage) {
        const int kc = kt * 32;
        const unsigned sb = sbase + stage*GSTG;
        #pragma unroll
        for (int half = 0; half < 2; half++) {
            int r  = lr + half*64;
            int gm = m0 + r;
            bool pa = gm < M;
            int gmc = pa ? gm : 0;
            unsigned drow = (unsigned)((r*LDSMP + lc) * 2);
            cpa16(sb + drow,         Ah + (size_t)gmc*K + kc + lc, pa);
            cpa16(sb + GARRB + drow, Wh + (size_t)(n0 + r)*K + kc + lc, true);
        }
    };

    const int nk = K >> 5;
    load_tile(0, 0);
    CP_COMMIT();

    for (int kt = 0; kt < nk; kt++) {
        const int cur = kt & 1;
        if (kt + 1 < nk) load_tile(kt + 1, cur ^ 1);
        CP_COMMIT();
        CP_WAIT1();
        __syncthreads();

        const unsigned sb    = sbase + cur*GSTG;
        const unsigned sAh_b = sb;
        const unsigned sWh_b = sb + GARRB;

        #pragma unroll
        for (int kk = 0; kk < 2; kk++) {
            unsigned ah[4][4], bh[4][2];
            #pragma unroll
            for (int mt = 0; mt < 4; mt++) {
                unsigned off = (unsigned)(((aRow + mt*16)*LDSMP + kk*16 + aColSel) * 2);
                ldsm_x4(ah[mt], sAh_b + off);
            }
            #pragma unroll
            for (int np = 0; np < 2; np++) {
                unsigned off = (unsigned)(((bRow + np*16)*LDSMP + kk*16 + bColSel) * 2);
                unsigned t[4];
                ldsm_x4(t, sWh_b + off);
                bh[2*np][0]=t[0]; bh[2*np][1]=t[1]; bh[2*np+1][0]=t[2]; bh[2*np+1][1]=t[3];
            }
            #pragma unroll
            for (int mt = 0; mt < 4; mt++)
                #pragma unroll
                for (int nt = 0; nt < 4; nt++)
                    mma_f16(c[mt][nt], ah[mt], bh[nt]);
        }
        __syncthreads();
    }

    #pragma unroll
    for (int mt = 0; mt < 4; mt++) {
        #pragma unroll
        for (int nt = 0; nt < 4; nt++) {
            int col  = n0 + wn*32 + nt*8 + (lane & 3)*2;
            float b0 = bias[col], b1 = bias[col+1];
            int row0 = m0 + wm*64 + mt*16 + (lane >> 2);
            int row1 = row0 + 8;
            float v0 = c[mt][nt][0] + b0, v1 = c[mt][nt][1] + b1;
            float v2 = c[mt][nt][2] + b0, v3 = c[mt][nt][3] + b1;
            if (DO_GELU) {
                v0 = 0.5f*v0*(1.0f+erff(v0*0.7071067811865475f));
                v1 = 0.5f*v1*(1.0f+erff(v1*0.7071067811865475f));
                v2 = 0.5f*v2*(1.0f+erff(v2*0.7071067811865475f));
                v3 = 0.5f*v3*(1.0f+erff(v3*0.7071067811865475f));
            }
            if (HALF_OUT) {
                __half2 h01 = __floats2half2_rn(v0, v1);
                __half2 h23 = __floats2half2_rn(v2, v3);
                if (row0 < M) *(__half2*)&Ch[(size_t)row0*N + col] = h01;
                if (row1 < M) *(__half2*)&Ch[(size_t)row1*N + col] = h23;
            } else {
                if (row0 < M) *(float2*)&C[(size_t)row0*N + col] = make_float2(v0, v1);
                if (row1 < M) *(float2*)&C[(size_t)row1*N + col] = make_float2(v2, v3);
            }
        }
    }
}

// ---------------- rope + split + relayout (fp16: Qh/Ql, Kh, Vh) ----------------
__global__ void __launch_bounds__(256) rope_split_kernel()
{
    int t = blockIdx.x*blockDim.x + threadIdx.x;
    if (t >= 64*SS) return;
    int s  = t % SS;
    int bh = t / SS;
    int b = bh >> 3, h = bh & 7;

    const float* src = g_QKV + ((size_t)(b*SS + s))*QKVN + h*DH;
    float q[48], k[48], v[48];
    #pragma unroll
    for (int i = 0; i < 12; i++) {
        *(float4*)&q[i*4] = *(const float4*)(src + i*4);
        *(float4*)&k[i*4] = *(const float4*)(src + DD + i*4);
        *(float4*)&v[i*4] = *(const float4*)(src + 2*DD + i*4);
    }

    float invf[8];
    #pragma unroll
    for (int j = 0; j < 8; j++)
        invf[j] = exp2f(-1.6609640474436813f * (float)j);

    #pragma unroll
    for (int a = 0; a < 3; a++) {
        float co = g_COORD[(b*SS + s)*3 + a];
        #pragma unroll
        for (int j = 0; j < 8; j++) {
            float ang = co * invf[j];
            float cs = cosf(ang), sn = sinf(ang);
            int i1 = a*16 + j, i2 = i1 + 8;
            float q1 = q[i1], q2 = q[i2];
            q[i1] = q1*cs - q2*sn;  q[i2] = q1*sn + q2*cs;
            float k1 = k[i1], k2 = k[i2];
            k[i1] = k1*cs - k2*sn;  k[i2] = k1*sn + k2*cs;
        }
    }

    const float scale = 0.14433756729740643f;
    size_t qkbase = ((size_t)bh*SPAD + s)*DH;
    #pragma unroll
    for (int d = 0; d < 48; d++) {
        float qq = q[d]*scale;
        __half hh = __float2half_rn(qq);
        g_QH[qkbase + d] = hh;
        g_QL[qkbase + d] = __float2half_rn(qq - __half2float(hh));
        g_KH[qkbase + d] = __float2half_rn(k[d]);
        g_VH[((size_t)bh*DH + d)*SPAD + s] = __float2half_rn(v[d]);
    }
}

// ---------------- tensor-core flash attention (fp16 2-term, 64-row tiles) ----------------
#define QKP 56
#define VTP 72

__global__ void __launch_bounds__(128) attn_mma_kernel(__half* __restrict__ AH)
{
    const int bh = blockIdx.y;
    const int b = bh >> 3, h = bh & 7;
    const int q0 = blockIdx.x * 64;
    const int tid = threadIdx.x;
    const int lane = tid & 31;
    const int warp = tid >> 5;

    __shared__ __half sQh[64*QKP], sQl[64*QKP];
    __shared__ __half sKh[64*QKP];
    __shared__ __half sVh[48*VTP];

    const unsigned sQh_b = smem_addr(sQh), sQl_b = smem_addr(sQl);
    const unsigned sKh_b = smem_addr(sKh);
    const unsigned sVh_b = smem_addr(sVh);

    const size_t qkBase = (size_t)bh*SPAD*DH;
    const size_t vBase  = (size_t)bh*DH*SPAD;

    #pragma unroll
    for (int i = 0; i < 3; i++) {
        int cidx = tid + i*128;
        int row = cidx / 6, off = (cidx % 6) * 8;
        unsigned d = (unsigned)((row*QKP + off) * 2);
        const size_t g = qkBase + (size_t)(q0 + row)*DH + off;
        cpa16(sQh_b + d, g_QH + g, true);
        cpa16(sQl_b + d, g_QL + g, true);
    }
    CP_COMMIT(); CP_WAIT0();
    __syncthreads();

    const int aRow = 16*warp + (lane & 7) + ((lane >> 3) & 1) * 8;
    const int aColSel = (lane >> 4) * 8;
    unsigned qh[3][4], ql[3][4];
    #pragma unroll
    for (int kk = 0; kk < 3; kk++) {
        unsigned off = (unsigned)((aRow*QKP + kk*16 + aColSel) * 2);
        ldsm_x4(qh[kk], sQh_b + off);
        ldsm_x4(ql[kk], sQl_b + off);
    }

    float o[6][4];
    #pragma unroll
    for (int i = 0; i < 6; i++)
        #pragma unroll
        for (int j = 0; j < 4; j++) o[i][j] = 0.f;
    float m0r = -1e30f, m1r = -1e30f, l0 = 0.f, l1 = 0.f;

    const int row0 = q0 + 16*warp + (lane >> 2);
    const int row1 = row0 + 8;
    const bool rm0 = row0 < NM1, rm1 = row1 < NM1;

    const int bRowSel = (lane & 7) + ((lane >> 4) & 1) * 8;
    const int bColSel = ((lane >> 3) & 1) * 8;

    for (int kt = 0; kt < 17; kt++) {
        int k0 = kt * 64;
        if ((q0 + 63 < NM1) && (k0 >= NM1)) continue;

        __syncthreads();
        #pragma unroll
        for (int i = 0; i < 3; i++) {
            int cidx = tid + i*128;
            int row = cidx / 6, off = (cidx % 6) * 8;
            unsigned d = (unsigned)((row*QKP + off) * 2);
            cpa16(sKh_b + d, g_KH + qkBase + (size_t)(k0 + row)*DH + off, true);
        }
        #pragma unroll
        for (int i = 0; i < 3; i++) {
            int cidx = tid + i*128;
            int row = cidx / 8, off = (cidx % 8) * 8;
            unsigned d = (unsigned)((row*VTP + off) * 2);
            cpa16(sVh_b + d, g_VH + vBase + (size_t)row*SPAD + k0 + off, true);
        }
        CP_COMMIT(); CP_WAIT0();
        __syncthreads();

        float s[8][4];
        #pragma unroll
        for (int i = 0; i < 8; i++)
            #pragma unroll
            for (int j = 0; j < 4; j++) s[i][j] = 0.f;

        #pragma unroll
        for (int kk = 0; kk < 3; kk++) {
            unsigned bhf[8][2];
            #pragma unroll
            for (int nb = 0; nb < 4; nb++) {
                unsigned off = (unsigned)(((nb*16 + bRowSel)*QKP + kk*16 + bColSel) * 2);
                unsigned t[4];
                ldsm_x4(t, sKh_b + off);
                bhf[2*nb][0]=t[0]; bhf[2*nb][1]=t[1]; bhf[2*nb+1][0]=t[2]; bhf[2*nb+1][1]=t[3];
            }
            #pragma unroll
            for (int nt = 0; nt < 8; nt++) {
                mma_f16(s[nt], qh[kk], bhf[nt]);
                mma_f16(s[nt], ql[kk], bhf[nt]);
            }
        }

        #pragma unroll
        for (int nt = 0; nt < 8; nt++) {
            #pragma unroll
            for (int e = 0; e < 2; e++) {
                int col = k0 + nt*8 + (lane & 3)*2 + e;
                bool cmm = (col >= SS);
                bool cnm = (col >= NM1);
                if (cmm || (rm0 && cnm)) s[nt][e]   = -1e30f;
                if (cmm || (rm1 && cnm)) s[nt][2+e] = -1e30f;
            }
        }

        float t0 = -1e30f, t1 = -1e30f;
        #pragma unroll
        for (int nt = 0; nt < 8; nt++) {
            t0 = fmaxf(t0, fmaxf(s[nt][0], s[nt][1]));
            t1 = fmaxf(t1, fmaxf(s[nt][2], s[nt][3]));
        }
        t0 = fmaxf(t0, __shfl_xor_sync(0xffffffffu, t0, 1));
        t0 = fmaxf(t0, __shfl_xor_sync(0xffffffffu, t0, 2));
        t1 = fmaxf(t1, __shfl_xor_sync(0xffffffffu, t1, 1));
        t1 = fmaxf(t1, __shfl_xor_sync(0xffffffffu, t1, 2));
        float nm0 = fmaxf(m0r, t0), nm1 = fmaxf(m1r, t1);
        float f0 = __expf(m0r - nm0), f1 = __expf(m1r - nm1);
        m0r = nm0; m1r = nm1;

        float ps0 = 0.f, ps1 = 0.f;
        #pragma unroll
        for (int nt = 0; nt < 8; nt++) {
            s[nt][0] = __expf(s[nt][0] - m0r);
            s[nt][1] = __expf(s[nt][1] - m0r);
            s[nt][2] = __expf(s[nt][2] - m1r);
            s[nt][3] = __expf(s[nt][3] - m1r);
            ps0 += s[nt][0] + s[nt][1];
            ps1 += s[nt][2] + s[nt][3];
        }
        ps0 += __shfl_xor_sync(0xffffffffu, ps0, 1);
        ps0 += __shfl_xor_sync(0xffffffffu, ps0, 2);
        ps1 += __shfl_xor_sync(0xffffffffu, ps1, 1);
        ps1 += __shfl_xor_sync(0xffffffffu, ps1, 2);
        l0 = l0*f0 + ps0;
        l1 = l1*f1 + ps1;
        #pragma unroll
        for (int nt = 0; nt < 6; nt++) {
            o[nt][0] *= f0; o[nt][1] *= f0;
            o[nt][2] *= f1; o[nt][3] *= f1;
        }

        #pragma unroll
        for (int kk = 0; kk < 4; kk++) {
            unsigned pah[4], pal[4];
            split2h(s[2*kk  ][0], s[2*kk  ][1], pah[0], pal[0]);
            split2h(s[2*kk  ][2], s[2*kk  ][3], pah[1], pal[1]);
            split2h(s[2*kk+1][0], s[2*kk+1][1], pah[2], pal[2]);
            split2h(s[2*kk+1][2], s[2*kk+1][3], pah[3], pal[3]);

            unsigned vbh[6][2];
            #pragma unroll
            for (int nb = 0; nb < 3; nb++) {
                unsigned off = (unsigned)(((nb*16 + bRowSel)*VTP + kk*16 + bColSel) * 2);
                unsigned t[4];
                ldsm_x4(t, sVh_b + off);
                vbh[2*nb][0]=t[0]; vbh[2*nb][1]=t[1]; vbh[2*nb+1][0]=t[2]; vbh[2*nb+1][1]=t[3];
            }
            #pragma unroll
            for (int nt = 0; nt < 6; nt++) {
                mma_f16(o[nt], pah, vbh[nt]);
                mma_f16(o[nt], pal, vbh[nt]);
            }
        }
    }

    float il0 = 1.f / l0, il1 = 1.f / l1;
    #pragma unroll
    for (int nt = 0; nt < 6; nt++) {
        int col = h*DH + nt*8 + (lane & 3)*2;
        if (row0 < SS) {
            __half2 hh = __floats2half2_rn(o[nt][0]*il0, o[nt][1]*il0);
            *(__half2*)&AH[(size_t)(b*SS + row0)*DD + col] = hh;
        }
        if (row1 < SS) {
            __half2 hh = __floats2half2_rn(o[nt][2]*il1, o[nt][3]*il1);
            *(__half2*)&AH[(size_t)(b*SS + row1)*DD + col] = hh;
        }
    }
}

// ---------------- residual add + layernorm (fp32 + fp16 hi) ----------------
__global__ void __launch_bounds__(128) add_ln_kernel(float* __restrict__ src, const float* __restrict__ res,
                                                     const float* __restrict__ g, const float* __restrict__ bta,
                                                     __half* __restrict__ XH)
{
    int row = blockIdx.x;
    int tid = threadIdx.x;
    float x[3];
    float s = 0.f, sq = 0.f;
    #pragma unroll
    for (int i = 0; i < 3; i++) {
        int d = tid + i*128;
        float v = src[(size_t)row*DD + d] + res[(size_t)row*DD + d];
        x[i] = v; s += v; sq += v*v;
    }
    #pragma unroll
    for (int o = 16; o > 0; o >>= 1) {
        s  += __shfl_xor_sync(0xffffffffu, s,  o);
        sq += __shfl_xor_sync(0xffffffffu, sq, o);
    }
    __shared__ float ss[4], ssq[4];
    int w = tid >> 5;
    if ((tid & 31) == 0) { ss[w] = s; ssq[w] = sq; }
    __syncthreads();
    s  = ss[0]+ss[1]+ss[2]+ss[3];
    sq = ssq[0]+ssq[1]+ssq[2]+ssq[3];
    float mean = s * (1.f/384.f);
    float var  = sq * (1.f/384.f) - mean*mean;
    float rs = rsqrtf(var + 1e-5f);
    #pragma unroll
    for (int i = 0; i < 3; i++) {
        int d = tid + i*128;
        float y = (x[i]-mean)*rs*g[d] + bta[d];
        src[(size_t)row*DD + d] = y;
        XH[(size_t)row*DD + d] = __float2half_rn(y);
    }
}

__global__ void copy_out_kernel(float* __restrict__ out)
{
    int idx = blockIdx.x*blockDim.x + threadIdx.x;
    if (idx >= BB*TT*DD) return;
    int d = idx % DD;
    int t = (idx/DD) % TT;
    int b = idx / (DD*TT);
    out[idx] = g_SRC[((size_t)(b*SS + (SS-TT) + t))*DD + d];
}

// ---------------- host launcher ----------------
extern "C" void kernel_launch(void* const* d_in, const int* in_sizes, int n_in,
                              void* d_out, int out_size)
{
    (void)in_sizes; (void)n_in; (void)out_size;
    const float* hand_t    = (const float*)d_in[0];
    const float* head_t    = (const float*)d_in[1];
    const float* hand_m1   = (const float*)d_in[2];
    const float* head_m1   = (const float*)d_in[3];
    const float* c_hand_t  = (const float*)d_in[4];
    const float* c_head_t  = (const float*)d_in[5];
    const float* c_hand_m1 = (const float*)d_in[6];
    const float* c_head_m1 = (const float*)d_in[7];
    const float* state_t   = (const float*)d_in[8];
    const float* state_m1  = (const float*)d_in[9];
    const float* tr_t      = (const float*)d_in[10];
    const float* tr_m1     = (const float*)d_in[11];
    const float* tok_m1    = (const float*)d_in[12];
    const float* tok_t     = (const float*)d_in[13];
    const float* Wq  = (const float*)d_in[14];
    const float* bq  = (const float*)d_in[15];
    const float* Wk  = (const float*)d_in[16];
    const float* bk  = (const float*)d_in[17];
    const float* Wv  = (const float*)d_in[18];
    const float* bv  = (const float*)d_in[19];
    const float* Wo  = (const float*)d_in[20];
    const float* bo  = (const float*)d_in[21];
    const float* W1  = (const float*)d_in[22];
    const float* b1  = (const float*)d_in[23];
    const float* W2  = (const float*)d_in[24];
    const float* b2  = (const float*)d_in[25];
    const float* g1  = (const float*)d_in[26];
    const float* be1 = (const float*)d_in[27];
    const float* g2  = (const float*)d_in[28];
    const float* be2 = (const float*)d_in[29];

    float *SRC, *QKVp, *PROJ, *BQKV;
    __half *XH, *FFH, *WqkvH, *WoH, *W1H, *W2H;
    cudaGetSymbolAddress((void**)&SRC,   g_SRC);
    cudaGetSymbolAddress((void**)&QKVp,  g_QKV);
    cudaGetSymbolAddress((void**)&PROJ,  g_PROJ);
    cudaGetSymbolAddress((void**)&XH,    g_XH);
    cudaGetSymbolAddress((void**)&FFH,   g_FFH);
    cudaGetSymbolAddress((void**)&WqkvH, g_WqkvH);
    cudaGetSymbolAddress((void**)&WoH,   g_WoH);
    cudaGetSymbolAddress((void**)&W1H,   g_W1H);
    cudaGetSymbolAddress((void**)&W2H,   g_W2H);
    cudaGetSymbolAddress((void**)&BQKV,  g_bqkv);

    cudaFuncSetAttribute(gemm_kernel<false,false>, cudaFuncAttributeMaxDynamicSharedMemorySize, GSMEM);
    cudaFuncSetAttribute(gemm_kernel<true,true>,   cudaFuncAttributeMaxDynamicSharedMemorySize, GSMEM);

    build_src_kernel<<<1024, 256>>>(hand_t, head_t, hand_m1, head_m1,
                                    state_t, state_m1, tok_m1, tok_t);
    build_coord_kernel<<<98, 256>>>(c_hand_t, c_head_t, c_hand_m1, c_head_m1, tr_t, tr_m1);
    split_qkv_w_kernel<<<2048, 256>>>(Wq, Wk, Wv, bq, bk, bv);
    split_weights_kernel<<<4096, 256>>>(Wo, W1, W2);
    split_kernel<<<2048, 256>>>(SRC, XH, MM*DD);

    const int MB = (MM + 127)/128;   // 65
    for (int l = 0; l < LL; l++) {
        gemm_kernel<false,false><<<dim3(MB, QKVN/128), 256, GSMEM>>>(MM, QKVN, DD, XH,
            WqkvH + (size_t)l*QKVN*DD, BQKV + l*QKVN, QKVp, nullptr);
        rope_split_kernel<<<(64*SS + 255)/256, 256>>>();
        attn_mma_kernel<<<dim3(17, 64), 128>>>(XH);
        gemm_kernel<false,false><<<dim3(MB, DD/128), 256, GSMEM>>>(MM, DD, DD, XH,
            WoH + (size_t)l*DD*DD, bo + l*DD, PROJ, nullptr);
        add_ln_kernel<<<MM, 128>>>(SRC, PROJ, g1 + l*DD, be1 + l*DD, XH);
        gemm_kernel<true,true><<<dim3(MB, FFD/128), 256, GSMEM>>>(MM, FFD, DD, XH,
            W1H + (size_t)l*FFD*DD, b1 + l*FFD, nullptr, FFH);
        gemm_kernel<false,false><<<dim3(MB, DD/128), 256, GSMEM>>>(MM, DD, FFD, FFH,
            W2H + (size_t)l*DD*FFD, b2 + l*DD, PROJ, nullptr);
        add_ln_kernel<<<MM, 128>>>(SRC, PROJ, g2 + l*DD, be2 + l*DD, XH);
    }
    copy_out_kernel<<<48, 256>>>((float*)d_out);
}

// round 10
// speedup vs baseline: 2.6981x; 1.5037x over previous
#include <cuda_runtime.h>
#include <cuda_fp16.h>
#include <math.h>

#define BB 8
#define NN 256
#define DD 384
#define LL 6
#define HH 8
#define FFD 1536
#define TT 4
#define DH 48
#define NM1 517
#define SS 1034
#define SPAD 1152
#define MM (BB*SS)
#define QKVN 1152

// ---------------- scratch ----------------
__device__ float g_SRC [MM*DD];
__device__ float g_COORD[MM*3];
__device__ float g_PROJ[MM*DD];

__device__ __half g_XH[MM*DD];
__device__ __half g_FFH[MM*FFD];

__device__ __half g_QH[64*SPAD*DH];
__device__ __half g_KH[64*SPAD*DH];
__device__ __half g_VH[64*DH*SPAD];

__device__ __half g_WqkvH[LL*QKVN*DD];
__device__ __half g_WoH[LL*DD*DD];
__device__ __half g_W1H[LL*FFD*DD];
__device__ __half g_W2H[LL*DD*FFD];
__device__ float g_bqkv[LL*QKVN];

// ---------------- input assembly ----------------
__global__ void build_src_kernel(const float* __restrict__ hand_t, const float* __restrict__ head_t,
                                 const float* __restrict__ hand_m1, const float* __restrict__ head_m1,
                                 const float* __restrict__ state_t, const float* __restrict__ state_m1,
                                 const float* __restrict__ tok_m1, const float* __restrict__ tok_t)
{
    for (int idx = blockIdx.x*blockDim.x + threadIdx.x; idx < BB*SS*DD; idx += gridDim.x*blockDim.x) {
        int d = idx % DD;
        int s = (idx / DD) % SS;
        int b = idx / (DD*SS);
        float v;
        if      (s == 0)    v = state_m1[b*DD + d];
        else if (s < 257)   v = hand_m1[((b*NN)+(s-1  ))*DD + d];
        else if (s < 513)   v = head_m1[((b*NN)+(s-257))*DD + d];
        else if (s < 517)   v = tok_m1[(s-513)*DD + d];
        else if (s == 517)  v = state_t[b*DD + d];
        else if (s < 774)   v = hand_t[((b*NN)+(s-518))*DD + d];
        else if (s < 1030)  v = head_t[((b*NN)+(s-774))*DD + d];
        else                v = tok_t[(s-1030)*DD + d];
        g_SRC[idx] = v;
    }
}

__global__ void build_coord_kernel(const float* __restrict__ c_hand_t, const float* __restrict__ c_head_t,
                                   const float* __restrict__ c_hand_m1, const float* __restrict__ c_head_m1,
                                   const float* __restrict__ tr_t, const float* __restrict__ tr_m1)
{
    for (int idx = blockIdx.x*blockDim.x + threadIdx.x; idx < BB*SS*3; idx += gridDim.x*blockDim.x) {
        int cdim = idx % 3;
        int s = (idx/3) % SS;
        int b = idx / (3*SS);
        float v;
        if      (s == 0)    v = tr_m1[b*3+cdim];
        else if (s < 257)   v = c_hand_m1[((b*NN)+(s-1  ))*3 + cdim];
        else if (s < 513)   v = c_head_m1[((b*NN)+(s-257))*3 + cdim];
        else if (s < 517)   v = tr_m1[b*3+cdim];
        else if (s == 517)  v = tr_t[b*3+cdim];
        else if (s < 774)   v = c_hand_t[((b*NN)+(s-518))*3 + cdim];
        else if (s < 1030)  v = c_head_t[((b*NN)+(s-774))*3 + cdim];
        else                v = tr_t[b*3+cdim];
        g_COORD[idx] = v;
    }
}

// ---------------- fp32 -> fp16 ----------------
__global__ void split_kernel(const float* __restrict__ x, __half* __restrict__ hi, int n)
{
    for (int i = blockIdx.x*blockDim.x + threadIdx.x; i < n; i += gridDim.x*blockDim.x)
        hi[i] = __float2half_rn(x[i]);
}

__global__ void split_qkv_w_kernel(const float* __restrict__ Wq, const float* __restrict__ Wk,
                                   const float* __restrict__ Wv, const float* __restrict__ bq,
                                   const float* __restrict__ bk, const float* __restrict__ bv)
{
    int tid0 = blockIdx.x*blockDim.x + threadIdx.x;
    if (tid0 < LL*QKVN) {
        int r = tid0 % QKVN, l = tid0 / QKVN;
        float v;
        if      (r < DD)   v = bq[l*DD + r];
        else if (r < 2*DD) v = bk[l*DD + r-DD];
        else               v = bv[l*DD + r-2*DD];
        g_bqkv[tid0] = v;
    }
    const int total = LL*QKVN*DD;
    for (int idx = tid0; idx < total; idx += gridDim.x*blockDim.x) {
        int k = idx % DD;
        int r = (idx / DD) % QKVN;
        int l = idx / (DD*QKVN);
        float v;
        if      (r < DD)    v = Wq[((size_t)l*DD + r      )*DD + k];
        else if (r < 2*DD)  v = Wk[((size_t)l*DD + r-DD   )*DD + k];
        else                v = Wv[((size_t)l*DD + r-2*DD )*DD + k];
        g_WqkvH[idx] = __float2half_rn(v);
    }
}

__global__ void split_weights_kernel(const float* __restrict__ Wo, const float* __restrict__ W1,
                                     const float* __restrict__ W2)
{
    const int S1 = DD*DD, S2 = FFD*DD, S3 = DD*FFD;
    const int SEG = S1 + S2 + S3;
    const int total = LL*SEG;
    for (int idx = blockIdx.x*blockDim.x + threadIdx.x; idx < total; idx += gridDim.x*blockDim.x) {
        int l = idx / SEG, r = idx % SEG;
        if (r < S1)         g_WoH[(size_t)l*S1 + r]      = __float2half_rn(Wo[(size_t)l*S1 + r]);
        else if (r < S1+S2) g_W1H[(size_t)l*S2 + r-S1]   = __float2half_rn(W1[(size_t)l*S2 + r-S1]);
        else                g_W2H[(size_t)l*S3 + r-S1-S2]= __float2half_rn(W2[(size_t)l*S3 + r-S1-S2]);
    }
}

// ---------------- helpers ----------------
__device__ __forceinline__ unsigned smem_addr(const void* p) {
    return (unsigned)__cvta_generic_to_shared(p);
}
__device__ __forceinline__ void ldsm_x4(unsigned r[4], unsigned addr) {
    asm volatile("ldmatrix.sync.aligned.m8n8.x4.shared.b16 {%0,%1,%2,%3}, [%4];"
                 : "=r"(r[0]), "=r"(r[1]), "=r"(r[2]), "=r"(r[3]) : "r"(addr));
}
__device__ __forceinline__ void mma_f16(float c[4], const unsigned a[4], const unsigned b[2]) {
    asm volatile("mma.sync.aligned.m16n8k16.row.col.f32.f16.f16.f32 "
                 "{%0,%1,%2,%3}, {%4,%5,%6,%7}, {%8,%9}, {%0,%1,%2,%3};"
                 : "+f"(c[0]), "+f"(c[1]), "+f"(c[2]), "+f"(c[3])
                 : "r"(a[0]), "r"(a[1]), "r"(a[2]), "r"(a[3]), "r"(b[0]), "r"(b[1]));
}
__device__ __forceinline__ void cpa16(unsigned dst, const void* src, bool pred) {
    int sz = pred ? 16 : 0;
    asm volatile("cp.async.cg.shared.global [%0], [%1], 16, %2;"
                 :: "r"(dst), "l"(src), "r"(sz) : "memory");
}
#define CP_COMMIT() asm volatile("cp.async.commit_group;" ::: "memory")
#define CP_WAIT1()  asm volatile("cp.async.wait_group 1;" ::: "memory")
#define CP_WAIT0()  asm volatile("cp.async.wait_group 0;" ::: "memory")

// ---------------- fp16 1-term GEMM, optional fused rope+relayout epilogue ----------
#define LDSMP 40
#define GARRB (128*LDSMP*2)
#define GSTG (2*GARRB)
#define GSMEM (2*GSTG)               // 40960

template<bool DO_GELU, bool HALF_OUT, bool ROPE>
__global__ void __launch_bounds__(256) gemm_kernel(int M, int N, int K,
    const __half* __restrict__ Ah, const __half* __restrict__ Wh,
    const float* __restrict__ bias, float* __restrict__ C,
    __half* __restrict__ Ch)
{
    extern __shared__ __half dsm[];
    const int tid  = threadIdx.x;
    const int lane = tid & 31;
    const int warp = tid >> 5;
    const int wm   = warp >> 2;
    const int wn   = warp & 3;
    const int m0   = blockIdx.x * 128;
    const int n0   = blockIdx.y * 128;

    float c[4][4][4];
    #pragma unroll
    for (int i = 0; i < 4; i++)
        #pragma unroll
        for (int j = 0; j < 4; j++)
            #pragma unroll
            for (int r = 0; r < 4; r++) c[i][j][r] = 0.f;

    const int lr = tid >> 2;
    const int lc = (tid & 3) * 8;

    const int aRow    = wm*64 + (lane & 7) + ((lane >> 3) & 1) * 8;
    const int aColSel = (lane >> 4) * 8;
    const int bRow    = wn*32 + (lane & 7) + ((lane >> 4) & 1) * 8;
    const int bColSel = ((lane >> 3) & 1) * 8;

    const unsigned sbase = smem_addr(dsm);

    auto load_tile = [&](int kt, int stage) {
        const int kc = kt * 32;
        const unsigned sb = sbase + stage*GSTG;
        #pragma unroll
        for (int half = 0; half < 2; half++) {
            int r  = lr + half*64;
            int gm = m0 + r;
            bool pa = gm < M;
            int gmc = pa ? gm : 0;
            unsigned drow = (unsigned)((r*LDSMP + lc) * 2);
            cpa16(sb + drow,         Ah + (size_t)gmc*K + kc + lc, pa);
            cpa16(sb + GARRB + drow, Wh + (size_t)(n0 + r)*K + kc + lc, true);
        }
    };

    const int nk = K >> 5;
    load_tile(0, 0);
    CP_COMMIT();

    for (int kt = 0; kt < nk; kt++) {
        const int cur = kt & 1;
        if (kt + 1 < nk) load_tile(kt + 1, cur ^ 1);
        CP_COMMIT();
        CP_WAIT1();
        __syncthreads();

        const unsigned sb    = sbase + cur*GSTG;
        const unsigned sAh_b = sb;
        const unsigned sWh_b = sb + GARRB;

        #pragma unroll
        for (int kk = 0; kk < 2; kk++) {
            unsigned ah[4][4], bh[4][2];
            #pragma unroll
            for (int mt = 0; mt < 4; mt++) {
                unsigned off = (unsigned)(((aRow + mt*16)*LDSMP + kk*16 + aColSel) * 2);
                ldsm_x4(ah[mt], sAh_b + off);
            }
            #pragma unroll
            for (int np = 0; np < 2; np++) {
                unsigned off = (unsigned)(((bRow + np*16)*LDSMP + kk*16 + bColSel) * 2);
                unsigned t[4];
                ldsm_x4(t, sWh_b + off);
                bh[2*np][0]=t[0]; bh[2*np][1]=t[1]; bh[2*np+1][0]=t[2]; bh[2*np+1][1]=t[3];
            }
            #pragma unroll
            for (int mt = 0; mt < 4; mt++)
                #pragma unroll
                for (int nt = 0; nt < 4; nt++)
                    mma_f16(c[mt][nt], ah[mt], bh[nt]);
        }
        __syncthreads();
    }

    if (ROPE) {
        // fused bias + rotary + relayout into QH/KH/VH
        const float scale = 0.14433756729740643f;   // 1/sqrt(48)
        const int j = (lane & 3) * 2;
        const float fj  = exp2f(-1.6609640474436813f * (float)j);
        const float fj1 = exp2f(-1.6609640474436813f * (float)(j+1));
        const int wcolBase = n0 + wn*32;
        #pragma unroll
        for (int mt = 0; mt < 4; mt++) {
            int row0 = m0 + wm*64 + mt*16 + (lane >> 2);
            int row1 = row0 + 8;
            bool ok0 = row0 < M, ok1 = row1 < M;
            int b0 = row0 / SS, s0 = row0 - b0*SS;
            int b1 = row1 / SS, s1 = row1 - b1*SS;
            #pragma unroll
            for (int p = 0; p < 2; p++) {
                int wcol = wcolBase + p*16;
                int sec  = wcol / DD;            // 0=Q,1=K,2=V
                int hcol = wcol - sec*DD;
                int h    = hcol / DH;
                int dh0  = hcol - h*DH;          // 0,16,32
                float x1a = c[mt][2*p][0] + bias[wcol + j];
                float x1b = c[mt][2*p][1] + bias[wcol + j + 1];
                float x1c = c[mt][2*p][2] + bias[wcol + j];
                float x1d = c[mt][2*p][3] + bias[wcol + j + 1];
                float x2a = c[mt][2*p+1][0] + bias[wcol + 8 + j];
                float x2b = c[mt][2*p+1][1] + bias[wcol + 8 + j + 1];
                float x2c = c[mt][2*p+1][2] + bias[wcol + 8 + j];
                float x2d = c[mt][2*p+1][3] + bias[wcol + 8 + j + 1];
                int bh0 = b0*HH + h, bh1 = b1*HH + h;
                if (sec == 2) {
                    if (ok0) {
                        size_t base = ((size_t)bh0*DH + dh0 + j)*SPAD + s0;
                        g_VH[base          ] = __float2half_rn(x1a);
                        g_VH[base +   SPAD ] = __float2half_rn(x1b);
                        g_VH[base + 8*SPAD ] = __float2half_rn(x2a);
                        g_VH[base + 9*SPAD ] = __float2half_rn(x2b);
                    }
                    if (ok1) {
                        size_t base = ((size_t)bh1*DH + dh0 + j)*SPAD + s1;
                        g_VH[base          ] = __float2half_rn(x1c);
                        g_VH[base +   SPAD ] = __float2half_rn(x1d);
                        g_VH[base + 8*SPAD ] = __float2half_rn(x2c);
                        g_VH[base + 9*SPAD ] = __float2half_rn(x2d);
                    }
                } else {
                    int a = dh0 >> 4;
                    float co0 = g_COORD[row0*3 + a];
                    float co1 = g_COORD[row1*3 + a];
                    float c00, s00, c01, s01, c10, s10, c11, s11;
                    __sincosf(co0*fj,  &s00, &c00);
                    __sincosf(co0*fj1, &s01, &c01);
                    __sincosf(co1*fj,  &s10, &c10);
                    __sincosf(co1*fj1, &s11, &c11);
                    float y1a = x1a*c00 - x2a*s00, y2a = x1a*s00 + x2a*c00;
                    float y1b = x1b*c01 - x2b*s01, y2b = x1b*s01 + x2b*c01;
                    float y1c = x1c*c10 - x2c*s10, y2c = x1c*s10 + x2c*c10;
                    float y1d = x1d*c11 - x2d*s11, y2d = x1d*s11 + x2d*c11;
                    __half* dst = (sec == 0) ? g_QH : g_KH;
                    float sc = (sec == 0) ? scale : 1.f;
                    if (ok0) {
                        size_t base = ((size_t)bh0*SPAD + s0)*DH + dh0;
                        *(__half2*)&dst[base + j]     = __floats2half2_rn(y1a*sc, y1b*sc);
                        *(__half2*)&dst[base + j + 8] = __floats2half2_rn(y2a*sc, y2b*sc);
                    }
                    if (ok1) {
                        size_t base = ((size_t)bh1*SPAD + s1)*DH + dh0;
                        *(__half2*)&dst[base + j]     = __floats2half2_rn(y1c*sc, y1d*sc);
                        *(__half2*)&dst[base + j + 8] = __floats2half2_rn(y2c*sc, y2d*sc);
                    }
                }
            }
        }
        return;
    }

    #pragma unroll
    for (int mt = 0; mt < 4; mt++) {
        #pragma unroll
        for (int nt = 0; nt < 4; nt++) {
            int col  = n0 + wn*32 + nt*8 + (lane & 3)*2;
            float b0 = bias[col], b1 = bias[col+1];
            int row0 = m0 + wm*64 + mt*16 + (lane >> 2);
            int row1 = row0 + 8;
            float v0 = c[mt][nt][0] + b0, v1 = c[mt][nt][1] + b1;
            float v2 = c[mt][nt][2] + b0, v3 = c[mt][nt][3] + b1;
            if (DO_GELU) {
                v0 = 0.5f*v0*(1.0f+erff(v0*0.7071067811865475f));
                v1 = 0.5f*v1*(1.0f+erff(v1*0.7071067811865475f));
                v2 = 0.5f*v2*(1.0f+erff(v2*0.7071067811865475f));
                v3 = 0.5f*v3*(1.0f+erff(v3*0.7071067811865475f));
            }
            if (HALF_OUT) {
                __half2 h01 = __floats2half2_rn(v0, v1);
                __half2 h23 = __floats2half2_rn(v2, v3);
                if (row0 < M) *(__half2*)&Ch[(size_t)row0*N + col] = h01;
                if (row1 < M) *(__half2*)&Ch[(size_t)row1*N + col] = h23;
            } else {
                if (row0 < M) *(float2*)&C[(size_t)row0*N + col] = make_float2(v0, v1);
                if (row1 < M) *(float2*)&C[(size_t)row1*N + col] = make_float2(v2, v3);
            }
        }
    }
}

// ---------------- tensor-core flash attention (fp16 1-term, 64-row tiles) ----------------
#define QKP 56
#define VTP 72

__global__ void __launch_bounds__(128) attn_mma_kernel(__half* __restrict__ AH)
{
    const int bh = blockIdx.y;
    const int b = bh >> 3, h = bh & 7;
    const int q0 = blockIdx.x * 64;
    const int tid = threadIdx.x;
    const int lane = tid & 31;
    const int warp = tid >> 5;

    __shared__ __half sQh[64*QKP];
    __shared__ __half sKh[64*QKP];
    __shared__ __half sVh[48*VTP];

    const unsigned sQh_b = smem_addr(sQh);
    const unsigned sKh_b = smem_addr(sKh);
    const unsigned sVh_b = smem_addr(sVh);

    const size_t qkBase = (size_t)bh*SPAD*DH;
    const size_t vBase  = (size_t)bh*DH*SPAD;

    #pragma unroll
    for (int i = 0; i < 3; i++) {
        int cidx = tid + i*128;
        int row = cidx / 6, off = (cidx % 6) * 8;
        unsigned d = (unsigned)((row*QKP + off) * 2);
        cpa16(sQh_b + d, g_QH + qkBase + (size_t)(q0 + row)*DH + off, true);
    }
    CP_COMMIT(); CP_WAIT0();
    __syncthreads();

    const int aRow = 16*warp + (lane & 7) + ((lane >> 3) & 1) * 8;
    const int aColSel = (lane >> 4) * 8;
    unsigned qh[3][4];
    #pragma unroll
    for (int kk = 0; kk < 3; kk++) {
        unsigned off = (unsigned)((aRow*QKP + kk*16 + aColSel) * 2);
        ldsm_x4(qh[kk], sQh_b + off);
    }

    float o[6][4];
    #pragma unroll
    for (int i = 0; i < 6; i++)
        #pragma unroll
        for (int j = 0; j < 4; j++) o[i][j] = 0.f;
    float m0r = -1e30f, m1r = -1e30f, l0 = 0.f, l1 = 0.f;

    const int row0 = q0 + 16*warp + (lane >> 2);
    const int row1 = row0 + 8;
    const bool rm0 = row0 < NM1, rm1 = row1 < NM1;

    const int bRowSel = (lane & 7) + ((lane >> 4) & 1) * 8;
    const int bColSel = ((lane >> 3) & 1) * 8;

    for (int kt = 0; kt < 17; kt++) {
        int k0 = kt * 64;
        if ((q0 + 63 < NM1) && (k0 >= NM1)) continue;

        __syncthreads();
        #pragma unroll
        for (int i = 0; i < 3; i++) {
            int cidx = tid + i*128;
            int row = cidx / 6, off = (cidx % 6) * 8;
            unsigned d = (unsigned)((row*QKP + off) * 2);
            cpa16(sKh_b + d, g_KH + qkBase + (size_t)(k0 + row)*DH + off, true);
        }
        #pragma unroll
        for (int i = 0; i < 3; i++) {
            int cidx = tid + i*128;
            int row = cidx / 8, off = (cidx % 8) * 8;
            unsigned d = (unsigned)((row*VTP + off) * 2);
            cpa16(sVh_b + d, g_VH + vBase + (size_t)row*SPAD + k0 + off, true);
        }
        CP_COMMIT(); CP_WAIT0();
        __syncthreads();

        float s[8][4];
        #pragma unroll
        for (int i = 0; i < 8; i++)
            #pragma unroll
            for (int j = 0; j < 4; j++) s[i][j] = 0.f;

        #pragma unroll
        for (int kk = 0; kk < 3; kk++) {
            unsigned bhf[8][2];
            #pragma unroll
            for (int nb = 0; nb < 4; nb++) {
                unsigned off = (unsigned)(((nb*16 + bRowSel)*QKP + kk*16 + bColSel) * 2);
                unsigned t[4];
                ldsm_x4(t, sKh_b + off);
                bhf[2*nb][0]=t[0]; bhf[2*nb][1]=t[1]; bhf[2*nb+1][0]=t[2]; bhf[2*nb+1][1]=t[3];
            }
            #pragma unroll
            for (int nt = 0; nt < 8; nt++)
                mma_f16(s[nt], qh[kk], bhf[nt]);
        }

        #pragma unroll
        for (int nt = 0; nt < 8; nt++) {
            #pragma unroll
            for (int e = 0; e < 2; e++) {
                int col = k0 + nt*8 + (lane & 3)*2 + e;
                bool cmm = (col >= SS);
                bool cnm = (col >= NM1);
                if (cmm || (rm0 && cnm)) s[nt][e]   = -1e30f;
                if (cmm || (rm1 && cnm)) s[nt][2+e] = -1e30f;
            }
        }

        float t0 = -1e30f, t1 = -1e30f;
        #pragma unroll
        for (int nt = 0; nt < 8; nt++) {
            t0 = fmaxf(t0, fmaxf(s[nt][0], s[nt][1]));
            t1 = fmaxf(t1, fmaxf(s[nt][2], s[nt][3]));
        }
        t0 = fmaxf(t0, __shfl_xor_sync(0xffffffffu, t0, 1));
        t0 = fmaxf(t0, __shfl_xor_sync(0xffffffffu, t0, 2));
        t1 = fmaxf(t1, __shfl_xor_sync(0xffffffffu, t1, 1));
        t1 = fmaxf(t1, __shfl_xor_sync(0xffffffffu, t1, 2));
        float nm0 = fmaxf(m0r, t0), nm1 = fmaxf(m1r, t1);
        float f0 = __expf(m0r - nm0), f1 = __expf(m1r - nm1);
        m0r = nm0; m1r = nm1;

        float ps0 = 0.f, ps1 = 0.f;
        #pragma unroll
        for (int nt = 0; nt < 8; nt++) {
            s[nt][0] = __expf(s[nt][0] - m0r);
            s[nt][1] = __expf(s[nt][1] - m0r);
            s[nt][2] = __expf(s[nt][2] - m1r);
            s[nt][3] = __expf(s[nt][3] - m1r);
            ps0 += s[nt][0] + s[nt][1];
            ps1 += s[nt][2] + s[nt][3];
        }
        ps0 += __shfl_xor_sync(0xffffffffu, ps0, 1);
        ps0 += __shfl_xor_sync(0xffffffffu, ps0, 2);
        ps1 += __shfl_xor_sync(0xffffffffu, ps1, 1);
        ps1 += __shfl_xor_sync(0xffffffffu, ps1, 2);
        l0 = l0*f0 + ps0;
        l1 = l1*f1 + ps1;
        #pragma unroll
        for (int nt = 0; nt < 6; nt++) {
            o[nt][0] *= f0; o[nt][1] *= f0;
            o[nt][2] *= f1; o[nt][3] *= f1;
        }

        #pragma unroll
        for (int kk = 0; kk < 4; kk++) {
            unsigned pah[4];
            __half2 t01;
            t01 = __floats2half2_rn(s[2*kk  ][0], s[2*kk  ][1]); pah[0] = *(unsigned*)&t01;
            t01 = __floats2half2_rn(s[2*kk  ][2], s[2*kk  ][3]); pah[1] = *(unsigned*)&t01;
            t01 = __floats2half2_rn(s[2*kk+1][0], s[2*kk+1][1]); pah[2] = *(unsigned*)&t01;
            t01 = __floats2half2_rn(s[2*kk+1][2], s[2*kk+1][3]); pah[3] = *(unsigned*)&t01;

            unsigned vbh[6][2];
            #pragma unroll
            for (int nb = 0; nb < 3; nb++) {
                unsigned off = (unsigned)(((nb*16 + bRowSel)*VTP + kk*16 + bColSel) * 2);
                unsigned t[4];
                ldsm_x4(t, sVh_b + off);
                vbh[2*nb][0]=t[0]; vbh[2*nb][1]=t[1]; vbh[2*nb+1][0]=t[2]; vbh[2*nb+1][1]=t[3];
            }
            #pragma unroll
            for (int nt = 0; nt < 6; nt++)
                mma_f16(o[nt], pah, vbh[nt]);
        }
    }

    float il0 = 1.f / l0, il1 = 1.f / l1;
    #pragma unroll
    for (int nt = 0; nt < 6; nt++) {
        int col = h*DH + nt*8 + (lane & 3)*2;
        if (row0 < SS) {
            __half2 hh = __floats2half2_rn(o[nt][0]*il0, o[nt][1]*il0);
            *(__half2*)&AH[(size_t)(b*SS + row0)*DD + col] = hh;
        }
        if (row1 < SS) {
            __half2 hh = __floats2half2_rn(o[nt][2]*il1, o[nt][3]*il1);
            *(__half2*)&AH[(size_t)(b*SS + row1)*DD + col] = hh;
        }
    }
}

// ---------------- residual add + layernorm ----------------
__global__ void __launch_bounds__(128) add_ln_kernel(float* __restrict__ src, const float* __restrict__ res,
                                                     const float* __restrict__ g, const float* __restrict__ bta,
                                                     __half* __restrict__ XH)
{
    int row = blockIdx.x;
    int tid = threadIdx.x;
    float x[3];
    float s = 0.f, sq = 0.f;
    #pragma unroll
    for (int i = 0; i < 3; i++) {
        int d = tid + i*128;
        float v = src[(size_t)row*DD + d] + res[(size_t)row*DD + d];
        x[i] = v; s += v; sq += v*v;
    }
    #pragma unroll
    for (int o = 16; o > 0; o >>= 1) {
        s  += __shfl_xor_sync(0xffffffffu, s,  o);
        sq += __shfl_xor_sync(0xffffffffu, sq, o);
    }
    __shared__ float ss[4], ssq[4];
    int w = tid >> 5;
    if ((tid & 31) == 0) { ss[w] = s; ssq[w] = sq; }
    __syncthreads();
    s  = ss[0]+ss[1]+ss[2]+ss[3];
    sq = ssq[0]+ssq[1]+ssq[2]+ssq[3];
    float mean = s * (1.f/384.f);
    float var  = sq * (1.f/384.f) - mean*mean;
    float rs = rsqrtf(var + 1e-5f);
    #pragma unroll
    for (int i = 0; i < 3; i++) {
        int d = tid + i*128;
        float y = (x[i]-mean)*rs*g[d] + bta[d];
        src[(size_t)row*DD + d] = y;
        XH[(size_t)row*DD + d] = __float2half_rn(y);
    }
}

__global__ void copy_out_kernel(float* __restrict__ out)
{
    int idx = blockIdx.x*blockDim.x + threadIdx.x;
    if (idx >= BB*TT*DD) return;
    int d = idx % DD;
    int t = (idx/DD) % TT;
    int b = idx / (DD*TT);
    out[idx] = g_SRC[((size_t)(b*SS + (SS-TT) + t))*DD + d];
}

// ---------------- host launcher ----------------
extern "C" void kernel_launch(void* const* d_in, const int* in_sizes, int n_in,
                              void* d_out, int out_size)
{
    (void)in_sizes; (void)n_in; (void)out_size;
    const float* hand_t    = (const float*)d_in[0];
    const float* head_t    = (const float*)d_in[1];
    const float* hand_m1   = (const float*)d_in[2];
    const float* head_m1   = (const float*)d_in[3];
    const float* c_hand_t  = (const float*)d_in[4];
    const float* c_head_t  = (const float*)d_in[5];
    const float* c_hand_m1 = (const float*)d_in[6];
    const float* c_head_m1 = (const float*)d_in[7];
    const float* state_t   = (const float*)d_in[8];
    const float* state_m1  = (const float*)d_in[9];
    const float* tr_t      = (const float*)d_in[10];
    const float* tr_m1     = (const float*)d_in[11];
    const float* tok_m1    = (const float*)d_in[12];
    const float* tok_t     = (const float*)d_in[13];
    const float* Wq  = (const float*)d_in[14];
    const float* bq  = (const float*)d_in[15];
    const float* Wk  = (const float*)d_in[16];
    const float* bk  = (const float*)d_in[17];
    const float* Wv  = (const float*)d_in[18];
    const float* bv  = (const float*)d_in[19];
    const float* Wo  = (const float*)d_in[20];
    const float* bo  = (const float*)d_in[21];
    const float* W1  = (const float*)d_in[22];
    const float* b1  = (const float*)d_in[23];
    const float* W2  = (const float*)d_in[24];
    const float* b2  = (const float*)d_in[25];
    const float* g1  = (const float*)d_in[26];
    const float* be1 = (const float*)d_in[27];
    const float* g2  = (const float*)d_in[28];
    const float* be2 = (const float*)d_in[29];

    float *SRC, *PROJ, *BQKV;
    __half *XH, *FFH, *WqkvH, *WoH, *W1H, *W2H;
    cudaGetSymbolAddress((void**)&SRC,   g_SRC);
    cudaGetSymbolAddress((void**)&PROJ,  g_PROJ);
    cudaGetSymbolAddress((void**)&XH,    g_XH);
    cudaGetSymbolAddress((void**)&FFH,   g_FFH);
    cudaGetSymbolAddress((void**)&WqkvH, g_WqkvH);
    cudaGetSymbolAddress((void**)&WoH,   g_WoH);
    cudaGetSymbolAddress((void**)&W1H,   g_W1H);
    cudaGetSymbolAddress((void**)&W2H,   g_W2H);
    cudaGetSymbolAddress((void**)&BQKV,  g_bqkv);

    cudaFuncSetAttribute(gemm_kernel<false,false,false>, cudaFuncAttributeMaxDynamicSharedMemorySize, GSMEM);
    cudaFuncSetAttribute(gemm_kernel<true,true,false>,   cudaFuncAttributeMaxDynamicSharedMemorySize, GSMEM);
    cudaFuncSetAttribute(gemm_kernel<false,false,true>,  cudaFuncAttributeMaxDynamicSharedMemorySize, GSMEM);

    build_src_kernel<<<1024, 256>>>(hand_t, head_t, hand_m1, head_m1,
                                    state_t, state_m1, tok_m1, tok_t);
    build_coord_kernel<<<98, 256>>>(c_hand_t, c_head_t, c_hand_m1, c_head_m1, tr_t, tr_m1);
    split_qkv_w_kernel<<<2048, 256>>>(Wq, Wk, Wv, bq, bk, bv);
    split_weights_kernel<<<4096, 256>>>(Wo, W1, W2);
    split_kernel<<<2048, 256>>>(SRC, XH, MM*DD);

    const int MB = (MM + 127)/128;   // 65
    for (int l = 0; l < LL; l++) {
        gemm_kernel<false,false,true><<<dim3(MB, QKVN/128), 256, GSMEM>>>(MM, QKVN, DD, XH,
            WqkvH + (size_t)l*QKVN*DD, BQKV + l*QKVN, nullptr, nullptr);
        attn_mma_kernel<<<dim3(17, 64), 128>>>(XH);
        gemm_kernel<false,false,false><<<dim3(MB, DD/128), 256, GSMEM>>>(MM, DD, DD, XH,
            WoH + (size_t)l*DD*DD, bo + l*DD, PROJ, nullptr);
        add_ln_kernel<<<MM, 128>>>(SRC, PROJ, g1 + l*DD, be1 + l*DD, XH);
        gemm_kernel<true,true,false><<<dim3(MB, FFD/128), 256, GSMEM>>>(MM, FFD, DD, XH,
            W1H + (size_t)l*FFD*DD, b1 + l*FFD, nullptr, FFH);
        gemm_kernel<false,false,false><<<dim3(MB, DD/128), 256, GSMEM>>>(MM, DD, FFD, FFH,
            W2H + (size_t)l*DD*FFD, b2 + l*DD, PROJ, nullptr);
        add_ln_kernel<<<MM, 128>>>(SRC, PROJ, g2 + l*DD, be2 + l*DD, XH);
    }
    copy_out_kernel<<<48, 256>>>((float*)d_out);
}

// round 11
// speedup vs baseline: 2.7063x; 1.0031x over previous
#include <cuda_runtime.h>
#include <cuda_fp16.h>
#include <math.h>

#define BB 8
#define NN 256
#define DD 384
#define LL 6
#define HH 8
#define FFD 1536
#define TT 4
#define DH 48
#define NM1 517
#define SS 1034
#define SPAD 1152
#define MM (BB*SS)
#define QKVN 1152

// ---------------- scratch ----------------
__device__ float g_SRC [MM*DD];
__device__ float g_COORD[MM*3];

__device__ __half g_XH[MM*DD];
__device__ __half g_FFH[MM*FFD];

__device__ __half g_QH[64*SPAD*DH];
__device__ __half g_KH[64*SPAD*DH];
__device__ __half g_VH[64*DH*SPAD];

__device__ __half g_WqkvH[LL*QKVN*DD];
__device__ __half g_WoH[LL*DD*DD];
__device__ __half g_W1H[LL*FFD*DD];
__device__ __half g_W2H[LL*DD*FFD];
__device__ float g_bqkv[LL*QKVN];

// ---------------- input assembly ----------------
__global__ void build_src_kernel(const float* __restrict__ hand_t, const float* __restrict__ head_t,
                                 const float* __restrict__ hand_m1, const float* __restrict__ head_m1,
                                 const float* __restrict__ state_t, const float* __restrict__ state_m1,
                                 const float* __restrict__ tok_m1, const float* __restrict__ tok_t)
{
    for (int idx = blockIdx.x*blockDim.x + threadIdx.x; idx < BB*SS*DD; idx += gridDim.x*blockDim.x) {
        int d = idx % DD;
        int s = (idx / DD) % SS;
        int b = idx / (DD*SS);
        float v;
        if      (s == 0)    v = state_m1[b*DD + d];
        else if (s < 257)   v = hand_m1[((b*NN)+(s-1  ))*DD + d];
        else if (s < 513)   v = head_m1[((b*NN)+(s-257))*DD + d];
        else if (s < 517)   v = tok_m1[(s-513)*DD + d];
        else if (s == 517)  v = state_t[b*DD + d];
        else if (s < 774)   v = hand_t[((b*NN)+(s-518))*DD + d];
        else if (s < 1030)  v = head_t[((b*NN)+(s-774))*DD + d];
        else                v = tok_t[(s-1030)*DD + d];
        g_SRC[idx] = v;
    }
}

__global__ void build_coord_kernel(const float* __restrict__ c_hand_t, const float* __restrict__ c_head_t,
                                   const float* __restrict__ c_hand_m1, const float* __restrict__ c_head_m1,
                                   const float* __restrict__ tr_t, const float* __restrict__ tr_m1)
{
    for (int idx = blockIdx.x*blockDim.x + threadIdx.x; idx < BB*SS*3; idx += gridDim.x*blockDim.x) {
        int cdim = idx % 3;
        int s = (idx/3) % SS;
        int b = idx / (3*SS);
        float v;
        if      (s == 0)    v = tr_m1[b*3+cdim];
        else if (s < 257)   v = c_hand_m1[((b*NN)+(s-1  ))*3 + cdim];
        else if (s < 513)   v = c_head_m1[((b*NN)+(s-257))*3 + cdim];
        else if (s < 517)   v = tr_m1[b*3+cdim];
        else if (s == 517)  v = tr_t[b*3+cdim];
        else if (s < 774)   v = c_hand_t[((b*NN)+(s-518))*3 + cdim];
        else if (s < 1030)  v = c_head_t[((b*NN)+(s-774))*3 + cdim];
        else                v = tr_t[b*3+cdim];
        g_COORD[idx] = v;
    }
}

// ---------------- fp32 -> fp16 ----------------
__global__ void split_kernel(const float* __restrict__ x, __half* __restrict__ hi, int n)
{
    for (int i = blockIdx.x*blockDim.x + threadIdx.x; i < n; i += gridDim.x*blockDim.x)
        hi[i] = __float2half_rn(x[i]);
}

__global__ void split_qkv_w_kernel(const float* __restrict__ Wq, const float* __restrict__ Wk,
                                   const float* __restrict__ Wv, const float* __restrict__ bq,
                                   const float* __restrict__ bk, const float* __restrict__ bv)
{
    int tid0 = blockIdx.x*blockDim.x + threadIdx.x;
    if (tid0 < LL*QKVN) {
        int r = tid0 % QKVN, l = tid0 / QKVN;
        float v;
        if      (r < DD)   v = bq[l*DD + r];
        else if (r < 2*DD) v = bk[l*DD + r-DD];
        else               v = bv[l*DD + r-2*DD];
        g_bqkv[tid0] = v;
    }
    const int total = LL*QKVN*DD;
    for (int idx = tid0; idx < total; idx += gridDim.x*blockDim.x) {
        int k = idx % DD;
        int r = (idx / DD) % QKVN;
        int l = idx / (DD*QKVN);
        float v;
        if      (r < DD)    v = Wq[((size_t)l*DD + r      )*DD + k];
        else if (r < 2*DD)  v = Wk[((size_t)l*DD + r-DD   )*DD + k];
        else                v = Wv[((size_t)l*DD + r-2*DD )*DD + k];
        g_WqkvH[idx] = __float2half_rn(v);
    }
}

__global__ void split_weights_kernel(const float* __restrict__ Wo, const float* __restrict__ W1,
                                     const float* __restrict__ W2)
{
    const int S1 = DD*DD, S2 = FFD*DD, S3 = DD*FFD;
    const int SEG = S1 + S2 + S3;
    const int total = LL*SEG;
    for (int idx = blockIdx.x*blockDim.x + threadIdx.x; idx < total; idx += gridDim.x*blockDim.x) {
        int l = idx / SEG, r = idx % SEG;
        if (r < S1)         g_WoH[(size_t)l*S1 + r]      = __float2half_rn(Wo[(size_t)l*S1 + r]);
        else if (r < S1+S2) g_W1H[(size_t)l*S2 + r-S1]   = __float2half_rn(W1[(size_t)l*S2 + r-S1]);
        else                g_W2H[(size_t)l*S3 + r-S1-S2]= __float2half_rn(W2[(size_t)l*S3 + r-S1-S2]);
    }
}

// ---------------- helpers ----------------
__device__ __forceinline__ unsigned smem_addr(const void* p) {
    return (unsigned)__cvta_generic_to_shared(p);
}
__device__ __forceinline__ void ldsm_x4(unsigned r[4], unsigned addr) {
    asm volatile("ldmatrix.sync.aligned.m8n8.x4.shared.b16 {%0,%1,%2,%3}, [%4];"
                 : "=r"(r[0]), "=r"(r[1]), "=r"(r[2]), "=r"(r[3]) : "r"(addr));
}
__device__ __forceinline__ void mma_f16(float c[4], const unsigned a[4], const unsigned b[2]) {
    asm volatile("mma.sync.aligned.m16n8k16.row.col.f32.f16.f16.f32 "
                 "{%0,%1,%2,%3}, {%4,%5,%6,%7}, {%8,%9}, {%0,%1,%2,%3};"
                 : "+f"(c[0]), "+f"(c[1]), "+f"(c[2]), "+f"(c[3])
                 : "r"(a[0]), "r"(a[1]), "r"(a[2]), "r"(a[3]), "r"(b[0]), "r"(b[1]));
}
__device__ __forceinline__ void cpa16(unsigned dst, const void* src, bool pred) {
    int sz = pred ? 16 : 0;
    asm volatile("cp.async.cg.shared.global [%0], [%1], 16, %2;"
                 :: "r"(dst), "l"(src), "r"(sz) : "memory");
}
#define CP_COMMIT() asm volatile("cp.async.commit_group;" ::: "memory")
#define CP_WAIT1()  asm volatile("cp.async.wait_group 1;" ::: "memory")
#define CP_WAIT0()  asm volatile("cp.async.wait_group 0;" ::: "memory")

// ---------------- fp16 GEMM (generic): BM=128,BN=128; optional GELU/half-out/rope ----
#define LDSMP 40
#define GARRB (128*LDSMP*2)
#define GSTG (2*GARRB)
#define GSMEM (2*GSTG)               // 40960

template<bool DO_GELU, bool HALF_OUT, bool ROPE>
__global__ void __launch_bounds__(256) gemm_kernel(int M, int N, int K,
    const __half* __restrict__ Ah, const __half* __restrict__ Wh,
    const float* __restrict__ bias, float* __restrict__ C,
    __half* __restrict__ Ch)
{
    extern __shared__ __half dsm[];
    const int tid  = threadIdx.x;
    const int lane = tid & 31;
    const int warp = tid >> 5;
    const int wm   = warp >> 2;
    const int wn   = warp & 3;
    const int m0   = blockIdx.x * 128;
    const int n0   = blockIdx.y * 128;

    float c[4][4][4];
    #pragma unroll
    for (int i = 0; i < 4; i++)
        #pragma unroll
        for (int j = 0; j < 4; j++)
            #pragma unroll
            for (int r = 0; r < 4; r++) c[i][j][r] = 0.f;

    const int lr = tid >> 2;
    const int lc = (tid & 3) * 8;

    const int aRow    = wm*64 + (lane & 7) + ((lane >> 3) & 1) * 8;
    const int aColSel = (lane >> 4) * 8;
    const int bRow    = wn*32 + (lane & 7) + ((lane >> 4) & 1) * 8;
    const int bColSel = ((lane >> 3) & 1) * 8;

    const unsigned sbase = smem_addr(dsm);

    auto load_tile = [&](int kt, int stage) {
        const int kc = kt * 32;
        const unsigned sb = sbase + stage*GSTG;
        #pragma unroll
        for (int half = 0; half < 2; half++) {
            int r  = lr + half*64;
            int gm = m0 + r;
            bool pa = gm < M;
            int gmc = pa ? gm : 0;
            unsigned drow = (unsigned)((r*LDSMP + lc) * 2);
            cpa16(sb + drow,         Ah + (size_t)gmc*K + kc + lc, pa);
            cpa16(sb + GARRB + drow, Wh + (size_t)(n0 + r)*K + kc + lc, true);
        }
    };

    const int nk = K >> 5;
    load_tile(0, 0);
    CP_COMMIT();

    for (int kt = 0; kt < nk; kt++) {
        const int cur = kt & 1;
        if (kt + 1 < nk) load_tile(kt + 1, cur ^ 1);
        CP_COMMIT();
        CP_WAIT1();
        __syncthreads();

        const unsigned sb    = sbase + cur*GSTG;
        const unsigned sAh_b = sb;
        const unsigned sWh_b = sb + GARRB;

        #pragma unroll
        for (int kk = 0; kk < 2; kk++) {
            unsigned ah[4][4], bh[4][2];
            #pragma unroll
            for (int mt = 0; mt < 4; mt++) {
                unsigned off = (unsigned)(((aRow + mt*16)*LDSMP + kk*16 + aColSel) * 2);
                ldsm_x4(ah[mt], sAh_b + off);
            }
            #pragma unroll
            for (int np = 0; np < 2; np++) {
                unsigned off = (unsigned)(((bRow + np*16)*LDSMP + kk*16 + bColSel) * 2);
                unsigned t[4];
                ldsm_x4(t, sWh_b + off);
                bh[2*np][0]=t[0]; bh[2*np][1]=t[1]; bh[2*np+1][0]=t[2]; bh[2*np+1][1]=t[3];
            }
            #pragma unroll
            for (int mt = 0; mt < 4; mt++)
                #pragma unroll
                for (int nt = 0; nt < 4; nt++)
                    mma_f16(c[mt][nt], ah[mt], bh[nt]);
        }
        __syncthreads();
    }

    if (ROPE) {
        const float scale = 0.14433756729740643f;   // 1/sqrt(48)
        const int j = (lane & 3) * 2;
        const float fj  = exp2f(-1.6609640474436813f * (float)j);
        const float fj1 = exp2f(-1.6609640474436813f * (float)(j+1));
        const int wcolBase = n0 + wn*32;
        #pragma unroll
        for (int mt = 0; mt < 4; mt++) {
            int row0 = m0 + wm*64 + mt*16 + (lane >> 2);
            int row1 = row0 + 8;
            bool ok0 = row0 < M, ok1 = row1 < M;
            int b0 = row0 / SS, s0 = row0 - b0*SS;
            int b1 = row1 / SS, s1 = row1 - b1*SS;
            #pragma unroll
            for (int p = 0; p < 2; p++) {
                int wcol = wcolBase + p*16;
                int sec  = wcol / DD;
                int hcol = wcol - sec*DD;
                int h    = hcol / DH;
                int dh0  = hcol - h*DH;
                float x1a = c[mt][2*p][0] + bias[wcol + j];
                float x1b = c[mt][2*p][1] + bias[wcol + j + 1];
                float x1c = c[mt][2*p][2] + bias[wcol + j];
                float x1d = c[mt][2*p][3] + bias[wcol + j + 1];
                float x2a = c[mt][2*p+1][0] + bias[wcol + 8 + j];
                float x2b = c[mt][2*p+1][1] + bias[wcol + 8 + j + 1];
                float x2c = c[mt][2*p+1][2] + bias[wcol + 8 + j];
                float x2d = c[mt][2*p+1][3] + bias[wcol + 8 + j + 1];
                int bh0 = b0*HH + h, bh1 = b1*HH + h;
                if (sec == 2) {
                    if (ok0) {
                        size_t base = ((size_t)bh0*DH + dh0 + j)*SPAD + s0;
                        g_VH[base          ] = __float2half_rn(x1a);
                        g_VH[base +   SPAD ] = __float2half_rn(x1b);
                        g_VH[base + 8*SPAD ] = __float2half_rn(x2a);
                        g_VH[base + 9*SPAD ] = __float2half_rn(x2b);
                    }
                    if (ok1) {
                        size_t base = ((size_t)bh1*DH + dh0 + j)*SPAD + s1;
                        g_VH[base          ] = __float2half_rn(x1c);
                        g_VH[base +   SPAD ] = __float2half_rn(x1d);
                        g_VH[base + 8*SPAD ] = __float2half_rn(x2c);
                        g_VH[base + 9*SPAD ] = __float2half_rn(x2d);
                    }
                } else {
                    int a = dh0 >> 4;
                    float co0 = g_COORD[row0*3 + a];
                    float co1 = g_COORD[row1*3 + a];
                    float c00, s00, c01, s01, c10, s10, c11, s11;
                    __sincosf(co0*fj,  &s00, &c00);
                    __sincosf(co0*fj1, &s01, &c01);
                    __sincosf(co1*fj,  &s10, &c10);
                    __sincosf(co1*fj1, &s11, &c11);
                    float y1a = x1a*c00 - x2a*s00, y2a = x1a*s00 + x2a*c00;
                    float y1b = x1b*c01 - x2b*s01, y2b = x1b*s01 + x2b*c01;
                    float y1c = x1c*c10 - x2c*s10, y2c = x1c*s10 + x2c*c10;
                    float y1d = x1d*c11 - x2d*s11, y2d = x1d*s11 + x2d*c11;
                    __half* dst = (sec == 0) ? g_QH : g_KH;
                    float sc = (sec == 0) ? scale : 1.f;
                    if (ok0) {
                        size_t base = ((size_t)bh0*SPAD + s0)*DH + dh0;
                        *(__half2*)&dst[base + j]     = __floats2half2_rn(y1a*sc, y1b*sc);
                        *(__half2*)&dst[base + j + 8] = __floats2half2_rn(y2a*sc, y2b*sc);
                    }
                    if (ok1) {
                        size_t base = ((size_t)bh1*SPAD + s1)*DH + dh0;
                        *(__half2*)&dst[base + j]     = __floats2half2_rn(y1c*sc, y1d*sc);
                        *(__half2*)&dst[base + j + 8] = __floats2half2_rn(y2c*sc, y2d*sc);
                    }
                }
            }
        }
        return;
    }

    #pragma unroll
    for (int mt = 0; mt < 4; mt++) {
        #pragma unroll
        for (int nt = 0; nt < 4; nt++) {
            int col  = n0 + wn*32 + nt*8 + (lane & 3)*2;
            float b0 = bias[col], b1 = bias[col+1];
            int row0 = m0 + wm*64 + mt*16 + (lane >> 2);
            int row1 = row0 + 8;
            float v0 = c[mt][nt][0] + b0, v1 = c[mt][nt][1] + b1;
            float v2 = c[mt][nt][2] + b0, v3 = c[mt][nt][3] + b1;
            if (DO_GELU) {
                v0 = 0.5f*v0*(1.0f+erff(v0*0.7071067811865475f));
                v1 = 0.5f*v1*(1.0f+erff(v1*0.7071067811865475f));
                v2 = 0.5f*v2*(1.0f+erff(v2*0.7071067811865475f));
                v3 = 0.5f*v3*(1.0f+erff(v3*0.7071067811865475f));
            }
            if (HALF_OUT) {
                __half2 h01 = __floats2half2_rn(v0, v1);
                __half2 h23 = __floats2half2_rn(v2, v3);
                if (row0 < M) *(__half2*)&Ch[(size_t)row0*N + col] = h01;
                if (row1 < M) *(__half2*)&Ch[(size_t)row1*N + col] = h23;
            } else {
                if (row0 < M) *(float2*)&C[(size_t)row0*N + col] = make_float2(v0, v1);
                if (row1 < M) *(float2*)&C[(size_t)row1*N + col] = make_float2(v2, v3);
            }
        }
    }
}

// ---------------- fused GEMM + residual + LayerNorm: BM=64, BN=384(=N) ------------
// x = A*W^T + bias + SRC ; LN over the row ; writes SRC (fp32) and XH (fp16)
#define LA_B (64*LDSMP*2)            // 5120
#define LW_B (384*LDSMP*2)           // 30720
#define LSTG (LA_B + LW_B)           // 35840
#define LSMEM (2*LSTG)               // 71680

__global__ void __launch_bounds__(256) gemm_ln_kernel(int M, int K,
    const __half* __restrict__ Ah, const __half* __restrict__ Wh,
    const float* __restrict__ bias, const float* __restrict__ g,
    const float* __restrict__ bta,
    float* __restrict__ SRC, __half* __restrict__ XH)
{
    extern __shared__ __half dsm[];
    __shared__ float rsum[64][4], rsq[64][4];

    const int tid  = threadIdx.x;
    const int lane = tid & 31;
    const int warp = tid >> 5;
    const int wm   = warp >> 2;          // 0..1 (rows 32*wm)
    const int wn   = warp & 3;           // 0..3 (cols 96*wn)
    const int m0   = blockIdx.x * 64;

    float c[2][12][4];
    #pragma unroll
    for (int i = 0; i < 2; i++)
        #pragma unroll
        for (int j = 0; j < 12; j++)
            #pragma unroll
            for (int r = 0; r < 4; r++) c[i][j][r] = 0.f;

    const int aRowSel = (lane & 7) + ((lane >> 3) & 1) * 8;
    const int aColSel = (lane >> 4) * 8;
    const int bRowSel = (lane & 7) + ((lane >> 4) & 1) * 8;
    const int bColSel = ((lane >> 3) & 1) * 8;

    const unsigned sbase = smem_addr(dsm);

    auto load_tile = [&](int kt, int stage) {
        const int kc = kt * 32;
        const unsigned sb = sbase + stage*LSTG;
        // A: 64 rows x 4 chunks = 256
        {
            int row = tid >> 2, u = tid & 3;
            int gm = m0 + row;
            bool pa = gm < M;
            int gmc = pa ? gm : 0;
            cpa16(sb + (unsigned)((row*LDSMP + u*8) * 2), Ah + (size_t)gmc*K + kc + u*8, pa);
        }
        // W: 384 rows x 4 chunks = 1536
        #pragma unroll
        for (int i = 0; i < 6; i++) {
            int idx = tid + i*256;
            int row = idx >> 2, u = idx & 3;
            cpa16(sb + LA_B + (unsigned)((row*LDSMP + u*8) * 2), Wh + (size_t)row*K + kc + u*8, true);
        }
    };

    const int nk = K >> 5;
    load_tile(0, 0);
    CP_COMMIT();

    for (int kt = 0; kt < nk; kt++) {
        const int cur = kt & 1;
        if (kt + 1 < nk) load_tile(kt + 1, cur ^ 1);
        CP_COMMIT();
        CP_WAIT1();
        __syncthreads();

        const unsigned sb    = sbase + cur*LSTG;
        const unsigned sWh_b = sb + LA_B;

        #pragma unroll
        for (int kk = 0; kk < 2; kk++) {
            unsigned ah[2][4], bh[12][2];
            #pragma unroll
            for (int mt = 0; mt < 2; mt++) {
                unsigned off = (unsigned)(((wm*32 + mt*16 + aRowSel)*LDSMP + kk*16 + aColSel) * 2);
                ldsm_x4(ah[mt], sb + off);
            }
            #pragma unroll
            for (int nb = 0; nb < 6; nb++) {
                unsigned off = (unsigned)(((wn*96 + nb*16 + bRowSel)*LDSMP + kk*16 + bColSel) * 2);
                unsigned t[4];
                ldsm_x4(t, sWh_b + off);
                bh[2*nb][0]=t[0]; bh[2*nb][1]=t[1]; bh[2*nb+1][0]=t[2]; bh[2*nb+1][1]=t[3];
            }
            #pragma unroll
            for (int mt = 0; mt < 2; mt++)
                #pragma unroll
                for (int nt = 0; nt < 12; nt++)
                    mma_f16(c[mt][nt], ah[mt], bh[nt]);
        }
        __syncthreads();
    }

    // epilogue: x = c + bias + SRC; row-reduce; LN; write SRC + XH
    #pragma unroll
    for (int mt = 0; mt < 2; mt++) {
        int r0 = m0 + wm*32 + mt*16 + (lane >> 2);
        int r1 = r0 + 8;
        bool ok0 = r0 < M, ok1 = r1 < M;
        float s0 = 0.f, q0 = 0.f, s1 = 0.f, q1 = 0.f;
        #pragma unroll
        for (int nt = 0; nt < 12; nt++) {
            int col = wn*96 + nt*8 + (lane & 3)*2;
            float b0 = bias[col], b1 = bias[col+1];
            float2 sr0 = ok0 ? *(float2*)&SRC[(size_t)r0*DD + col] : make_float2(0.f,0.f);
            float2 sr1 = ok1 ? *(float2*)&SRC[(size_t)r1*DD + col] : make_float2(0.f,0.f);
            float x0 = c[mt][nt][0] + b0 + sr0.x;
            float x1 = c[mt][nt][1] + b1 + sr0.y;
            float x2 = c[mt][nt][2] + b0 + sr1.x;
            float x3 = c[mt][nt][3] + b1 + sr1.y;
            c[mt][nt][0]=x0; c[mt][nt][1]=x1; c[mt][nt][2]=x2; c[mt][nt][3]=x3;
            s0 += x0 + x1; q0 += x0*x0 + x1*x1;
            s1 += x2 + x3; q1 += x2*x2 + x3*x3;
        }
        s0 += __shfl_xor_sync(0xffffffffu, s0, 1);
        s0 += __shfl_xor_sync(0xffffffffu, s0, 2);
        q0 += __shfl_xor_sync(0xffffffffu, q0, 1);
        q0 += __shfl_xor_sync(0xffffffffu, q0, 2);
        s1 += __shfl_xor_sync(0xffffffffu, s1, 1);
        s1 += __shfl_xor_sync(0xffffffffu, s1, 2);
        q1 += __shfl_xor_sync(0xffffffffu, q1, 1);
        q1 += __shfl_xor_sync(0xffffffffu, q1, 2);
        if ((lane & 3) == 0) {
            int rl = wm*32 + mt*16 + (lane >> 2);
            rsum[rl][wn] = s0;  rsq[rl][wn] = q0;
            rsum[rl+8][wn] = s1; rsq[rl+8][wn] = q1;
        }
    }
    __syncthreads();

    #pragma unroll
    for (int mt = 0; mt < 2; mt++) {
        int rl0 = wm*32 + mt*16 + (lane >> 2);
        int r0 = m0 + rl0, r1 = r0 + 8;
        float S0 = rsum[rl0][0]+rsum[rl0][1]+rsum[rl0][2]+rsum[rl0][3];
        float Q0 = rsq[rl0][0]+rsq[rl0][1]+rsq[rl0][2]+rsq[rl0][3];
        float S1 = rsum[rl0+8][0]+rsum[rl0+8][1]+rsum[rl0+8][2]+rsum[rl0+8][3];
        float Q1 = rsq[rl0+8][0]+rsq[rl0+8][1]+rsq[rl0+8][2]+rsq[rl0+8][3];
        float mean0 = S0*(1.f/384.f), var0 = Q0*(1.f/384.f) - mean0*mean0;
        float mean1 = S1*(1.f/384.f), var1 = Q1*(1.f/384.f) - mean1*mean1;
        float rs0 = rsqrtf(var0 + 1e-5f), rs1 = rsqrtf(var1 + 1e-5f);
        bool ok0 = r0 < M, ok1 = r1 < M;
        #pragma unroll
        for (int nt = 0; nt < 12; nt++) {
            int col = wn*96 + nt*8 + (lane & 3)*2;
            float g0 = g[col], g1 = g[col+1];
            float t0 = bta[col], t1 = bta[col+1];
            float y0 = (c[mt][nt][0]-mean0)*rs0*g0 + t0;
            float y1 = (c[mt][nt][1]-mean0)*rs0*g1 + t1;
            float y2 = (c[mt][nt][2]-mean1)*rs1*g0 + t0;
            float y3 = (c[mt][nt][3]-mean1)*rs1*g1 + t1;
            if (ok0) {
                *(float2*)&SRC[(size_t)r0*DD + col] = make_float2(y0, y1);
                *(__half2*)&XH[(size_t)r0*DD + col] = __floats2half2_rn(y0, y1);
            }
            if (ok1) {
                *(float2*)&SRC[(size_t)r1*DD + col] = make_float2(y2, y3);
                *(__half2*)&XH[(size_t)r1*DD + col] = __floats2half2_rn(y2, y3);
            }
        }
    }
}

// ---------------- tensor-core flash attention (fp16, pipelined K/V) ----------------
#define QKP 56
#define VTP 72

__global__ void __launch_bounds__(128) attn_mma_kernel(__half* __restrict__ AH)
{
    const int bh = blockIdx.y;
    const int b = bh >> 3, h = bh & 7;
    const int q0 = blockIdx.x * 64;
    const int tid = threadIdx.x;
    const int lane = tid & 31;
    const int warp = tid >> 5;

    __shared__ __half sQh[64*QKP];
    __shared__ __half sKh[2][64*QKP];
    __shared__ __half sVh[2][48*VTP];

    const unsigned sQh_b = smem_addr(sQh);
    const unsigned sKh_b = smem_addr(sKh);
    const unsigned sVh_b = smem_addr(sVh);
    const unsigned KSZ = 64*QKP*2, VSZ = 48*VTP*2;

    const size_t qkBase = (size_t)bh*SPAD*DH;
    const size_t vBase  = (size_t)bh*DH*SPAD;

    // Q stage
    #pragma unroll
    for (int i = 0; i < 3; i++) {
        int cidx = tid + i*128;
        int row = cidx / 6, off = (cidx % 6) * 8;
        cpa16(sQh_b + (unsigned)((row*QKP + off)*2),
              g_QH + qkBase + (size_t)(q0 + row)*DH + off, true);
    }
    CP_COMMIT();

    const int ktMax = (q0 + 63 < NM1) ? 9 : 17;

    auto stageKV = [&](int kt, int buf) {
        int k0 = kt * 64;
        #pragma unroll
        for (int i = 0; i < 3; i++) {
            int cidx = tid + i*128;
            int row = cidx / 6, off = (cidx % 6) * 8;
            cpa16(sKh_b + buf*KSZ + (unsigned)((row*QKP + off)*2),
                  g_KH + qkBase + (size_t)(k0 + row)*DH + off, true);
        }
        #pragma unroll
        for (int i = 0; i < 3; i++) {
            int cidx = tid + i*128;
            int row = cidx / 8, off = (cidx % 8) * 8;
            cpa16(sVh_b + buf*VSZ + (unsigned)((row*VTP + off)*2),
                  g_VH + vBase + (size_t)row*SPAD + k0 + off, true);
        }
    };

    stageKV(0, 0);
    CP_COMMIT();
    CP_WAIT1();            // Q ready
    __syncthreads();

    const int aRow = 16*warp + (lane & 7) + ((lane >> 3) & 1) * 8;
    const int aColSel = (lane >> 4) * 8;
    unsigned qh[3][4];
    #pragma unroll
    for (int kk = 0; kk < 3; kk++) {
        unsigned off = (unsigned)((aRow*QKP + kk*16 + aColSel) * 2);
        ldsm_x4(qh[kk], sQh_b + off);
    }

    float o[6][4];
    #pragma unroll
    for (int i = 0; i < 6; i++)
        #pragma unroll
        for (int j = 0; j < 4; j++) o[i][j] = 0.f;
    float m0r = -1e30f, m1r = -1e30f, l0 = 0.f, l1 = 0.f;

    const int row0 = q0 + 16*warp + (lane >> 2);
    const int row1 = row0 + 8;
    const bool rm0 = row0 < NM1, rm1 = row1 < NM1;

    const int bRowSel = (lane & 7) + ((lane >> 4) & 1) * 8;
    const int bColSel = ((lane >> 3) & 1) * 8;

    for (int kt = 0; kt < ktMax; kt++) {
        const int buf = kt & 1;
        if (kt + 1 < ktMax) stageKV(kt + 1, buf ^ 1);
        CP_COMMIT();
        CP_WAIT1();
        __syncthreads();

        const int k0 = kt * 64;
        const unsigned kB = sKh_b + buf*KSZ;
        const unsigned vB = sVh_b + buf*VSZ;

        float s[8][4];
        #pragma unroll
        for (int i = 0; i < 8; i++)
            #pragma unroll
            for (int j = 0; j < 4; j++) s[i][j] = 0.f;

        #pragma unroll
        for (int kk = 0; kk < 3; kk++) {
            unsigned bhf[8][2];
            #pragma unroll
            for (int nb = 0; nb < 4; nb++) {
                unsigned off = (unsigned)(((nb*16 + bRowSel)*QKP + kk*16 + bColSel) * 2);
                unsigned t[4];
                ldsm_x4(t, kB + off);
                bhf[2*nb][0]=t[0]; bhf[2*nb][1]=t[1]; bhf[2*nb+1][0]=t[2]; bhf[2*nb+1][1]=t[3];
            }
            #pragma unroll
            for (int nt = 0; nt < 8; nt++)
                mma_f16(s[nt], qh[kk], bhf[nt]);
        }

        #pragma unroll
        for (int nt = 0; nt < 8; nt++) {
            #pragma unroll
            for (int e = 0; e < 2; e++) {
                int col = k0 + nt*8 + (lane & 3)*2 + e;
                bool cmm = (col >= SS);
                bool cnm = (col >= NM1);
                if (cmm || (rm0 && cnm)) s[nt][e]   = -1e30f;
                if (cmm || (rm1 && cnm)) s[nt][2+e] = -1e30f;
            }
        }

        float t0 = -1e30f, t1 = -1e30f;
        #pragma unroll
        for (int nt = 0; nt < 8; nt++) {
            t0 = fmaxf(t0, fmaxf(s[nt][0], s[nt][1]));
            t1 = fmaxf(t1, fmaxf(s[nt][2], s[nt][3]));
        }
        t0 = fmaxf(t0, __shfl_xor_sync(0xffffffffu, t0, 1));
        t0 = fmaxf(t0, __shfl_xor_sync(0xffffffffu, t0, 2));
        t1 = fmaxf(t1, __shfl_xor_sync(0xffffffffu, t1, 1));
        t1 = fmaxf(t1, __shfl_xor_sync(0xffffffffu, t1, 2));
        float nm0 = fmaxf(m0r, t0), nm1 = fmaxf(m1r, t1);
        float f0 = __expf(m0r - nm0), f1 = __expf(m1r - nm1);
        m0r = nm0; m1r = nm1;

        float ps0 = 0.f, ps1 = 0.f;
        #pragma unroll
        for (int nt = 0; nt < 8; nt++) {
            s[nt][0] = __expf(s[nt][0] - m0r);
            s[nt][1] = __expf(s[nt][1] - m0r);
            s[nt][2] = __expf(s[nt][2] - m1r);
            s[nt][3] = __expf(s[nt][3] - m1r);
            ps0 += s[nt][0] + s[nt][1];
            ps1 += s[nt][2] + s[nt][3];
        }
        ps0 += __shfl_xor_sync(0xffffffffu, ps0, 1);
        ps0 += __shfl_xor_sync(0xffffffffu, ps0, 2);
        ps1 += __shfl_xor_sync(0xffffffffu, ps1, 1);
        ps1 += __shfl_xor_sync(0xffffffffu, ps1, 2);
        l0 = l0*f0 + ps0;
        l1 = l1*f1 + ps1;
        #pragma unroll
        for (int nt = 0; nt < 6; nt++) {
            o[nt][0] *= f0; o[nt][1] *= f0;
            o[nt][2] *= f1; o[nt][3] *= f1;
        }

        #pragma unroll
        for (int kk = 0; kk < 4; kk++) {
            unsigned pah[4];
            __half2 t01;
            t01 = __floats2half2_rn(s[2*kk  ][0], s[2*kk  ][1]); pah[0] = *(unsigned*)&t01;
            t01 = __floats2half2_rn(s[2*kk  ][2], s[2*kk  ][3]); pah[1] = *(unsigned*)&t01;
            t01 = __floats2half2_rn(s[2*kk+1][0], s[2*kk+1][1]); pah[2] = *(unsigned*)&t01;
            t01 = __floats2half2_rn(s[2*kk+1][2], s[2*kk+1][3]); pah[3] = *(unsigned*)&t01;

            unsigned vbh[6][2];
            #pragma unroll
            for (int nb = 0; nb < 3; nb++) {
                unsigned off = (unsigned)(((nb*16 + bRowSel)*VTP + kk*16 + bColSel) * 2);
                unsigned t[4];
                ldsm_x4(t, vB + off);
                vbh[2*nb][0]=t[0]; vbh[2*nb][1]=t[1]; vbh[2*nb+1][0]=t[2]; vbh[2*nb+1][1]=t[3];
            }
            #pragma unroll
            for (int nt = 0; nt < 6; nt++)
                mma_f16(o[nt], pah, vbh[nt]);
        }
        __syncthreads();
    }

    float il0 = 1.f / l0, il1 = 1.f / l1;
    #pragma unroll
    for (int nt = 0; nt < 6; nt++) {
        int col = h*DH + nt*8 + (lane & 3)*2;
        if (row0 < SS) {
            __half2 hh = __floats2half2_rn(o[nt][0]*il0, o[nt][1]*il0);
            *(__half2*)&AH[(size_t)(b*SS + row0)*DD + col] = hh;
        }
        if (row1 < SS) {
            __half2 hh = __floats2half2_rn(o[nt][2]*il1, o[nt][3]*il1);
            *(__half2*)&AH[(size_t)(b*SS + row1)*DD + col] = hh;
        }
    }
}

__global__ void copy_out_kernel(float* __restrict__ out)
{
    int idx = blockIdx.x*blockDim.x + threadIdx.x;
    if (idx >= BB*TT*DD) return;
    int d = idx % DD;
    int t = (idx/DD) % TT;
    int b = idx / (DD*TT);
    out[idx] = g_SRC[((size_t)(b*SS + (SS-TT) + t))*DD + d];
}

// ---------------- host launcher ----------------
extern "C" void kernel_launch(void* const* d_in, const int* in_sizes, int n_in,
                              void* d_out, int out_size)
{
    (void)in_sizes; (void)n_in; (void)out_size;
    const float* hand_t    = (const float*)d_in[0];
    const float* head_t    = (const float*)d_in[1];
    const float* hand_m1   = (const float*)d_in[2];
    const float* head_m1   = (const float*)d_in[3];
    const float* c_hand_t  = (const float*)d_in[4];
    const float* c_head_t  = (const float*)d_in[5];
    const float* c_hand_m1 = (const float*)d_in[6];
    const float* c_head_m1 = (const float*)d_in[7];
    const float* state_t   = (const float*)d_in[8];
    const float* state_m1  = (const float*)d_in[9];
    const float* tr_t      = (const float*)d_in[10];
    const float* tr_m1     = (const float*)d_in[11];
    const float* tok_m1    = (const float*)d_in[12];
    const float* tok_t     = (const float*)d_in[13];
    const float* Wq  = (const float*)d_in[14];
    const float* bq  = (const float*)d_in[15];
    const float* Wk  = (const float*)d_in[16];
    const float* bk  = (const float*)d_in[17];
    const float* Wv  = (const float*)d_in[18];
    const float* bv  = (const float*)d_in[19];
    const float* Wo  = (const float*)d_in[20];
    const float* bo  = (const float*)d_in[21];
    const float* W1  = (const float*)d_in[22];
    const float* b1  = (const float*)d_in[23];
    const float* W2  = (const float*)d_in[24];
    const float* b2  = (const float*)d_in[25];
    const float* g1  = (const float*)d_in[26];
    const float* be1 = (const float*)d_in[27];
    const float* g2  = (const float*)d_in[28];
    const float* be2 = (const float*)d_in[29];

    float *SRC, *BQKV;
    __half *XH, *FFH, *WqkvH, *WoH, *W1H, *W2H;
    cudaGetSymbolAddress((void**)&SRC,   g_SRC);
    cudaGetSymbolAddress((void**)&XH,    g_XH);
    cudaGetSymbolAddress((void**)&FFH,   g_FFH);
    cudaGetSymbolAddress((void**)&WqkvH, g_WqkvH);
    cudaGetSymbolAddress((void**)&WoH,   g_WoH);
    cudaGetSymbolAddress((void**)&W1H,   g_W1H);
    cudaGetSymbolAddress((void**)&W2H,   g_W2H);
    cudaGetSymbolAddress((void**)&BQKV,  g_bqkv);

    cudaFuncSetAttribute(gemm_kernel<true,true,false>,   cudaFuncAttributeMaxDynamicSharedMemorySize, GSMEM);
    cudaFuncSetAttribute(gemm_kernel<false,false,true>,  cudaFuncAttributeMaxDynamicSharedMemorySize, GSMEM);
    cudaFuncSetAttribute(gemm_ln_kernel,                 cudaFuncAttributeMaxDynamicSharedMemorySize, LSMEM);

    build_src_kernel<<<1024, 256>>>(hand_t, head_t, hand_m1, head_m1,
                                    state_t, state_m1, tok_m1, tok_t);
    build_coord_kernel<<<98, 256>>>(c_hand_t, c_head_t, c_hand_m1, c_head_m1, tr_t, tr_m1);
    split_qkv_w_kernel<<<2048, 256>>>(Wq, Wk, Wv, bq, bk, bv);
    split_weights_kernel<<<4096, 256>>>(Wo, W1, W2);
    split_kernel<<<2048, 256>>>(SRC, XH, MM*DD);

    const int MB = (MM + 127)/128;    // 65
    const int MBL = (MM + 63)/64;     // 130
    for (int l = 0; l < LL; l++) {
        gemm_kernel<false,false,true><<<dim3(MB, QKVN/128), 256, GSMEM>>>(MM, QKVN, DD, XH,
            WqkvH + (size_t)l*QKVN*DD, BQKV + l*QKVN, nullptr, nullptr);
        attn_mma_kernel<<<dim3(17, 64), 128>>>(XH);
        gemm_ln_kernel<<<MBL, 256, LSMEM>>>(MM, DD, XH,
            WoH + (size_t)l*DD*DD, bo + l*DD, g1 + l*DD, be1 + l*DD, SRC, XH);
        gemm_kernel<true,true,false><<<dim3(MB, FFD/128), 256, GSMEM>>>(MM, FFD, DD, XH,
            W1H + (size_t)l*FFD*DD, b1 + l*FFD, nullptr, FFH);
        gemm_ln_kernel<<<MBL, 256, LSMEM>>>(MM, FFD, FFH,
            W2H + (size_t)l*DD*FFD, b2 + l*DD, g2 + l*DD, be2 + l*DD, SRC, XH);
        attn_mma_kernel<<<dim3(0,0,0), 1>>>(nullptr); // placeholder removed below
        copy_out_kernel<<<0, 0>>>(nullptr);           // placeholder removed below
    }
    copy_out_kernel<<<48, 256>>>((float*)d_out);
}

// round 13
// speedup vs baseline: 2.7729x; 1.0246x over previous
#include <cuda_runtime.h>
#include <cuda_fp16.h>
#include <math.h>

#define BB 8
#define NN 256
#define DD 384
#define LL 6
#define HH 8
#define FFD 1536
#define TT 4
#define DH 48
#define NM1 517
#define SS 1034
#define SPAD 1152
#define MM (BB*SS)
#define QKVN 1152

// ---------------- scratch ----------------
__device__ float g_SRC [MM*DD];
__device__ float g_COORD[MM*3];

__device__ __half g_XH[MM*DD];
__device__ __half g_FFH[MM*FFD];

__device__ __half g_QH[64*SPAD*DH];
__device__ __half g_KH[64*SPAD*DH];
__device__ __half g_VH[64*DH*SPAD];

__device__ __half g_WqkvH[LL*QKVN*DD];
__device__ __half g_WoH[LL*DD*DD];
__device__ __half g_W1H[LL*FFD*DD];
__device__ __half g_W2H[LL*DD*FFD];
__device__ float g_bqkv[LL*QKVN];

// ---------------- input assembly ----------------
__global__ void build_src_kernel(const float* __restrict__ hand_t, const float* __restrict__ head_t,
                                 const float* __restrict__ hand_m1, const float* __restrict__ head_m1,
                                 const float* __restrict__ state_t, const float* __restrict__ state_m1,
                                 const float* __restrict__ tok_m1, const float* __restrict__ tok_t)
{
    for (int idx = blockIdx.x*blockDim.x + threadIdx.x; idx < BB*SS*DD; idx += gridDim.x*blockDim.x) {
        int d = idx % DD;
        int s = (idx / DD) % SS;
        int b = idx / (DD*SS);
        float v;
        if      (s == 0)    v = state_m1[b*DD + d];
        else if (s < 257)   v = hand_m1[((b*NN)+(s-1  ))*DD + d];
        else if (s < 513)   v = head_m1[((b*NN)+(s-257))*DD + d];
        else if (s < 517)   v = tok_m1[(s-513)*DD + d];
        else if (s == 517)  v = state_t[b*DD + d];
        else if (s < 774)   v = hand_t[((b*NN)+(s-518))*DD + d];
        else if (s < 1030)  v = head_t[((b*NN)+(s-774))*DD + d];
        else                v = tok_t[(s-1030)*DD + d];
        g_SRC[idx] = v;
    }
}

__global__ void build_coord_kernel(const float* __restrict__ c_hand_t, const float* __restrict__ c_head_t,
                                   const float* __restrict__ c_hand_m1, const float* __restrict__ c_head_m1,
                                   const float* __restrict__ tr_t, const float* __restrict__ tr_m1)
{
    for (int idx = blockIdx.x*blockDim.x + threadIdx.x; idx < BB*SS*3; idx += gridDim.x*blockDim.x) {
        int cdim = idx % 3;
        int s = (idx/3) % SS;
        int b = idx / (3*SS);
        float v;
        if      (s == 0)    v = tr_m1[b*3+cdim];
        else if (s < 257)   v = c_hand_m1[((b*NN)+(s-1  ))*3 + cdim];
        else if (s < 513)   v = c_head_m1[((b*NN)+(s-257))*3 + cdim];
        else if (s < 517)   v = tr_m1[b*3+cdim];
        else if (s == 517)  v = tr_t[b*3+cdim];
        else if (s < 774)   v = c_hand_t[((b*NN)+(s-518))*3 + cdim];
        else if (s < 1030)  v = c_head_t[((b*NN)+(s-774))*3 + cdim];
        else                v = tr_t[b*3+cdim];
        g_COORD[idx] = v;
    }
}

// ---------------- fp32 -> fp16 ----------------
__global__ void split_kernel(const float* __restrict__ x, __half* __restrict__ hi, int n)
{
    for (int i = blockIdx.x*blockDim.x + threadIdx.x; i < n; i += gridDim.x*blockDim.x)
        hi[i] = __float2half_rn(x[i]);
}

__global__ void split_qkv_w_kernel(const float* __restrict__ Wq, const float* __restrict__ Wk,
                                   const float* __restrict__ Wv, const float* __restrict__ bq,
                                   const float* __restrict__ bk, const float* __restrict__ bv)
{
    int tid0 = blockIdx.x*blockDim.x + threadIdx.x;
    if (tid0 < LL*QKVN) {
        int r = tid0 % QKVN, l = tid0 / QKVN;
        float v;
        if      (r < DD)   v = bq[l*DD + r];
        else if (r < 2*DD) v = bk[l*DD + r-DD];
        else               v = bv[l*DD + r-2*DD];
        g_bqkv[tid0] = v;
    }
    const int total = LL*QKVN*DD;
    for (int idx = tid0; idx < total; idx += gridDim.x*blockDim.x) {
        int k = idx % DD;
        int r = (idx / DD) % QKVN;
        int l = idx / (DD*QKVN);
        float v;
        if      (r < DD)    v = Wq[((size_t)l*DD + r      )*DD + k];
        else if (r < 2*DD)  v = Wk[((size_t)l*DD + r-DD   )*DD + k];
        else                v = Wv[((size_t)l*DD + r-2*DD )*DD + k];
        g_WqkvH[idx] = __float2half_rn(v);
    }
}

__global__ void split_weights_kernel(const float* __restrict__ Wo, const float* __restrict__ W1,
                                     const float* __restrict__ W2)
{
    const int S1 = DD*DD, S2 = FFD*DD, S3 = DD*FFD;
    const int SEG = S1 + S2 + S3;
    const int total = LL*SEG;
    for (int idx = blockIdx.x*blockDim.x + threadIdx.x; idx < total; idx += gridDim.x*blockDim.x) {
        int l = idx / SEG, r = idx % SEG;
        if (r < S1)         g_WoH[(size_t)l*S1 + r]      = __float2half_rn(Wo[(size_t)l*S1 + r]);
        else if (r < S1+S2) g_W1H[(size_t)l*S2 + r-S1]   = __float2half_rn(W1[(size_t)l*S2 + r-S1]);
        else                g_W2H[(size_t)l*S3 + r-S1-S2]= __float2half_rn(W2[(size_t)l*S3 + r-S1-S2]);
    }
}

// ---------------- helpers ----------------
__device__ __forceinline__ unsigned smem_addr(const void* p) {
    return (unsigned)__cvta_generic_to_shared(p);
}
__device__ __forceinline__ void ldsm_x4(unsigned r[4], unsigned addr) {
    asm volatile("ldmatrix.sync.aligned.m8n8.x4.shared.b16 {%0,%1,%2,%3}, [%4];"
                 : "=r"(r[0]), "=r"(r[1]), "=r"(r[2]), "=r"(r[3]) : "r"(addr));
}
__device__ __forceinline__ void mma_f16(float c[4], const unsigned a[4], const unsigned b[2]) {
    asm volatile("mma.sync.aligned.m16n8k16.row.col.f32.f16.f16.f32 "
                 "{%0,%1,%2,%3}, {%4,%5,%6,%7}, {%8,%9}, {%0,%1,%2,%3};"
                 : "+f"(c[0]), "+f"(c[1]), "+f"(c[2]), "+f"(c[3])
                 : "r"(a[0]), "r"(a[1]), "r"(a[2]), "r"(a[3]), "r"(b[0]), "r"(b[1]));
}
__device__ __forceinline__ void cpa16(unsigned dst, const void* src, bool pred) {
    int sz = pred ? 16 : 0;
    asm volatile("cp.async.cg.shared.global [%0], [%1], 16, %2;"
                 :: "r"(dst), "l"(src), "r"(sz) : "memory");
}
#define CP_COMMIT() asm volatile("cp.async.commit_group;" ::: "memory")
#define CP_WAIT2()  asm volatile("cp.async.wait_group 2;" ::: "memory")
#define CP_WAIT1()  asm volatile("cp.async.wait_group 1;" ::: "memory")
#define CP_WAIT0()  asm volatile("cp.async.wait_group 0;" ::: "memory")

// ---------------- fp16 GEMM (generic): 4-stage pipeline, 1 sync/iter ----------------
#define LDSMP 40
#define GARRB (128*LDSMP*2)
#define GSTG (2*GARRB)
#define GSMEM (4*GSTG)               // 81920

template<bool DO_GELU, bool HALF_OUT, bool ROPE>
__global__ void __launch_bounds__(256) gemm_kernel(int M, int N, int K,
    const __half* __restrict__ Ah, const __half* __restrict__ Wh,
    const float* __restrict__ bias, float* __restrict__ C,
    __half* __restrict__ Ch)
{
    extern __shared__ __half dsm[];
    const int tid  = threadIdx.x;
    const int lane = tid & 31;
    const int warp = tid >> 5;
    const int wm   = warp >> 2;
    const int wn   = warp & 3;
    const int m0   = blockIdx.x * 128;
    const int n0   = blockIdx.y * 128;

    float c[4][4][4];
    #pragma unroll
    for (int i = 0; i < 4; i++)
        #pragma unroll
        for (int j = 0; j < 4; j++)
            #pragma unroll
            for (int r = 0; r < 4; r++) c[i][j][r] = 0.f;

    const int lr = tid >> 2;
    const int lc = (tid & 3) * 8;

    const int aRow    = wm*64 + (lane & 7) + ((lane >> 3) & 1) * 8;
    const int aColSel = (lane >> 4) * 8;
    const int bRow    = wn*32 + (lane & 7) + ((lane >> 4) & 1) * 8;
    const int bColSel = ((lane >> 3) & 1) * 8;

    const unsigned sbase = smem_addr(dsm);

    auto load_tile = [&](int kt, int stage) {
        const int kc = kt * 32;
        const unsigned sb = sbase + stage*GSTG;
        #pragma unroll
        for (int half = 0; half < 2; half++) {
            int r  = lr + half*64;
            int gm = m0 + r;
            bool pa = gm < M;
            int gmc = pa ? gm : 0;
            unsigned drow = (unsigned)((r*LDSMP + lc) * 2);
            cpa16(sb + drow,         Ah + (size_t)gmc*K + kc + lc, pa);
            cpa16(sb + GARRB + drow, Wh + (size_t)(n0 + r)*K + kc + lc, true);
        }
    };

    const int nk = K >> 5;
    load_tile(0, 0);              CP_COMMIT();
    if (nk > 1) load_tile(1, 1);  CP_COMMIT();
    if (nk > 2) load_tile(2, 2);  CP_COMMIT();

    for (int kt = 0; kt < nk; kt++) {
        CP_WAIT2();
        __syncthreads();
        if (kt + 3 < nk) load_tile(kt + 3, (kt + 3) & 3);
        CP_COMMIT();

        const unsigned sb    = sbase + (kt & 3)*GSTG;
        const unsigned sWh_b = sb + GARRB;

        #pragma unroll
        for (int kk = 0; kk < 2; kk++) {
            unsigned ah[4][4], bh[4][2];
            #pragma unroll
            for (int mt = 0; mt < 4; mt++) {
                unsigned off = (unsigned)(((aRow + mt*16)*LDSMP + kk*16 + aColSel) * 2);
                ldsm_x4(ah[mt], sb + off);
            }
            #pragma unroll
            for (int np = 0; np < 2; np++) {
                unsigned off = (unsigned)(((bRow + np*16)*LDSMP + kk*16 + bColSel) * 2);
                unsigned t[4];
                ldsm_x4(t, sWh_b + off);
                bh[2*np][0]=t[0]; bh[2*np][1]=t[1]; bh[2*np+1][0]=t[2]; bh[2*np+1][1]=t[3];
            }
            #pragma unroll
            for (int mt = 0; mt < 4; mt++)
                #pragma unroll
                for (int nt = 0; nt < 4; nt++)
                    mma_f16(c[mt][nt], ah[mt], bh[nt]);
        }
    }

    if (ROPE) {
        const float scale = 0.14433756729740643f;
        const int j = (lane & 3) * 2;
        const float fj  = exp2f(-1.6609640474436813f * (float)j);
        const float fj1 = exp2f(-1.6609640474436813f * (float)(j+1));
        const int wcolBase = n0 + wn*32;
        #pragma unroll
        for (int mt = 0; mt < 4; mt++) {
            int row0 = m0 + wm*64 + mt*16 + (lane >> 2);
            int row1 = row0 + 8;
            bool ok0 = row0 < M, ok1 = row1 < M;
            int b0 = row0 / SS, s0 = row0 - b0*SS;
            int b1 = row1 / SS, s1 = row1 - b1*SS;
            #pragma unroll
            for (int p = 0; p < 2; p++) {
                int wcol = wcolBase + p*16;
                int sec  = wcol / DD;
                int hcol = wcol - sec*DD;
                int h    = hcol / DH;
                int dh0  = hcol - h*DH;
                float x1a = c[mt][2*p][0] + bias[wcol + j];
                float x1b = c[mt][2*p][1] + bias[wcol + j + 1];
                float x1c = c[mt][2*p][2] + bias[wcol + j];
                float x1d = c[mt][2*p][3] + bias[wcol + j + 1];
                float x2a = c[mt][2*p+1][0] + bias[wcol + 8 + j];
                float x2b = c[mt][2*p+1][1] + bias[wcol + 8 + j + 1];
                float x2c = c[mt][2*p+1][2] + bias[wcol + 8 + j];
                float x2d = c[mt][2*p+1][3] + bias[wcol + 8 + j + 1];
                int bh0 = b0*HH + h, bh1 = b1*HH + h;
                if (sec == 2) {
                    if (ok0) {
                        size_t base = ((size_t)bh0*DH + dh0 + j)*SPAD + s0;
                        g_VH[base          ] = __float2half_rn(x1a);
                        g_VH[base +   SPAD ] = __float2half_rn(x1b);
                        g_VH[base + 8*SPAD ] = __float2half_rn(x2a);
                        g_VH[base + 9*SPAD ] = __float2half_rn(x2b);
                    }
                    if (ok1) {
                        size_t base = ((size_t)bh1*DH + dh0 + j)*SPAD + s1;
                        g_VH[base          ] = __float2half_rn(x1c);
                        g_VH[base +   SPAD ] = __float2half_rn(x1d);
                        g_VH[base + 8*SPAD ] = __float2half_rn(x2c);
                        g_VH[base + 9*SPAD ] = __float2half_rn(x2d);
                    }
                } else {
                    int a = dh0 >> 4;
                    float co0 = g_COORD[row0*3 + a];
                    float co1 = g_COORD[row1*3 + a];
                    float c00, s00, c01, s01, c10, s10, c11, s11;
                    __sincosf(co0*fj,  &s00, &c00);
                    __sincosf(co0*fj1, &s01, &c01);
                    __sincosf(co1*fj,  &s10, &c10);
                    __sincosf(co1*fj1, &s11, &c11);
                    float y1a = x1a*c00 - x2a*s00, y2a = x1a*s00 + x2a*c00;
                    float y1b = x1b*c01 - x2b*s01, y2b = x1b*s01 + x2b*c01;
                    float y1c = x1c*c10 - x2c*s10, y2c = x1c*s10 + x2c*c10;
                    float y1d = x1d*c11 - x2d*s11, y2d = x1d*s11 + x2d*c11;
                    __half* dst = (sec == 0) ? g_QH : g_KH;
                    float sc = (sec == 0) ? scale : 1.f;
                    if (ok0) {
                        size_t base = ((size_t)bh0*SPAD + s0)*DH + dh0;
                        *(__half2*)&dst[base + j]     = __floats2half2_rn(y1a*sc, y1b*sc);
                        *(__half2*)&dst[base + j + 8] = __floats2half2_rn(y2a*sc, y2b*sc);
                    }
                    if (ok1) {
                        size_t base = ((size_t)bh1*SPAD + s1)*DH + dh0;
                        *(__half2*)&dst[base + j]     = __floats2half2_rn(y1c*sc, y1d*sc);
                        *(__half2*)&dst[base + j + 8] = __floats2half2_rn(y2c*sc, y2d*sc);
                    }
                }
            }
        }
        return;
    }

    #pragma unroll
    for (int mt = 0; mt < 4; mt++) {
        #pragma unroll
        for (int nt = 0; nt < 4; nt++) {
            int col  = n0 + wn*32 + nt*8 + (lane & 3)*2;
            float b0 = bias[col], b1 = bias[col+1];
            int row0 = m0 + wm*64 + mt*16 + (lane >> 2);
            int row1 = row0 + 8;
            float v0 = c[mt][nt][0] + b0, v1 = c[mt][nt][1] + b1;
            float v2 = c[mt][nt][2] + b0, v3 = c[mt][nt][3] + b1;
            if (DO_GELU) {
                v0 = 0.5f*v0*(1.0f+erff(v0*0.7071067811865475f));
                v1 = 0.5f*v1*(1.0f+erff(v1*0.7071067811865475f));
                v2 = 0.5f*v2*(1.0f+erff(v2*0.7071067811865475f));
                v3 = 0.5f*v3*(1.0f+erff(v3*0.7071067811865475f));
            }
            if (HALF_OUT) {
                __half2 h01 = __floats2half2_rn(v0, v1);
                __half2 h23 = __floats2half2_rn(v2, v3);
                if (row0 < M) *(__half2*)&Ch[(size_t)row0*N + col] = h01;
                if (row1 < M) *(__half2*)&Ch[(size_t)row1*N + col] = h23;
            } else {
                if (row0 < M) *(float2*)&C[(size_t)row0*N + col] = make_float2(v0, v1);
                if (row1 < M) *(float2*)&C[(size_t)row1*N + col] = make_float2(v2, v3);
            }
        }
    }
}

// ---------------- fused GEMM + residual + LayerNorm: 3-stage pipeline ------------
#define LA_B (64*LDSMP*2)            // 5120
#define LW_B (384*LDSMP*2)           // 30720
#define LSTG (LA_B + LW_B)           // 35840
#define LSMEM (3*LSTG)               // 107520

__global__ void __launch_bounds__(256) gemm_ln_kernel(int M, int K,
    const __half* __restrict__ Ah, const __half* __restrict__ Wh,
    const float* __restrict__ bias, const float* __restrict__ g,
    const float* __restrict__ bta,
    float* __restrict__ SRC, __half* __restrict__ XH)
{
    extern __shared__ __half dsm[];
    __shared__ float rsum[64][4], rsq[64][4];

    const int tid  = threadIdx.x;
    const int lane = tid & 31;
    const int warp = tid >> 5;
    const int wm   = warp >> 2;
    const int wn   = warp & 3;
    const int m0   = blockIdx.x * 64;

    float c[2][12][4];
    #pragma unroll
    for (int i = 0; i < 2; i++)
        #pragma unroll
        for (int j = 0; j < 12; j++)
            #pragma unroll
            for (int r = 0; r < 4; r++) c[i][j][r] = 0.f;

    const int aRowSel = (lane & 7) + ((lane >> 3) & 1) * 8;
    const int aColSel = (lane >> 4) * 8;
    const int bRowSel = (lane & 7) + ((lane >> 4) & 1) * 8;
    const int bColSel = ((lane >> 3) & 1) * 8;

    const unsigned sbase = smem_addr(dsm);

    auto load_tile = [&](int kt, int stage) {
        const int kc = kt * 32;
        const unsigned sb = sbase + stage*LSTG;
        {
            int row = tid >> 2, u = tid & 3;
            int gm = m0 + row;
            bool pa = gm < M;
            int gmc = pa ? gm : 0;
            cpa16(sb + (unsigned)((row*LDSMP + u*8) * 2), Ah + (size_t)gmc*K + kc + u*8, pa);
        }
        #pragma unroll
        for (int i = 0; i < 6; i++) {
            int idx = tid + i*256;
            int row = idx >> 2, u = idx & 3;
            cpa16(sb + LA_B + (unsigned)((row*LDSMP + u*8) * 2), Wh + (size_t)row*K + kc + u*8, true);
        }
    };

    const int nk = K >> 5;
    load_tile(0, 0);              CP_COMMIT();
    if (nk > 1) load_tile(1, 1);  CP_COMMIT();

    for (int kt = 0; kt < nk; kt++) {
        CP_WAIT1();
        __syncthreads();
        if (kt + 2 < nk) load_tile(kt + 2, (kt + 2) % 3);
        CP_COMMIT();

        const unsigned sb    = sbase + (kt % 3)*LSTG;
        const unsigned sWh_b = sb + LA_B;

        #pragma unroll
        for (int kk = 0; kk < 2; kk++) {
            unsigned ah[2][4], bh[12][2];
            #pragma unroll
            for (int mt = 0; mt < 2; mt++) {
                unsigned off = (unsigned)(((wm*32 + mt*16 + aRowSel)*LDSMP + kk*16 + aColSel) * 2);
                ldsm_x4(ah[mt], sb + off);
            }
            #pragma unroll
            for (int nb = 0; nb < 6; nb++) {
                unsigned off = (unsigned)(((wn*96 + nb*16 + bRowSel)*LDSMP + kk*16 + bColSel) * 2);
                unsigned t[4];
                ldsm_x4(t, sWh_b + off);
                bh[2*nb][0]=t[0]; bh[2*nb][1]=t[1]; bh[2*nb+1][0]=t[2]; bh[2*nb+1][1]=t[3];
            }
            #pragma unroll
            for (int mt = 0; mt < 2; mt++)
                #pragma unroll
                for (int nt = 0; nt < 12; nt++)
                    mma_f16(c[mt][nt], ah[mt], bh[nt]);
        }
    }

    // epilogue: x = c + bias + SRC; row-reduce; LN; write SRC + XH
    #pragma unroll
    for (int mt = 0; mt < 2; mt++) {
        int r0 = m0 + wm*32 + mt*16 + (lane >> 2);
        int r1 = r0 + 8;
        bool ok0 = r0 < M, ok1 = r1 < M;
        float s0 = 0.f, q0 = 0.f, s1 = 0.f, q1 = 0.f;
        #pragma unroll
        for (int nt = 0; nt < 12; nt++) {
            int col = wn*96 + nt*8 + (lane & 3)*2;
            float b0 = bias[col], b1 = bias[col+1];
            float2 sr0 = ok0 ? *(float2*)&SRC[(size_t)r0*DD + col] : make_float2(0.f,0.f);
            float2 sr1 = ok1 ? *(float2*)&SRC[(size_t)r1*DD + col] : make_float2(0.f,0.f);
            float x0 = c[mt][nt][0] + b0 + sr0.x;
            float x1 = c[mt][nt][1] + b1 + sr0.y;
            float x2 = c[mt][nt][2] + b0 + sr1.x;
            float x3 = c[mt][nt][3] + b1 + sr1.y;
            c[mt][nt][0]=x0; c[mt][nt][1]=x1; c[mt][nt][2]=x2; c[mt][nt][3]=x3;
            s0 += x0 + x1; q0 += x0*x0 + x1*x1;
            s1 += x2 + x3; q1 += x2*x2 + x3*x3;
        }
        s0 += __shfl_xor_sync(0xffffffffu, s0, 1);
        s0 += __shfl_xor_sync(0xffffffffu, s0, 2);
        q0 += __shfl_xor_sync(0xffffffffu, q0, 1);
        q0 += __shfl_xor_sync(0xffffffffu, q0, 2);
        s1 += __shfl_xor_sync(0xffffffffu, s1, 1);
        s1 += __shfl_xor_sync(0xffffffffu, s1, 2);
        q1 += __shfl_xor_sync(0xffffffffu, q1, 1);
        q1 += __shfl_xor_sync(0xffffffffu, q1, 2);
        if ((lane & 3) == 0) {
            int rl = wm*32 + mt*16 + (lane >> 2);
            rsum[rl][wn] = s0;  rsq[rl][wn] = q0;
            rsum[rl+8][wn] = s1; rsq[rl+8][wn] = q1;
        }
    }
    __syncthreads();

    #pragma unroll
    for (int mt = 0; mt < 2; mt++) {
        int rl0 = wm*32 + mt*16 + (lane >> 2);
        int r0 = m0 + rl0, r1 = r0 + 8;
        float S0 = rsum[rl0][0]+rsum[rl0][1]+rsum[rl0][2]+rsum[rl0][3];
        float Q0 = rsq[rl0][0]+rsq[rl0][1]+rsq[rl0][2]+rsq[rl0][3];
        float S1 = rsum[rl0+8][0]+rsum[rl0+8][1]+rsum[rl0+8][2]+rsum[rl0+8][3];
        float Q1 = rsq[rl0+8][0]+rsq[rl0+8][1]+rsq[rl0+8][2]+rsq[rl0+8][3];
        float mean0 = S0*(1.f/384.f), var0 = Q0*(1.f/384.f) - mean0*mean0;
        float mean1 = S1*(1.f/384.f), var1 = Q1*(1.f/384.f) - mean1*mean1;
        float rs0 = rsqrtf(var0 + 1e-5f), rs1 = rsqrtf(var1 + 1e-5f);
        bool ok0 = r0 < M, ok1 = r1 < M;
        #pragma unroll
        for (int nt = 0; nt < 12; nt++) {
            int col = wn*96 + nt*8 + (lane & 3)*2;
            float g0 = g[col], g1 = g[col+1];
            float t0 = bta[col], t1 = bta[col+1];
            float y0 = (c[mt][nt][0]-mean0)*rs0*g0 + t0;
            float y1 = (c[mt][nt][1]-mean0)*rs0*g1 + t1;
            float y2 = (c[mt][nt][2]-mean1)*rs1*g0 + t0;
            float y3 = (c[mt][nt][3]-mean1)*rs1*g1 + t1;
            if (ok0) {
                *(float2*)&SRC[(size_t)r0*DD + col] = make_float2(y0, y1);
                *(__half2*)&XH[(size_t)r0*DD + col] = __floats2half2_rn(y0, y1);
            }
            if (ok1) {
                *(float2*)&SRC[(size_t)r1*DD + col] = make_float2(y2, y3);
                *(__half2*)&XH[(size_t)r1*DD + col] = __floats2half2_rn(y2, y3);
            }
        }
    }
}

// ---------------- flash attention: 3-buffer K/V ring, 1 sync/iter ----------------
#define QKP 56
#define VTP 72
#define AKSZ (64*QKP*2)      // 7168
#define AVSZ (48*VTP*2)      // 6912
#define ASMEM (AKSZ + 3*AKSZ + 3*AVSZ)   // Q + 3K + 3V = 49408

__global__ void __launch_bounds__(128) attn_mma_kernel(__half* __restrict__ AH)
{
    extern __shared__ __half adsm[];
    const int bh = blockIdx.y;
    const int b = bh >> 3, h = bh & 7;
    const int q0 = blockIdx.x * 64;
    const int tid = threadIdx.x;
    const int lane = tid & 31;
    const int warp = tid >> 5;

    const unsigned sQh_b = smem_addr(adsm);
    const unsigned sKh_b = sQh_b + AKSZ;
    const unsigned sVh_b = sKh_b + 3*AKSZ;

    const size_t qkBase = (size_t)bh*SPAD*DH;
    const size_t vBase  = (size_t)bh*DH*SPAD;

    #pragma unroll
    for (int i = 0; i < 3; i++) {
        int cidx = tid + i*128;
        int row = cidx / 6, off = (cidx % 6) * 8;
        cpa16(sQh_b + (unsigned)((row*QKP + off)*2),
              g_QH + qkBase + (size_t)(q0 + row)*DH + off, true);
    }
    CP_COMMIT();

    const int ktMax = (q0 + 63 < NM1) ? 9 : 17;

    auto stageKV = [&](int kt, int buf) {
        int k0 = kt * 64;
        #pragma unroll
        for (int i = 0; i < 3; i++) {
            int cidx = tid + i*128;
            int row = cidx / 6, off = (cidx % 6) * 8;
            cpa16(sKh_b + buf*AKSZ + (unsigned)((row*QKP + off)*2),
                  g_KH + qkBase + (size_t)(k0 + row)*DH + off, true);
        }
        #pragma unroll
        for (int i = 0; i < 3; i++) {
            int cidx = tid + i*128;
            int row = cidx / 8, off = (cidx % 8) * 8;
            cpa16(sVh_b + buf*AVSZ + (unsigned)((row*VTP + off)*2),
                  g_VH + vBase + (size_t)row*SPAD + k0 + off, true);
        }
    };

    stageKV(0, 0);
    CP_COMMIT();
    CP_WAIT1();            // Q ready
    __syncthreads();

    const int aRow = 16*warp + (lane & 7) + ((lane >> 3) & 1) * 8;
    const int aColSel = (lane >> 4) * 8;
    unsigned qh[3][4];
    #pragma unroll
    for (int kk = 0; kk < 3; kk++) {
        unsigned off = (unsigned)((aRow*QKP + kk*16 + aColSel) * 2);
        ldsm_x4(qh[kk], sQh_b + off);
    }

    float o[6][4];
    #pragma unroll
    for (int i = 0; i < 6; i++)
        #pragma unroll
        for (int j = 0; j < 4; j++) o[i][j] = 0.f;
    float m0r = -1e30f, m1r = -1e30f, l0 = 0.f, l1 = 0.f;

    const int row0 = q0 + 16*warp + (lane >> 2);
    const int row1 = row0 + 8;
    const bool rm0 = row0 < NM1, rm1 = row1 < NM1;

    const int bRowSel = (lane & 7) + ((lane >> 4) & 1) * 8;
    const int bColSel = ((lane >> 3) & 1) * 8;

    for (int kt = 0; kt < ktMax; kt++) {
        if (kt + 1 < ktMax) stageKV(kt + 1, (kt + 1) % 3);
        CP_COMMIT();
        CP_WAIT1();
        __syncthreads();

        const int k0 = kt * 64;
        const int buf = kt % 3;
        const unsigned kB = sKh_b + buf*AKSZ;
        const unsigned vB = sVh_b + buf*AVSZ;

        float s[8][4];
        #pragma unroll
        for (int i = 0; i < 8; i++)
            #pragma unroll
            for (int j = 0; j < 4; j++) s[i][j] = 0.f;

        #pragma unroll
        for (int kk = 0; kk < 3; kk++) {
            unsigned bhf[8][2];
            #pragma unroll
            for (int nb = 0; nb < 4; nb++) {
                unsigned off = (unsigned)(((nb*16 + bRowSel)*QKP + kk*16 + bColSel) * 2);
                unsigned t[4];
                ldsm_x4(t, kB + off);
                bhf[2*nb][0]=t[0]; bhf[2*nb][1]=t[1]; bhf[2*nb+1][0]=t[2]; bhf[2*nb+1][1]=t[3];
            }
            #pragma unroll
            for (int nt = 0; nt < 8; nt++)
                mma_f16(s[nt], qh[kk], bhf[nt]);
        }

        #pragma unroll
        for (int nt = 0; nt < 8; nt++) {
            #pragma unroll
            for (int e = 0; e < 2; e++) {
                int col = k0 + nt*8 + (lane & 3)*2 + e;
                bool cmm = (col >= SS);
                bool cnm = (col >= NM1);
                if (cmm || (rm0 && cnm)) s[nt][e]   = -1e30f;
                if (cmm || (rm1 && cnm)) s[nt][2+e] = -1e30f;
            }
        }

        float t0 = -1e30f, t1 = -1e30f;
        #pragma unroll
        for (int nt = 0; nt < 8; nt++) {
            t0 = fmaxf(t0, fmaxf(s[nt][0], s[nt][1]));
            t1 = fmaxf(t1, fmaxf(s[nt][2], s[nt][3]));
        }
        t0 = fmaxf(t0, __shfl_xor_sync(0xffffffffu, t0, 1));
        t0 = fmaxf(t0, __shfl_xor_sync(0xffffffffu, t0, 2));
        t1 = fmaxf(t1, __shfl_xor_sync(0xffffffffu, t1, 1));
        t1 = fmaxf(t1, __shfl_xor_sync(0xffffffffu, t1, 2));
        float nm0 = fmaxf(m0r, t0), nm1 = fmaxf(m1r, t1);
        float f0 = __expf(m0r - nm0), f1 = __expf(m1r - nm1);
        m0r = nm0; m1r = nm1;

        float ps0 = 0.f, ps1 = 0.f;
        #pragma unroll
        for (int nt = 0; nt < 8; nt++) {
            s[nt][0] = __expf(s[nt][0] - m0r);
            s[nt][1] = __expf(s[nt][1] - m0r);
            s[nt][2] = __expf(s[nt][2] - m1r);
            s[nt][3] = __expf(s[nt][3] - m1r);
            ps0 += s[nt][0] + s[nt][1];
            ps1 += s[nt][2] + s[nt][3];
        }
        ps0 += __shfl_xor_sync(0xffffffffu, ps0, 1);
        ps0 += __shfl_xor_sync(0xffffffffu, ps0, 2);
        ps1 += __shfl_xor_sync(0xffffffffu, ps1, 1);
        ps1 += __shfl_xor_sync(0xffffffffu, ps1, 2);
        l0 = l0*f0 + ps0;
        l1 = l1*f1 + ps1;
        #pragma unroll
        for (int nt = 0; nt < 6; nt++) {
            o[nt][0] *= f0; o[nt][1] *= f0;
            o[nt][2] *= f1; o[nt][3] *= f1;
        }

        #pragma unroll
        for (int kk = 0; kk < 4; kk++) {
            unsigned pah[4];
            __half2 t01;
            t01 = __floats2half2_rn(s[2*kk  ][0], s[2*kk  ][1]); pah[0] = *(unsigned*)&t01;
            t01 = __floats2half2_rn(s[2*kk  ][2], s[2*kk  ][3]); pah[1] = *(unsigned*)&t01;
            t01 = __floats2half2_rn(s[2*kk+1][0], s[2*kk+1][1]); pah[2] = *(unsigned*)&t01;
            t01 = __floats2half2_rn(s[2*kk+1][2], s[2*kk+1][3]); pah[3] = *(unsigned*)&t01;

            unsigned vbh[6][2];
            #pragma unroll
            for (int nb = 0; nb < 3; nb++) {
                unsigned off = (unsigned)(((nb*16 + bRowSel)*VTP + kk*16 + bColSel) * 2);
                unsigned t[4];
                ldsm_x4(t, vB + off);
                vbh[2*nb][0]=t[0]; vbh[2*nb][1]=t[1]; vbh[2*nb+1][0]=t[2]; vbh[2*nb+1][1]=t[3];
            }
            #pragma unroll
            for (int nt = 0; nt < 6; nt++)
                mma_f16(o[nt], pah, vbh[nt]);
        }
    }

    float il0 = 1.f / l0, il1 = 1.f / l1;
    #pragma unroll
    for (int nt = 0; nt < 6; nt++) {
        int col = h*DH + nt*8 + (lane & 3)*2;
        if (row0 < SS) {
            __half2 hh = __floats2half2_rn(o[nt][0]*il0, o[nt][1]*il0);
            *(__half2*)&AH[(size_t)(b*SS + row0)*DD + col] = hh;
        }
        if (row1 < SS) {
            __half2 hh = __floats2half2_rn(o[nt][2]*il1, o[nt][3]*il1);
            *(__half2*)&AH[(size_t)(b*SS + row1)*DD + col] = hh;
        }
    }
}

__global__ void copy_out_kernel(float* __restrict__ out)
{
    int idx = blockIdx.x*blockDim.x + threadIdx.x;
    if (idx >= BB*TT*DD) return;
    int d = idx % DD;
    int t = (idx/DD) % TT;
    int b = idx / (DD*TT);
    out[idx] = g_SRC[((size_t)(b*SS + (SS-TT) + t))*DD + d];
}

// ---------------- host launcher ----------------
extern "C" void kernel_launch(void* const* d_in, const int* in_sizes, int n_in,
                              void* d_out, int out_size)
{
    (void)in_sizes; (void)n_in; (void)out_size;
    const float* hand_t    = (const float*)d_in[0];
    const float* head_t    = (const float*)d_in[1];
    const float* hand_m1   = (const float*)d_in[2];
    const float* head_m1   = (const float*)d_in[3];
    const float* c_hand_t  = (const float*)d_in[4];
    const float* c_head_t  = (const float*)d_in[5];
    const float* c_hand_m1 = (const float*)d_in[6];
    const float* c_head_m1 = (const float*)d_in[7];
    const float* state_t   = (const float*)d_in[8];
    const float* state_m1  = (const float*)d_in[9];
    const float* tr_t      = (const float*)d_in[10];
    const float* tr_m1     = (const float*)d_in[11];
    const float* tok_m1    = (const float*)d_in[12];
    const float* tok_t     = (const float*)d_in[13];
    const float* Wq  = (const float*)d_in[14];
    const float* bq  = (const float*)d_in[15];
    const float* Wk  = (const float*)d_in[16];
    const float* bk  = (const float*)d_in[17];
    const float* Wv  = (const float*)d_in[18];
    const float* bv  = (const float*)d_in[19];
    const float* Wo  = (const float*)d_in[20];
    const float* bo  = (const float*)d_in[21];
    const float* W1  = (const float*)d_in[22];
    const float* b1  = (const float*)d_in[23];
    const float* W2  = (const float*)d_in[24];
    const float* b2  = (const float*)d_in[25];
    const float* g1  = (const float*)d_in[26];
    const float* be1 = (const float*)d_in[27];
    const float* g2  = (const float*)d_in[28];
    const float* be2 = (const float*)d_in[29];

    float *SRC, *BQKV;
    __half *XH, *FFH, *WqkvH, *WoH, *W1H, *W2H;
    cudaGetSymbolAddress((void**)&SRC,   g_SRC);
    cudaGetSymbolAddress((void**)&XH,    g_XH);
    cudaGetSymbolAddress((void**)&FFH,   g_FFH);
    cudaGetSymbolAddress((void**)&WqkvH, g_WqkvH);
    cudaGetSymbolAddress((void**)&WoH,   g_WoH);
    cudaGetSymbolAddress((void**)&W1H,   g_W1H);
    cudaGetSymbolAddress((void**)&W2H,   g_W2H);
    cudaGetSymbolAddress((void**)&BQKV,  g_bqkv);

    cudaFuncSetAttribute(gemm_kernel<true,true,false>,  cudaFuncAttributeMaxDynamicSharedMemorySize, GSMEM);
    cudaFuncSetAttribute(gemm_kernel<false,false,true>, cudaFuncAttributeMaxDynamicSharedMemorySize, GSMEM);
    cudaFuncSetAttribute(gemm_ln_kernel,                cudaFuncAttributeMaxDynamicSharedMemorySize, LSMEM);
    cudaFuncSetAttribute(attn_mma_kernel,               cudaFuncAttributeMaxDynamicSharedMemorySize, ASMEM);

    build_src_kernel<<<1024, 256>>>(hand_t, head_t, hand_m1, head_m1,
                                    state_t, state_m1, tok_m1, tok_t);
    build_coord_kernel<<<98, 256>>>(c_hand_t, c_head_t, c_hand_m1, c_head_m1, tr_t, tr_m1);
    split_qkv_w_kernel<<<2048, 256>>>(Wq, Wk, Wv, bq, bk, bv);
    split_weights_kernel<<<4096, 256>>>(Wo, W1, W2);
    split_kernel<<<2048, 256>>>(SRC, XH, MM*DD);

    const int MB = (MM + 127)/128;    // 65
    const int MBL = (MM + 63)/64;     // 130
    for (int l = 0; l < LL; l++) {
        gemm_kernel<false,false,true><<<dim3(MB, QKVN/128), 256, GSMEM>>>(MM, QKVN, DD, XH,
            WqkvH + (size_t)l*QKVN*DD, BQKV + l*QKVN, nullptr, nullptr);
        attn_mma_kernel<<<dim3(17, 64), 128, ASMEM>>>(XH);
        gemm_ln_kernel<<<MBL, 256, LSMEM>>>(MM, DD, XH,
            WoH + (size_t)l*DD*DD, bo + l*DD, g1 + l*DD, be1 + l*DD, SRC, XH);
        gemm_kernel<true,true,false><<<dim3(MB, FFD/128), 256, GSMEM>>>(MM, FFD, DD, XH,
            W1H + (size_t)l*FFD*DD, b1 + l*FFD, nullptr, FFH);
        gemm_ln_kernel<<<MBL, 256, LSMEM>>>(MM, FFD, FFH,
            W2H + (size_t)l*DD*FFD, b2 + l*DD, g2 + l*DD, be2 + l*DD, SRC, XH);
    }
    copy_out_kernel<<<48, 256>>>((float*)d_out);
}